// round 2
// baseline (speedup 1.0000x reference)
#include <cuda_runtime.h>
#include <math.h>

#define B_ 2
#define N_ 2048
#define E_ 1024
#define H_ 16
#define HD_ 64
#define MROWS (B_*N_)   // 4096

// Scratch (allocation-free rule: __device__ globals)
__device__ float g_Q[(size_t)B_*H_*N_*HD_];   // 16 MB
__device__ float g_K[(size_t)B_*H_*N_*HD_];   // 16 MB
__device__ float g_V[(size_t)B_*H_*N_*HD_];   // 16 MB
__device__ float g_sa[(size_t)B_*N_*E_];      // 32 MB

// ---------------------------------------------------------------------------
// QKV projection: per head h, C[4096 x 192] = x[4096 x 1024] @ Wqkv[h] + bqkv[h]
// grid = (3 col-tiles of 64, 64 row-tiles, 16 heads); colTile 0->K, 1->Q, 2->V
// ---------------------------------------------------------------------------
__global__ __launch_bounds__(256) void qkv_kernel(const float* __restrict__ x,
                                                  const float* __restrict__ W,
                                                  const float* __restrict__ bias) {
    const int BK = 16;
    __shared__ float As[BK][68];   // transposed A tile, padded for alignment
    __shared__ float Bs[BK][64];

    int tid = threadIdx.x;
    int tx = tid & 15, ty = tid >> 4;
    int colTile = blockIdx.x;              // 0..2
    int rowBase = blockIdx.y * 64;
    int h = blockIdx.z;

    const float* Bm = W + (size_t)h * E_ * 192 + colTile * 64;

    float acc[4][4];
#pragma unroll
    for (int i = 0; i < 4; i++)
#pragma unroll
        for (int j = 0; j < 4; j++) acc[i][j] = 0.f;

    for (int kb = 0; kb < E_; kb += BK) {
#pragma unroll
        for (int l = 0; l < 4; l++) {
            int i = tid + l * 256;
            int r = i >> 4, c = i & 15;
            As[c][r] = x[(size_t)(rowBase + r) * E_ + kb + c];
        }
#pragma unroll
        for (int l = 0; l < 4; l++) {
            int i = tid + l * 256;
            int r = i >> 6, c = i & 63;
            Bs[r][c] = Bm[(size_t)(kb + r) * 192 + c];
        }
        __syncthreads();
#pragma unroll
        for (int k = 0; k < BK; k++) {
            float4 a4 = *(const float4*)&As[k][ty * 4];
            float4 b4 = *(const float4*)&Bs[k][tx * 4];
            float a[4] = {a4.x, a4.y, a4.z, a4.w};
            float b[4] = {b4.x, b4.y, b4.z, b4.w};
#pragma unroll
            for (int i = 0; i < 4; i++)
#pragma unroll
                for (int j = 0; j < 4; j++) acc[i][j] += a[i] * b[j];
        }
        __syncthreads();
    }

    // Reference split order: k, q, v  ->  colTile 0 = K, 1 = Q, 2 = V
    float* dst = (colTile == 0) ? g_K : (colTile == 1) ? g_Q : g_V;
#pragma unroll
    for (int i = 0; i < 4; i++) {
        int m = rowBase + ty * 4 + i;
        int bb = m >> 11;            // /2048
        int n  = m & 2047;
        float* drow = dst + (((size_t)(bb * H_ + h)) * N_ + n) * HD_;
#pragma unroll
        for (int j = 0; j < 4; j++) {
            int d = tx * 4 + j;
            drow[d] = acc[i][j] + bias[h * 192 + colTile * 64 + d];
        }
    }
}

// ---------------------------------------------------------------------------
// Causal flash attention, fp32. One block = 128 query rows of one (b,h).
// One thread = one query row; q[64], o[64] in registers; K/V tiles (64 keys)
// in smem; softmax processed in 16-key register chunks (online rescale).
// grid = (16 qtiles [reversed for load balance], 32 bh)
// ---------------------------------------------------------------------------
__global__ __launch_bounds__(128) void attn_kernel() {
    __shared__ float Ks[64 * 64];
    __shared__ float Vs[64 * 64];

    int qt = (gridDim.x - 1) - blockIdx.x;   // heavy tiles launch first
    int bh = blockIdx.y;                     // b*16 + h
    int r  = threadIdx.x;                    // 0..127
    int qrow = qt * 128 + r;

    const float* Qp = g_Q + ((size_t)bh * N_ + qrow) * HD_;
    float q[64];
    {
        const float4* Qv = (const float4*)Qp;
#pragma unroll
        for (int d4 = 0; d4 < 16; d4++) {
            float4 t = Qv[d4];
            q[4*d4] = t.x; q[4*d4+1] = t.y; q[4*d4+2] = t.z; q[4*d4+3] = t.w;
        }
    }
    float o[64];
#pragma unroll
    for (int d = 0; d < 64; d++) o[d] = 0.f;
    float mrun = -1e30f, lrun = 0.f;

    const float4* Kbase = (const float4*)(g_K + (size_t)bh * N_ * HD_);
    const float4* Vbase = (const float4*)(g_V + (size_t)bh * N_ * HD_);
    float4* Ksv = (float4*)Ks;
    float4* Vsv = (float4*)Vs;

    int nkt = 2 * qt + 2;                    // causal: tiles needed
    for (int kt = 0; kt < nkt; kt++) {
        int off = kt * 64 * 16;              // tile offset in float4s
#pragma unroll
        for (int l = 0; l < 8; l++) {
            Ksv[r + l * 128] = Kbase[off + r + l * 128];
            Vsv[r + l * 128] = Vbase[off + r + l * 128];
        }
        __syncthreads();

        int kbase = kt * 64;
#pragma unroll 1
        for (int jc = 0; jc < 64; jc += 16) {
            float s[16];
            float smax = -1e30f;
#pragma unroll
            for (int jj = 0; jj < 16; jj++) {
                int j = jc + jj;
                const float4* krow = (const float4*)(Ks + j * 64);
                float acc = 0.f;
#pragma unroll
                for (int d4 = 0; d4 < 16; d4++) {
                    float4 kv = krow[d4];
                    acc += q[4*d4] * kv.x + q[4*d4+1] * kv.y
                         + q[4*d4+2] * kv.z + q[4*d4+3] * kv.w;
                }
                acc *= 0.125f;                       // 1/sqrt(64)
                acc = (kbase + j <= qrow) ? acc : -1e30f;
                s[jj] = acc;
                smax = fmaxf(smax, acc);
            }
            float mnew = fmaxf(mrun, smax);
            float alpha = __expf(mrun - mnew);
            lrun *= alpha;
#pragma unroll
            for (int d = 0; d < 64; d++) o[d] *= alpha;
            mrun = mnew;
#pragma unroll
            for (int jj = 0; jj < 16; jj++) {
                float p = __expf(s[jj] - mnew);
                lrun += p;
                const float4* vrow = (const float4*)(Vs + (jc + jj) * 64);
#pragma unroll
                for (int d4 = 0; d4 < 16; d4++) {
                    float4 vv = vrow[d4];
                    o[4*d4]   += p * vv.x;
                    o[4*d4+1] += p * vv.y;
                    o[4*d4+2] += p * vv.z;
                    o[4*d4+3] += p * vv.w;
                }
            }
        }
        __syncthreads();
    }

    float inv = 1.f / lrun;
    int b = bh >> 4, h = bh & 15;
    float* orow = g_sa + ((size_t)(b * N_ + qrow)) * E_ + h * HD_;
    float4* orv = (float4*)orow;
#pragma unroll
    for (int d4 = 0; d4 < 16; d4++) {
        float4 t;
        t.x = o[4*d4] * inv;   t.y = o[4*d4+1] * inv;
        t.z = o[4*d4+2] * inv; t.w = o[4*d4+3] * inv;
        orv[d4] = t;
    }
}

// ---------------------------------------------------------------------------
// Output projection: out[4096 x 1024] = g_sa @ Wout + bout
// grid = (16 col-tiles, 64 row-tiles)
// ---------------------------------------------------------------------------
__global__ __launch_bounds__(256) void outproj_kernel(const float* __restrict__ Wout,
                                                      const float* __restrict__ bout,
                                                      float* __restrict__ out) {
    const int BK = 16;
    __shared__ float As[BK][68];
    __shared__ float Bs[BK][64];

    int tid = threadIdx.x;
    int tx = tid & 15, ty = tid >> 4;
    int colBase = blockIdx.x * 64;
    int rowBase = blockIdx.y * 64;

    const float* Bm = Wout + colBase;

    float acc[4][4];
#pragma unroll
    for (int i = 0; i < 4; i++)
#pragma unroll
        for (int j = 0; j < 4; j++) acc[i][j] = 0.f;

    for (int kb = 0; kb < E_; kb += BK) {
#pragma unroll
        for (int l = 0; l < 4; l++) {
            int i = tid + l * 256;
            int r = i >> 4, c = i & 15;
            As[c][r] = g_sa[(size_t)(rowBase + r) * E_ + kb + c];
        }
#pragma unroll
        for (int l = 0; l < 4; l++) {
            int i = tid + l * 256;
            int r = i >> 6, c = i & 63;
            Bs[r][c] = Bm[(size_t)(kb + r) * E_ + c];
        }
        __syncthreads();
#pragma unroll
        for (int k = 0; k < BK; k++) {
            float4 a4 = *(const float4*)&As[k][ty * 4];
            float4 b4 = *(const float4*)&Bs[k][tx * 4];
            float a[4] = {a4.x, a4.y, a4.z, a4.w};
            float b[4] = {b4.x, b4.y, b4.z, b4.w};
#pragma unroll
            for (int i = 0; i < 4; i++)
#pragma unroll
                for (int j = 0; j < 4; j++) acc[i][j] += a[i] * b[j];
        }
        __syncthreads();
    }

#pragma unroll
    for (int i = 0; i < 4; i++) {
        int m = rowBase + ty * 4 + i;
#pragma unroll
        for (int j = 0; j < 4; j++) {
            int c = colBase + tx * 4 + j;
            out[(size_t)m * E_ + c] = acc[i][j] + bout[c];
        }
    }
}

// ---------------------------------------------------------------------------
extern "C" void kernel_launch(void* const* d_in, const int* in_sizes, int n_in,
                              void* d_out, int out_size) {
    const float* x    = (const float*)d_in[0];
    const float* Wqkv = (const float*)d_in[1];
    const float* bqkv = (const float*)d_in[2];
    const float* Wout = (const float*)d_in[3];
    const float* bout = (const float*)d_in[4];
    float* out = (float*)d_out;

    dim3 g1(3, 64, 16);
    qkv_kernel<<<g1, 256>>>(x, Wqkv, bqkv);

    dim3 g2(16, 32);
    attn_kernel<<<g2, 128>>>();

    dim3 g3(16, 64);
    outproj_kernel<<<g3, 256>>>(Wout, bout, out);
}

// round 5
// speedup vs baseline: 1.3210x; 1.3210x over previous
#include <cuda_runtime.h>
#include <cuda_bf16.h>
#include <math.h>
#include <stdint.h>

#define B_ 2
#define N_ 2048
#define E_ 1024
#define H_ 16
#define HD_ 64

// ---------------------------------------------------------------------------
// Scratch (__device__ globals; allocation-free rule)
// ---------------------------------------------------------------------------
__device__ float g_Q[(size_t)B_*H_*N_*HD_];
__device__ float g_K[(size_t)B_*H_*N_*HD_];
__device__ float g_V[(size_t)B_*H_*N_*HD_];
__device__ float g_sa[(size_t)B_*N_*E_];

// bf16 split operands
__device__ __nv_bfloat16 g_xh[(size_t)4096*1024];
__device__ __nv_bfloat16 g_xl[(size_t)4096*1024];
__device__ __nv_bfloat16 g_wqh[(size_t)16*192*1024];   // [h][n][k] (transposed)
__device__ __nv_bfloat16 g_wql[(size_t)16*192*1024];
__device__ __nv_bfloat16 g_woh[(size_t)1024*1024];     // [n][k] (transposed)
__device__ __nv_bfloat16 g_wol[(size_t)1024*1024];
__device__ __nv_bfloat16 g_sah[(size_t)4096*1024];
__device__ __nv_bfloat16 g_sal[(size_t)4096*1024];

// ---------------------------------------------------------------------------
// mma.sync m16n8k16 bf16 (baseline PTX feature set; works at compute_103)
// ---------------------------------------------------------------------------
__device__ __forceinline__ void mma_bf16(float* c, const uint32_t* a, const uint32_t* b) {
    asm volatile(
        "mma.sync.aligned.m16n8k16.row.col.f32.bf16.bf16.f32 "
        "{%0,%1,%2,%3},{%4,%5,%6,%7},{%8,%9},{%0,%1,%2,%3};"
        : "+f"(c[0]), "+f"(c[1]), "+f"(c[2]), "+f"(c[3])
        : "r"(a[0]), "r"(a[1]), "r"(a[2]), "r"(a[3]), "r"(b[0]), "r"(b[1]));
}

// ---------------------------------------------------------------------------
// Conversion kernels: fp32 -> bf16 hi/lo split (write device globals directly)
// ---------------------------------------------------------------------------
__device__ __forceinline__ void split_body(const float* __restrict__ src,
                                           __nv_bfloat16* __restrict__ hi,
                                           __nv_bfloat16* __restrict__ lo, int n4) {
    int i = blockIdx.x * blockDim.x + threadIdx.x;
    int stride = gridDim.x * blockDim.x;
    for (; i < n4; i += stride) {
        float4 v = ((const float4*)src)[i];
        union { __nv_bfloat16 b[4]; uint2 u; } Hh, Ll;
        float vs[4] = {v.x, v.y, v.z, v.w};
#pragma unroll
        for (int j = 0; j < 4; j++) {
            __nv_bfloat16 h = __float2bfloat16(vs[j]);
            Hh.b[j] = h;
            Ll.b[j] = __float2bfloat16(vs[j] - __bfloat162float(h));
        }
        ((uint2*)hi)[i] = Hh.u;
        ((uint2*)lo)[i] = Ll.u;
    }
}

__global__ void split_x_kernel(const float* __restrict__ x) {
    split_body(x, g_xh, g_xl, 4096 * 1024 / 4);
}
__global__ void split_sa_kernel() {
    split_body(g_sa, g_sah, g_sal, 4096 * 1024 / 4);
}

// out[z][c][r] = in[z][r][c]  (R rows, C cols per z-slice)
__device__ __forceinline__ void tsplit_body(const float* __restrict__ in,
                                            __nv_bfloat16* __restrict__ oh,
                                            __nv_bfloat16* __restrict__ ol,
                                            int R, int C) {
    __shared__ float t[32][33];
    size_t zo = (size_t)blockIdx.z * R * C;
    in += zo; oh += zo; ol += zo;
    int c0 = blockIdx.x * 32, r0 = blockIdx.y * 32;
    int tx = threadIdx.x, ty = threadIdx.y;   // 32 x 8
#pragma unroll
    for (int i = 0; i < 32; i += 8)
        t[ty + i][tx] = in[(size_t)(r0 + ty + i) * C + c0 + tx];
    __syncthreads();
#pragma unroll
    for (int i = 0; i < 32; i += 8) {
        float v = t[tx][ty + i];
        __nv_bfloat16 h = __float2bfloat16(v);
        oh[(size_t)(c0 + ty + i) * R + r0 + tx] = h;
        ol[(size_t)(c0 + ty + i) * R + r0 + tx] = __float2bfloat16(v - __bfloat162float(h));
    }
}

__global__ void tsplit_wq_kernel(const float* __restrict__ Wqkv) {
    tsplit_body(Wqkv, g_wqh, g_wql, 1024, 192);
}
__global__ void tsplit_wo_kernel(const float* __restrict__ Wout) {
    tsplit_body(Wout, g_woh, g_wol, 1024, 1024);
}

// ---------------------------------------------------------------------------
// Warp-MMA GEMM mainloop: C[128 x 64] += A[128 x 1024] @ B[64 x 1024]^T
// (B stored n-major: B[n][k]). Split-bf16 3-pass accumulation.
// 256 threads = 8 warps in 4(m) x 2(n); warp tile 32x32; BK=32.
// Smem rows padded to 40 elems (80B): 20*r mod 32 is a permutation ->
// conflict-free fragment reads.
// ---------------------------------------------------------------------------
#define ASTR 40
#define BSTR 40

__device__ __forceinline__ void gemm_bf16_mainloop(
    const uint2* __restrict__ Ahg, const uint2* __restrict__ Alg,   // at row mbase (uint2-indexed, row stride 256)
    const uint2* __restrict__ Bhg, const uint2* __restrict__ Blg,   // at row n0   (uint2-indexed, row stride 256)
    float C[2][4][4])
{
    __shared__ __nv_bfloat16 sAh[128 * ASTR];
    __shared__ __nv_bfloat16 sAl[128 * ASTR];
    __shared__ __nv_bfloat16 sBh[64 * BSTR];
    __shared__ __nv_bfloat16 sBl[64 * BSTR];

    int tid = threadIdx.x;
    int lane = tid & 31, w = tid >> 5;
    int wm = (w & 3) * 32, wn = (w >> 2) * 32;
    int g = lane >> 2, tg = lane & 3;

#pragma unroll
    for (int mt = 0; mt < 2; mt++)
#pragma unroll
        for (int nt = 0; nt < 4; nt++)
#pragma unroll
            for (int i = 0; i < 4; i++) C[mt][nt][i] = 0.f;

    const uint32_t* wAh = (const uint32_t*)sAh;
    const uint32_t* wAl = (const uint32_t*)sAl;
    const uint32_t* wBh = (const uint32_t*)sBh;
    const uint32_t* wBl = (const uint32_t*)sBl;

    for (int kc = 0; kc < 32; kc++) {
        int kb2 = kc * 8;                        // uint2 offset within row
        // ---- global -> smem (padded rows) ----
#pragma unroll
        for (int p = 0; p < 4; p++) {
            int idx = tid + p * 256;
            int r = idx >> 3, c = idx & 7;
            *(uint2*)&sAh[r * ASTR + c * 4] = Ahg[(size_t)r * 256 + kb2 + c];
            *(uint2*)&sAl[r * ASTR + c * 4] = Alg[(size_t)r * 256 + kb2 + c];
        }
#pragma unroll
        for (int p = 0; p < 2; p++) {
            int idx = tid + p * 256;
            int r = idx >> 3, c = idx & 7;
            *(uint2*)&sBh[r * BSTR + c * 4] = Bhg[(size_t)r * 256 + kb2 + c];
            *(uint2*)&sBl[r * BSTR + c * 4] = Blg[(size_t)r * 256 + kb2 + c];
        }
        __syncthreads();

        // ---- compute ----
#pragma unroll
        for (int k16 = 0; k16 < 2; k16++) {
            int ko = k16 * 16;
            uint32_t ah[2][4], al[2][4], bh[4][2], bl[4][2];
#pragma unroll
            for (int mt = 0; mt < 2; mt++) {
                int r0 = wm + mt * 16;
                int i0 = ((r0 + g) * ASTR + ko + tg * 2) >> 1;
                int i1 = ((r0 + g + 8) * ASTR + ko + tg * 2) >> 1;
                ah[mt][0] = wAh[i0]; ah[mt][1] = wAh[i1];
                ah[mt][2] = wAh[i0 + 4]; ah[mt][3] = wAh[i1 + 4];
                al[mt][0] = wAl[i0]; al[mt][1] = wAl[i1];
                al[mt][2] = wAl[i0 + 4]; al[mt][3] = wAl[i1 + 4];
            }
#pragma unroll
            for (int nt = 0; nt < 4; nt++) {
                int n0 = wn + nt * 8;
                int j0 = ((n0 + g) * BSTR + ko + tg * 2) >> 1;
                bh[nt][0] = wBh[j0]; bh[nt][1] = wBh[j0 + 4];
                bl[nt][0] = wBl[j0]; bl[nt][1] = wBl[j0 + 4];
            }
#pragma unroll
            for (int mt = 0; mt < 2; mt++)
#pragma unroll
                for (int nt = 0; nt < 4; nt++) {
                    mma_bf16(C[mt][nt], ah[mt], bh[nt]);
                    mma_bf16(C[mt][nt], ah[mt], bl[nt]);
                    mma_bf16(C[mt][nt], al[mt], bh[nt]);
                }
        }
        __syncthreads();
    }
}

// ---------------------------------------------------------------------------
// QKV: per head h, C[4096 x 192] = x @ Wqkv[h] + bqkv[h]; ntile 0->K,1->Q,2->V
// grid = (3, 32, 16), block = 256
// ---------------------------------------------------------------------------
__global__ __launch_bounds__(256) void qkv_mma_kernel(const float* __restrict__ bqkv) {
    int nt = blockIdx.x, mt = blockIdx.y, h = blockIdx.z;
    int mbase = mt * 128;

    const uint2* Ahg = (const uint2*)g_xh + (size_t)mbase * 256;
    const uint2* Alg = (const uint2*)g_xl + (size_t)mbase * 256;
    size_t boff = ((size_t)h * 192 + nt * 64) * 256;
    const uint2* Bhg = (const uint2*)g_wqh + boff;
    const uint2* Blg = (const uint2*)g_wql + boff;

    float C[2][4][4];
    gemm_bf16_mainloop(Ahg, Alg, Bhg, Blg, C);

    int lane = threadIdx.x & 31, w = threadIdx.x >> 5;
    int wm = (w & 3) * 32, wn = (w >> 2) * 32;
    int g = lane >> 2, tg = lane & 3;

    const float* bp = bqkv + h * 192 + nt * 64;
    float* base = (nt == 0) ? g_K : (nt == 1) ? g_Q : g_V;

#pragma unroll
    for (int mt2 = 0; mt2 < 2; mt2++) {
#pragma unroll
        for (int half = 0; half < 2; half++) {
            int m = mbase + wm + mt2 * 16 + g + half * 8;
            int b = m >> 11, n = m & 2047;
            float* drow = base + (((size_t)(b * H_ + h)) * N_ + n) * HD_;
#pragma unroll
            for (int nt2 = 0; nt2 < 4; nt2++) {
                int col = wn + nt2 * 8 + tg * 2;
                float2 v;
                v.x = C[mt2][nt2][half * 2 + 0] + bp[col];
                v.y = C[mt2][nt2][half * 2 + 1] + bp[col + 1];
                *(float2*)&drow[col] = v;
            }
        }
    }
}

// ---------------------------------------------------------------------------
// Output projection: out[4096 x 1024] = g_sa @ Wout + bout
// grid = (16, 32), block = 256
// ---------------------------------------------------------------------------
__global__ __launch_bounds__(256) void outproj_mma_kernel(const float* __restrict__ bout,
                                                          float* __restrict__ out) {
    int nt = blockIdx.x, mt = blockIdx.y;
    int mbase = mt * 128;

    const uint2* Ahg = (const uint2*)g_sah + (size_t)mbase * 256;
    const uint2* Alg = (const uint2*)g_sal + (size_t)mbase * 256;
    size_t boff = (size_t)nt * 64 * 256;
    const uint2* Bhg = (const uint2*)g_woh + boff;
    const uint2* Blg = (const uint2*)g_wol + boff;

    float C[2][4][4];
    gemm_bf16_mainloop(Ahg, Alg, Bhg, Blg, C);

    int lane = threadIdx.x & 31, w = threadIdx.x >> 5;
    int wm = (w & 3) * 32, wn = (w >> 2) * 32;
    int g = lane >> 2, tg = lane & 3;

    const float* bp = bout + nt * 64;

#pragma unroll
    for (int mt2 = 0; mt2 < 2; mt2++) {
#pragma unroll
        for (int half = 0; half < 2; half++) {
            int m = mbase + wm + mt2 * 16 + g + half * 8;
            float* drow = out + (size_t)m * E_ + nt * 64;
#pragma unroll
            for (int nt2 = 0; nt2 < 4; nt2++) {
                int col = wn + nt2 * 8 + tg * 2;
                float2 v;
                v.x = C[mt2][nt2][half * 2 + 0] + bp[col];
                v.y = C[mt2][nt2][half * 2 + 1] + bp[col + 1];
                *(float2*)&drow[col] = v;
            }
        }
    }
}

// ---------------------------------------------------------------------------
// Causal flash attention, fp32 SIMT (unchanged; next optimization target)
// ---------------------------------------------------------------------------
__global__ __launch_bounds__(128) void attn_kernel() {
    __shared__ float Ks[64 * 64];
    __shared__ float Vs[64 * 64];

    int qt = (gridDim.x - 1) - blockIdx.x;
    int bh = blockIdx.y;
    int r  = threadIdx.x;
    int qrow = qt * 128 + r;

    const float* Qp = g_Q + ((size_t)bh * N_ + qrow) * HD_;
    float q[64];
    {
        const float4* Qv = (const float4*)Qp;
#pragma unroll
        for (int d4 = 0; d4 < 16; d4++) {
            float4 t = Qv[d4];
            q[4*d4] = t.x; q[4*d4+1] = t.y; q[4*d4+2] = t.z; q[4*d4+3] = t.w;
        }
    }
    float o[64];
#pragma unroll
    for (int d = 0; d < 64; d++) o[d] = 0.f;
    float mrun = -1e30f, lrun = 0.f;

    const float4* Kbase = (const float4*)(g_K + (size_t)bh * N_ * HD_);
    const float4* Vbase = (const float4*)(g_V + (size_t)bh * N_ * HD_);
    float4* Ksv = (float4*)Ks;
    float4* Vsv = (float4*)Vs;

    int nkt = 2 * qt + 2;
    for (int kt = 0; kt < nkt; kt++) {
        int off = kt * 64 * 16;
#pragma unroll
        for (int l = 0; l < 8; l++) {
            Ksv[r + l * 128] = Kbase[off + r + l * 128];
            Vsv[r + l * 128] = Vbase[off + r + l * 128];
        }
        __syncthreads();

        int kbase = kt * 64;
#pragma unroll 1
        for (int jc = 0; jc < 64; jc += 16) {
            float s[16];
            float smax = -1e30f;
#pragma unroll
            for (int jj = 0; jj < 16; jj++) {
                int j = jc + jj;
                const float4* krow = (const float4*)(Ks + j * 64);
                float acc = 0.f;
#pragma unroll
                for (int d4 = 0; d4 < 16; d4++) {
                    float4 kv = krow[d4];
                    acc += q[4*d4] * kv.x + q[4*d4+1] * kv.y
                         + q[4*d4+2] * kv.z + q[4*d4+3] * kv.w;
                }
                acc *= 0.125f;
                acc = (kbase + j <= qrow) ? acc : -1e30f;
                s[jj] = acc;
                smax = fmaxf(smax, acc);
            }
            float mnew = fmaxf(mrun, smax);
            float alpha = __expf(mrun - mnew);
            lrun *= alpha;
#pragma unroll
            for (int d = 0; d < 64; d++) o[d] *= alpha;
            mrun = mnew;
#pragma unroll
            for (int jj = 0; jj < 16; jj++) {
                float p = __expf(s[jj] - mnew);
                lrun += p;
                const float4* vrow = (const float4*)(Vs + (jc + jj) * 64);
#pragma unroll
                for (int d4 = 0; d4 < 16; d4++) {
                    float4 vv = vrow[d4];
                    o[4*d4]   += p * vv.x;
                    o[4*d4+1] += p * vv.y;
                    o[4*d4+2] += p * vv.z;
                    o[4*d4+3] += p * vv.w;
                }
            }
        }
        __syncthreads();
    }

    float inv = 1.f / lrun;
    int b = bh >> 4, h = bh & 15;
    float* orow = g_sa + ((size_t)(b * N_ + qrow)) * E_ + h * HD_;
    float4* orv = (float4*)orow;
#pragma unroll
    for (int d4 = 0; d4 < 16; d4++) {
        float4 t;
        t.x = o[4*d4] * inv;   t.y = o[4*d4+1] * inv;
        t.z = o[4*d4+2] * inv; t.w = o[4*d4+3] * inv;
        orv[d4] = t;
    }
}

// ---------------------------------------------------------------------------
extern "C" void kernel_launch(void* const* d_in, const int* in_sizes, int n_in,
                              void* d_out, int out_size) {
    const float* x    = (const float*)d_in[0];
    const float* Wqkv = (const float*)d_in[1];
    const float* bqkv = (const float*)d_in[2];
    const float* Wout = (const float*)d_in[3];
    const float* bout = (const float*)d_in[4];
    float* out = (float*)d_out;

    // 1. operand conversions (write __device__ globals directly)
    split_x_kernel<<<2048, 256>>>(x);
    tsplit_wq_kernel<<<dim3(6, 32, 16), dim3(32, 8)>>>(Wqkv);
    tsplit_wo_kernel<<<dim3(32, 32, 1), dim3(32, 8)>>>(Wout);

    // 2. QKV projection (mma.sync bf16, split 3-pass)
    qkv_mma_kernel<<<dim3(3, 32, 16), 256>>>(bqkv);

    // 3. attention (fp32 SIMT)
    attn_kernel<<<dim3(16, 32), 128>>>();

    // 4. convert attention output, output projection (mma.sync bf16)
    split_sa_kernel<<<2048, 256>>>();
    outproj_mma_kernel<<<dim3(16, 32), 256>>>(bout, out);
}

// round 6
// speedup vs baseline: 2.5429x; 1.9249x over previous
#include <cuda_runtime.h>
#include <cuda_bf16.h>
#include <math.h>
#include <stdint.h>

#define B_ 2
#define N_ 2048
#define E_ 1024
#define H_ 16
#define HD_ 64

// ---------------------------------------------------------------------------
// Scratch (__device__ globals; allocation-free rule)
// ---------------------------------------------------------------------------
__device__ __nv_bfloat16 g_xh[(size_t)4096*1024];
__device__ __nv_bfloat16 g_xl[(size_t)4096*1024];
__device__ __nv_bfloat16 g_wqh[(size_t)16*192*1024];   // [h][n][k] (transposed)
__device__ __nv_bfloat16 g_wql[(size_t)16*192*1024];
__device__ __nv_bfloat16 g_woh[(size_t)1024*1024];     // [n][k] (transposed)
__device__ __nv_bfloat16 g_wol[(size_t)1024*1024];
__device__ __nv_bfloat16 g_sah[(size_t)4096*1024];
__device__ __nv_bfloat16 g_sal[(size_t)4096*1024];

// Q/K/V bf16 hi/lo, layout [bh][n][64]
__device__ __nv_bfloat16 g_Qh[(size_t)B_*H_*N_*HD_];
__device__ __nv_bfloat16 g_Ql[(size_t)B_*H_*N_*HD_];
__device__ __nv_bfloat16 g_Kh[(size_t)B_*H_*N_*HD_];
__device__ __nv_bfloat16 g_Kl[(size_t)B_*H_*N_*HD_];
__device__ __nv_bfloat16 g_Vh[(size_t)B_*H_*N_*HD_];
__device__ __nv_bfloat16 g_Vl[(size_t)B_*H_*N_*HD_];

// ---------------------------------------------------------------------------
// mma.sync m16n8k16 bf16 (baseline PTX feature set)
// ---------------------------------------------------------------------------
__device__ __forceinline__ void mma_bf16(float* c, const uint32_t* a, const uint32_t* b) {
    asm volatile(
        "mma.sync.aligned.m16n8k16.row.col.f32.bf16.bf16.f32 "
        "{%0,%1,%2,%3},{%4,%5,%6,%7},{%8,%9},{%0,%1,%2,%3};"
        : "+f"(c[0]), "+f"(c[1]), "+f"(c[2]), "+f"(c[3])
        : "r"(a[0]), "r"(a[1]), "r"(a[2]), "r"(a[3]), "r"(b[0]), "r"(b[1]));
}

// pack two floats -> bf16x2 (lo = first arg, hi = second)
__device__ __forceinline__ uint32_t pack_bf16(float lo, float hi) {
    uint32_t r;
    asm("cvt.rn.bf16x2.f32 %0, %1, %2;" : "=r"(r) : "f"(hi), "f"(lo));
    return r;
}

__device__ __forceinline__ void split_store_pair(float vx, float vy,
                                                 __nv_bfloat16* dh, __nv_bfloat16* dl) {
    __nv_bfloat16 hx = __float2bfloat16(vx);
    __nv_bfloat16 hy = __float2bfloat16(vy);
    union { __nv_bfloat162 v; uint32_t u; } H, L;
    H.v.x = hx; H.v.y = hy;
    L.v.x = __float2bfloat16(vx - __bfloat162float(hx));
    L.v.y = __float2bfloat16(vy - __bfloat162float(hy));
    *(uint32_t*)dh = H.u;
    *(uint32_t*)dl = L.u;
}

// ---------------------------------------------------------------------------
// Conversion kernels
// ---------------------------------------------------------------------------
__device__ __forceinline__ void split_body(const float* __restrict__ src,
                                           __nv_bfloat16* __restrict__ hi,
                                           __nv_bfloat16* __restrict__ lo, int n4) {
    int i = blockIdx.x * blockDim.x + threadIdx.x;
    int stride = gridDim.x * blockDim.x;
    for (; i < n4; i += stride) {
        float4 v = ((const float4*)src)[i];
        union { __nv_bfloat16 b[4]; uint2 u; } Hh, Ll;
        float vs[4] = {v.x, v.y, v.z, v.w};
#pragma unroll
        for (int j = 0; j < 4; j++) {
            __nv_bfloat16 h = __float2bfloat16(vs[j]);
            Hh.b[j] = h;
            Ll.b[j] = __float2bfloat16(vs[j] - __bfloat162float(h));
        }
        ((uint2*)hi)[i] = Hh.u;
        ((uint2*)lo)[i] = Ll.u;
    }
}

__global__ void split_x_kernel(const float* __restrict__ x) {
    split_body(x, g_xh, g_xl, 4096 * 1024 / 4);
}

// out[z][c][r] = in[z][r][c]
__device__ __forceinline__ void tsplit_body(const float* __restrict__ in,
                                            __nv_bfloat16* __restrict__ oh,
                                            __nv_bfloat16* __restrict__ ol,
                                            int R, int C) {
    __shared__ float t[32][33];
    size_t zo = (size_t)blockIdx.z * R * C;
    in += zo; oh += zo; ol += zo;
    int c0 = blockIdx.x * 32, r0 = blockIdx.y * 32;
    int tx = threadIdx.x, ty = threadIdx.y;
#pragma unroll
    for (int i = 0; i < 32; i += 8)
        t[ty + i][tx] = in[(size_t)(r0 + ty + i) * C + c0 + tx];
    __syncthreads();
#pragma unroll
    for (int i = 0; i < 32; i += 8) {
        float v = t[tx][ty + i];
        __nv_bfloat16 h = __float2bfloat16(v);
        oh[(size_t)(c0 + ty + i) * R + r0 + tx] = h;
        ol[(size_t)(c0 + ty + i) * R + r0 + tx] = __float2bfloat16(v - __bfloat162float(h));
    }
}

__global__ void tsplit_wq_kernel(const float* __restrict__ Wqkv) {
    tsplit_body(Wqkv, g_wqh, g_wql, 1024, 192);
}
__global__ void tsplit_wo_kernel(const float* __restrict__ Wout) {
    tsplit_body(Wout, g_woh, g_wol, 1024, 1024);
}

// ---------------------------------------------------------------------------
// Warp-MMA GEMM mainloop (proven R4): C[128x64] = A[128x1024] @ B[64x1024]^T
// ---------------------------------------------------------------------------
#define ASTR 40
#define BSTR 40

__device__ __forceinline__ void gemm_bf16_mainloop(
    const uint2* __restrict__ Ahg, const uint2* __restrict__ Alg,
    const uint2* __restrict__ Bhg, const uint2* __restrict__ Blg,
    float C[2][4][4])
{
    __shared__ __nv_bfloat16 sAh[128 * ASTR];
    __shared__ __nv_bfloat16 sAl[128 * ASTR];
    __shared__ __nv_bfloat16 sBh[64 * BSTR];
    __shared__ __nv_bfloat16 sBl[64 * BSTR];

    int tid = threadIdx.x;
    int lane = tid & 31, w = tid >> 5;
    int wm = (w & 3) * 32, wn = (w >> 2) * 32;
    int g = lane >> 2, tg = lane & 3;

#pragma unroll
    for (int mt = 0; mt < 2; mt++)
#pragma unroll
        for (int nt = 0; nt < 4; nt++)
#pragma unroll
            for (int i = 0; i < 4; i++) C[mt][nt][i] = 0.f;

    const uint32_t* wAh = (const uint32_t*)sAh;
    const uint32_t* wAl = (const uint32_t*)sAl;
    const uint32_t* wBh = (const uint32_t*)sBh;
    const uint32_t* wBl = (const uint32_t*)sBl;

    for (int kc = 0; kc < 32; kc++) {
        int kb2 = kc * 8;
#pragma unroll
        for (int p = 0; p < 4; p++) {
            int idx = tid + p * 256;
            int r = idx >> 3, c = idx & 7;
            *(uint2*)&sAh[r * ASTR + c * 4] = Ahg[(size_t)r * 256 + kb2 + c];
            *(uint2*)&sAl[r * ASTR + c * 4] = Alg[(size_t)r * 256 + kb2 + c];
        }
#pragma unroll
        for (int p = 0; p < 2; p++) {
            int idx = tid + p * 256;
            int r = idx >> 3, c = idx & 7;
            *(uint2*)&sBh[r * BSTR + c * 4] = Bhg[(size_t)r * 256 + kb2 + c];
            *(uint2*)&sBl[r * BSTR + c * 4] = Blg[(size_t)r * 256 + kb2 + c];
        }
        __syncthreads();

#pragma unroll
        for (int k16 = 0; k16 < 2; k16++) {
            int ko = k16 * 16;
            uint32_t ah[2][4], al[2][4], bh[4][2], bl[4][2];
#pragma unroll
            for (int mt = 0; mt < 2; mt++) {
                int r0 = wm + mt * 16;
                int i0 = ((r0 + g) * ASTR + ko + tg * 2) >> 1;
                int i1 = ((r0 + g + 8) * ASTR + ko + tg * 2) >> 1;
                ah[mt][0] = wAh[i0]; ah[mt][1] = wAh[i1];
                ah[mt][2] = wAh[i0 + 4]; ah[mt][3] = wAh[i1 + 4];
                al[mt][0] = wAl[i0]; al[mt][1] = wAl[i1];
                al[mt][2] = wAl[i0 + 4]; al[mt][3] = wAl[i1 + 4];
            }
#pragma unroll
            for (int nt = 0; nt < 4; nt++) {
                int n0 = wn + nt * 8;
                int j0 = ((n0 + g) * BSTR + ko + tg * 2) >> 1;
                bh[nt][0] = wBh[j0]; bh[nt][1] = wBh[j0 + 4];
                bl[nt][0] = wBl[j0]; bl[nt][1] = wBl[j0 + 4];
            }
#pragma unroll
            for (int mt = 0; mt < 2; mt++)
#pragma unroll
                for (int nt = 0; nt < 4; nt++) {
                    mma_bf16(C[mt][nt], ah[mt], bh[nt]);
                    mma_bf16(C[mt][nt], ah[mt], bl[nt]);
                    mma_bf16(C[mt][nt], al[mt], bh[nt]);
                }
        }
        __syncthreads();
    }
}

// ---------------------------------------------------------------------------
// QKV: writes bf16 hi/lo Q/K/V directly. grid = (3, 32, 16), block = 256
// ---------------------------------------------------------------------------
__global__ __launch_bounds__(256) void qkv_mma_kernel(const float* __restrict__ bqkv) {
    int nt = blockIdx.x, mt = blockIdx.y, h = blockIdx.z;
    int mbase = mt * 128;

    const uint2* Ahg = (const uint2*)g_xh + (size_t)mbase * 256;
    const uint2* Alg = (const uint2*)g_xl + (size_t)mbase * 256;
    size_t boff = ((size_t)h * 192 + nt * 64) * 256;
    const uint2* Bhg = (const uint2*)g_wqh + boff;
    const uint2* Blg = (const uint2*)g_wql + boff;

    float C[2][4][4];
    gemm_bf16_mainloop(Ahg, Alg, Bhg, Blg, C);

    int lane = threadIdx.x & 31, w = threadIdx.x >> 5;
    int wm = (w & 3) * 32, wn = (w >> 2) * 32;
    int g = lane >> 2, tg = lane & 3;

    const float* bp = bqkv + h * 192 + nt * 64;
    __nv_bfloat16* dh = (nt == 0) ? g_Kh : (nt == 1) ? g_Qh : g_Vh;
    __nv_bfloat16* dl = (nt == 0) ? g_Kl : (nt == 1) ? g_Ql : g_Vl;

#pragma unroll
    for (int mt2 = 0; mt2 < 2; mt2++) {
#pragma unroll
        for (int half = 0; half < 2; half++) {
            int m = mbase + wm + mt2 * 16 + g + half * 8;
            int b = m >> 11, n = m & 2047;
            size_t ro = (((size_t)(b * H_ + h)) * N_ + n) * HD_;
#pragma unroll
            for (int nt2 = 0; nt2 < 4; nt2++) {
                int col = wn + nt2 * 8 + tg * 2;
                float vx = C[mt2][nt2][half * 2 + 0] + bp[col];
                float vy = C[mt2][nt2][half * 2 + 1] + bp[col + 1];
                split_store_pair(vx, vy, dh + ro + col, dl + ro + col);
            }
        }
    }
}

// ---------------------------------------------------------------------------
// Tensor-core causal flash attention.
// Block = 128 q rows of one (b,h); 8 warps x 16 rows; warp owns full rows.
// S and O via split-bf16 3-pass mma. grid = (16, 32), block = 256.
// ---------------------------------------------------------------------------
#define KSTR 72   // padded row stride (halves) for 64-wide K/V tiles

__global__ __launch_bounds__(256) void attn_mma_kernel() {
    __shared__ __nv_bfloat16 sKh[64 * KSTR];
    __shared__ __nv_bfloat16 sKl[64 * KSTR];
    __shared__ __nv_bfloat16 sVh[64 * KSTR];
    __shared__ __nv_bfloat16 sVl[64 * KSTR];

    int qt = (int)(gridDim.x - 1) - (int)blockIdx.x;   // heavy tiles first
    int bh = blockIdx.y;
    int tid = threadIdx.x, lane = tid & 31, w = tid >> 5;
    int g = lane >> 2, tg = lane & 3;
    int qbase = qt * 128, wrow = w * 16;
    int row0 = qbase + wrow + g, row1 = row0 + 8;

    // Q fragments (hi/lo) straight from gmem
    const __nv_bfloat16* Qh = g_Qh + ((size_t)bh * N_ + qbase + wrow) * HD_;
    const __nv_bfloat16* Ql = g_Ql + ((size_t)bh * N_ + qbase + wrow) * HD_;
    uint32_t qh[4][4], ql[4][4];
#pragma unroll
    for (int ko = 0; ko < 4; ko++) {
        int c = ko * 16 + tg * 2;
        qh[ko][0] = *(const uint32_t*)&Qh[(size_t)g * 64 + c];
        qh[ko][1] = *(const uint32_t*)&Qh[(size_t)(g + 8) * 64 + c];
        qh[ko][2] = *(const uint32_t*)&Qh[(size_t)g * 64 + c + 8];
        qh[ko][3] = *(const uint32_t*)&Qh[(size_t)(g + 8) * 64 + c + 8];
        ql[ko][0] = *(const uint32_t*)&Ql[(size_t)g * 64 + c];
        ql[ko][1] = *(const uint32_t*)&Ql[(size_t)(g + 8) * 64 + c];
        ql[ko][2] = *(const uint32_t*)&Ql[(size_t)g * 64 + c + 8];
        ql[ko][3] = *(const uint32_t*)&Ql[(size_t)(g + 8) * 64 + c + 8];
    }

    float Co[8][4];
#pragma unroll
    for (int nt = 0; nt < 8; nt++)
#pragma unroll
        for (int i = 0; i < 4; i++) Co[nt][i] = 0.f;
    float m0 = -1e30f, m1 = -1e30f, l0 = 0.f, l1 = 0.f;

    const uint4* KhG = (const uint4*)(g_Kh + (size_t)bh * N_ * HD_);
    const uint4* KlG = (const uint4*)(g_Kl + (size_t)bh * N_ * HD_);
    const uint4* VhG = (const uint4*)(g_Vh + (size_t)bh * N_ * HD_);
    const uint4* VlG = (const uint4*)(g_Vl + (size_t)bh * N_ * HD_);

    int nkt = 2 * qt + 2;
    for (int kt = 0; kt < nkt; kt++) {
        int base4 = kt * 64 * 8;
#pragma unroll
        for (int p = 0; p < 2; p++) {
            int idx = tid + p * 256;
            int r = idx >> 3, c = idx & 7;
            uint32_t so = (uint32_t)(r * KSTR + c * 8);
            *(uint4*)&sKh[so] = KhG[base4 + idx];
            *(uint4*)&sKl[so] = KlG[base4 + idx];
            *(uint4*)&sVh[so] = VhG[base4 + idx];
            *(uint4*)&sVl[so] = VlG[base4 + idx];
        }
        __syncthreads();

        // ---- S = Q K^T (3-pass split) ----
        float Cs[8][4];
#pragma unroll
        for (int nt = 0; nt < 8; nt++)
#pragma unroll
            for (int i = 0; i < 4; i++) Cs[nt][i] = 0.f;

#pragma unroll
        for (int ko = 0; ko < 4; ko++) {
            int c = ko * 16 + tg * 2;
#pragma unroll
            for (int nt = 0; nt < 8; nt++) {
                int kr = nt * 8 + g;
                uint32_t bh2[2], bl2[2];
                bh2[0] = *(const uint32_t*)&sKh[kr * KSTR + c];
                bh2[1] = *(const uint32_t*)&sKh[kr * KSTR + c + 8];
                bl2[0] = *(const uint32_t*)&sKl[kr * KSTR + c];
                bl2[1] = *(const uint32_t*)&sKl[kr * KSTR + c + 8];
                mma_bf16(Cs[nt], qh[ko], bh2);
                mma_bf16(Cs[nt], ql[ko], bh2);
                mma_bf16(Cs[nt], qh[ko], bl2);
            }
        }

        // ---- mask + scale + row max ----
        int kb = kt * 64;
        float mt0 = -1e30f, mt1 = -1e30f;
#pragma unroll
        for (int nt = 0; nt < 8; nt++) {
            int col = kb + nt * 8 + tg * 2;
#pragma unroll
            for (int j = 0; j < 2; j++) {
                float v0 = Cs[nt][j] * 0.125f;
                float v1 = Cs[nt][2 + j] * 0.125f;
                v0 = (col + j <= row0) ? v0 : -1e30f;
                v1 = (col + j <= row1) ? v1 : -1e30f;
                Cs[nt][j] = v0; Cs[nt][2 + j] = v1;
                mt0 = fmaxf(mt0, v0); mt1 = fmaxf(mt1, v1);
            }
        }
        mt0 = fmaxf(mt0, __shfl_xor_sync(0xffffffffu, mt0, 1));
        mt0 = fmaxf(mt0, __shfl_xor_sync(0xffffffffu, mt0, 2));
        mt1 = fmaxf(mt1, __shfl_xor_sync(0xffffffffu, mt1, 1));
        mt1 = fmaxf(mt1, __shfl_xor_sync(0xffffffffu, mt1, 2));

        float mn0 = fmaxf(m0, mt0), mn1 = fmaxf(m1, mt1);
        float a0 = __expf(m0 - mn0), a1 = __expf(m1 - mn1);
        m0 = mn0; m1 = mn1;
        l0 *= a0; l1 *= a1;
#pragma unroll
        for (int nt = 0; nt < 8; nt++) {
            Co[nt][0] *= a0; Co[nt][1] *= a0;
            Co[nt][2] *= a1; Co[nt][3] *= a1;
        }

        // ---- exp + row sums ----
        float s0 = 0.f, s1 = 0.f;
#pragma unroll
        for (int nt = 0; nt < 8; nt++) {
#pragma unroll
            for (int j = 0; j < 2; j++) {
                float p0 = __expf(Cs[nt][j] - m0);
                float p1 = __expf(Cs[nt][2 + j] - m1);
                Cs[nt][j] = p0; Cs[nt][2 + j] = p1;
                s0 += p0; s1 += p1;
            }
        }
        s0 += __shfl_xor_sync(0xffffffffu, s0, 1);
        s0 += __shfl_xor_sync(0xffffffffu, s0, 2);
        s1 += __shfl_xor_sync(0xffffffffu, s1, 1);
        s1 += __shfl_xor_sync(0xffffffffu, s1, 2);
        l0 += s0; l1 += s1;

        // ---- O += P V (3-pass split); P fragments built in registers ----
#pragma unroll
        for (int ko = 0; ko < 4; ko++) {
            uint32_t ph[4], pl[4];
            ph[0] = pack_bf16(Cs[2 * ko][0], Cs[2 * ko][1]);
            ph[1] = pack_bf16(Cs[2 * ko][2], Cs[2 * ko][3]);
            ph[2] = pack_bf16(Cs[2 * ko + 1][0], Cs[2 * ko + 1][1]);
            ph[3] = pack_bf16(Cs[2 * ko + 1][2], Cs[2 * ko + 1][3]);
#pragma unroll
            for (int i = 0; i < 4; i++) {
                const float* src = &Cs[2 * ko + (i >> 1)][(i & 1) * 2];
                union { uint32_t u; __nv_bfloat162 v; } U; U.u = ph[i];
                pl[i] = pack_bf16(src[0] - __bfloat162float(U.v.x),
                                  src[1] - __bfloat162float(U.v.y));
            }
            int krow = ko * 16 + tg * 2;
#pragma unroll
            for (int nt = 0; nt < 8; nt++) {
                int d = nt * 8 + g;
                uint32_t vh2[2], vl2[2];
                {
                    uint32_t x0 = *(const unsigned short*)&sVh[krow * KSTR + d];
                    uint32_t x1 = *(const unsigned short*)&sVh[(krow + 1) * KSTR + d];
                    uint32_t x2 = *(const unsigned short*)&sVh[(krow + 8) * KSTR + d];
                    uint32_t x3 = *(const unsigned short*)&sVh[(krow + 9) * KSTR + d];
                    vh2[0] = x0 | (x1 << 16);
                    vh2[1] = x2 | (x3 << 16);
                }
                {
                    uint32_t x0 = *(const unsigned short*)&sVl[krow * KSTR + d];
                    uint32_t x1 = *(const unsigned short*)&sVl[(krow + 1) * KSTR + d];
                    uint32_t x2 = *(const unsigned short*)&sVl[(krow + 8) * KSTR + d];
                    uint32_t x3 = *(const unsigned short*)&sVl[(krow + 9) * KSTR + d];
                    vl2[0] = x0 | (x1 << 16);
                    vl2[1] = x2 | (x3 << 16);
                }
                mma_bf16(Co[nt], ph, vh2);
                mma_bf16(Co[nt], ph, vl2);
                mma_bf16(Co[nt], pl, vh2);
            }
        }
        __syncthreads();
    }

    // ---- finalize: O /= l, write bf16 hi/lo into sa layout [b][n][E] ----
    float inv0 = 1.f / l0, inv1 = 1.f / l1;
    int b = bh >> 4, h = bh & 15;
    size_t ro0 = ((size_t)(b * N_) + row0) * E_ + h * HD_;
    size_t ro1 = ((size_t)(b * N_) + row1) * E_ + h * HD_;
#pragma unroll
    for (int nt = 0; nt < 8; nt++) {
        int col = nt * 8 + tg * 2;
        split_store_pair(Co[nt][0] * inv0, Co[nt][1] * inv0,
                         g_sah + ro0 + col, g_sal + ro0 + col);
        split_store_pair(Co[nt][2] * inv1, Co[nt][3] * inv1,
                         g_sah + ro1 + col, g_sal + ro1 + col);
    }
}

// ---------------------------------------------------------------------------
// Output projection: out[4096 x 1024] = sa @ Wout + bout. grid = (16, 32)
// ---------------------------------------------------------------------------
__global__ __launch_bounds__(256) void outproj_mma_kernel(const float* __restrict__ bout,
                                                          float* __restrict__ out) {
    int nt = blockIdx.x, mt = blockIdx.y;
    int mbase = mt * 128;

    const uint2* Ahg = (const uint2*)g_sah + (size_t)mbase * 256;
    const uint2* Alg = (const uint2*)g_sal + (size_t)mbase * 256;
    size_t boff = (size_t)nt * 64 * 256;
    const uint2* Bhg = (const uint2*)g_woh + boff;
    const uint2* Blg = (const uint2*)g_wol + boff;

    float C[2][4][4];
    gemm_bf16_mainloop(Ahg, Alg, Bhg, Blg, C);

    int lane = threadIdx.x & 31, w = threadIdx.x >> 5;
    int wm = (w & 3) * 32, wn = (w >> 2) * 32;
    int g = lane >> 2, tg = lane & 3;

    const float* bp = bout + nt * 64;

#pragma unroll
    for (int mt2 = 0; mt2 < 2; mt2++) {
#pragma unroll
        for (int half = 0; half < 2; half++) {
            int m = mbase + wm + mt2 * 16 + g + half * 8;
            float* drow = out + (size_t)m * E_ + nt * 64;
#pragma unroll
            for (int nt2 = 0; nt2 < 4; nt2++) {
                int col = wn + nt2 * 8 + tg * 2;
                float2 v;
                v.x = C[mt2][nt2][half * 2 + 0] + bp[col];
                v.y = C[mt2][nt2][half * 2 + 1] + bp[col + 1];
                *(float2*)&drow[col] = v;
            }
        }
    }
}

// ---------------------------------------------------------------------------
extern "C" void kernel_launch(void* const* d_in, const int* in_sizes, int n_in,
                              void* d_out, int out_size) {
    const float* x    = (const float*)d_in[0];
    const float* Wqkv = (const float*)d_in[1];
    const float* bqkv = (const float*)d_in[2];
    const float* Wout = (const float*)d_in[3];
    const float* bout = (const float*)d_in[4];
    float* out = (float*)d_out;

    split_x_kernel<<<2048, 256>>>(x);
    tsplit_wq_kernel<<<dim3(6, 32, 16), dim3(32, 8)>>>(Wqkv);
    tsplit_wo_kernel<<<dim3(32, 32, 1), dim3(32, 8)>>>(Wout);

    qkv_mma_kernel<<<dim3(3, 32, 16), 256>>>(bqkv);

    attn_mma_kernel<<<dim3(16, 32), 256>>>();

    outproj_mma_kernel<<<dim3(16, 32), 256>>>(bout, out);
}

// round 7
// speedup vs baseline: 3.4589x; 1.3602x over previous
#include <cuda_runtime.h>
#include <cuda_bf16.h>
#include <math.h>
#include <stdint.h>

#define B_ 2
#define N_ 2048
#define E_ 1024
#define H_ 16
#define HD_ 64

// ---------------------------------------------------------------------------
// Scratch (__device__ globals; allocation-free rule)
// ---------------------------------------------------------------------------
__device__ __nv_bfloat16 g_xh[(size_t)4096*1024];
__device__ __nv_bfloat16 g_xl[(size_t)4096*1024];
__device__ __nv_bfloat16 g_wqh[(size_t)16*192*1024];   // [h][n][k] (transposed)
__device__ __nv_bfloat16 g_wql[(size_t)16*192*1024];
__device__ __nv_bfloat16 g_woh[(size_t)1024*1024];     // [n][k] (transposed)
__device__ __nv_bfloat16 g_wol[(size_t)1024*1024];
__device__ __nv_bfloat16 g_sah[(size_t)4096*1024];
__device__ __nv_bfloat16 g_sal[(size_t)4096*1024];

// Q/K/V bf16 hi/lo, layout [bh][n][64]
__device__ __nv_bfloat16 g_Qh[(size_t)B_*H_*N_*HD_];
__device__ __nv_bfloat16 g_Ql[(size_t)B_*H_*N_*HD_];
__device__ __nv_bfloat16 g_Kh[(size_t)B_*H_*N_*HD_];
__device__ __nv_bfloat16 g_Kl[(size_t)B_*H_*N_*HD_];
__device__ __nv_bfloat16 g_Vh[(size_t)B_*H_*N_*HD_];
__device__ __nv_bfloat16 g_Vl[(size_t)B_*H_*N_*HD_];

// ---------------------------------------------------------------------------
// PTX helpers (all baseline-PTX features: mma.sync sm_80, ldmatrix sm_75,
// cp.async sm_80 — compile at compute_103)
// ---------------------------------------------------------------------------
__device__ __forceinline__ void mma_bf16(float* c, const uint32_t* a, const uint32_t* b) {
    asm volatile(
        "mma.sync.aligned.m16n8k16.row.col.f32.bf16.bf16.f32 "
        "{%0,%1,%2,%3},{%4,%5,%6,%7},{%8,%9},{%0,%1,%2,%3};"
        : "+f"(c[0]), "+f"(c[1]), "+f"(c[2]), "+f"(c[3])
        : "r"(a[0]), "r"(a[1]), "r"(a[2]), "r"(a[3]), "r"(b[0]), "r"(b[1]));
}

__device__ __forceinline__ void ldsm_x4(uint32_t* r, uint32_t addr) {
    asm volatile("ldmatrix.sync.aligned.m8n8.x4.shared.b16 {%0,%1,%2,%3}, [%4];"
        : "=r"(r[0]), "=r"(r[1]), "=r"(r[2]), "=r"(r[3]) : "r"(addr));
}
__device__ __forceinline__ void ldsm_x4_t(uint32_t* r, uint32_t addr) {
    asm volatile("ldmatrix.sync.aligned.m8n8.x4.trans.shared.b16 {%0,%1,%2,%3}, [%4];"
        : "=r"(r[0]), "=r"(r[1]), "=r"(r[2]), "=r"(r[3]) : "r"(addr));
}

#define CP_ASYNC16(dst, src) \
    asm volatile("cp.async.cg.shared.global [%0], [%1], 16;" :: "r"(dst), "l"(src))
#define CP_COMMIT() asm volatile("cp.async.commit_group;" ::: "memory")
#define CP_WAIT0()  asm volatile("cp.async.wait_group 0;" ::: "memory")

__device__ __forceinline__ uint32_t smem_u32(const void* p) {
    return (uint32_t)__cvta_generic_to_shared(p);
}

// 128B rows, classic SW128: 16B slot s of row r lives at slot s^(r&7)
#define SWB(r, s) ((uint32_t)((r) * 128 + (((s) ^ ((r) & 7)) << 4)))

// pack two floats -> bf16x2 (lo = first arg, hi = second)
__device__ __forceinline__ uint32_t pack_bf16(float lo, float hi) {
    uint32_t r;
    asm("cvt.rn.bf16x2.f32 %0, %1, %2;" : "=r"(r) : "f"(hi), "f"(lo));
    return r;
}

__device__ __forceinline__ void split_store_pair(float vx, float vy,
                                                 __nv_bfloat16* dh, __nv_bfloat16* dl) {
    __nv_bfloat16 hx = __float2bfloat16(vx);
    __nv_bfloat16 hy = __float2bfloat16(vy);
    union { __nv_bfloat162 v; uint32_t u; } H, L;
    H.v.x = hx; H.v.y = hy;
    L.v.x = __float2bfloat16(vx - __bfloat162float(hx));
    L.v.y = __float2bfloat16(vy - __bfloat162float(hy));
    *(uint32_t*)dh = H.u;
    *(uint32_t*)dl = L.u;
}

// ---------------------------------------------------------------------------
// Conversion kernels (unchanged from R5)
// ---------------------------------------------------------------------------
__device__ __forceinline__ void split_body(const float* __restrict__ src,
                                           __nv_bfloat16* __restrict__ hi,
                                           __nv_bfloat16* __restrict__ lo, int n4) {
    int i = blockIdx.x * blockDim.x + threadIdx.x;
    int stride = gridDim.x * blockDim.x;
    for (; i < n4; i += stride) {
        float4 v = ((const float4*)src)[i];
        union { __nv_bfloat16 b[4]; uint2 u; } Hh, Ll;
        float vs[4] = {v.x, v.y, v.z, v.w};
#pragma unroll
        for (int j = 0; j < 4; j++) {
            __nv_bfloat16 h = __float2bfloat16(vs[j]);
            Hh.b[j] = h;
            Ll.b[j] = __float2bfloat16(vs[j] - __bfloat162float(h));
        }
        ((uint2*)hi)[i] = Hh.u;
        ((uint2*)lo)[i] = Ll.u;
    }
}

__global__ void split_x_kernel(const float* __restrict__ x) {
    split_body(x, g_xh, g_xl, 4096 * 1024 / 4);
}

__device__ __forceinline__ void tsplit_body(const float* __restrict__ in,
                                            __nv_bfloat16* __restrict__ oh,
                                            __nv_bfloat16* __restrict__ ol,
                                            int R, int C) {
    __shared__ float t[32][33];
    size_t zo = (size_t)blockIdx.z * R * C;
    in += zo; oh += zo; ol += zo;
    int c0 = blockIdx.x * 32, r0 = blockIdx.y * 32;
    int tx = threadIdx.x, ty = threadIdx.y;
#pragma unroll
    for (int i = 0; i < 32; i += 8)
        t[ty + i][tx] = in[(size_t)(r0 + ty + i) * C + c0 + tx];
    __syncthreads();
#pragma unroll
    for (int i = 0; i < 32; i += 8) {
        float v = t[tx][ty + i];
        __nv_bfloat16 h = __float2bfloat16(v);
        oh[(size_t)(c0 + ty + i) * R + r0 + tx] = h;
        ol[(size_t)(c0 + ty + i) * R + r0 + tx] = __float2bfloat16(v - __bfloat162float(h));
    }
}

__global__ void tsplit_wq_kernel(const float* __restrict__ Wqkv) {
    tsplit_body(Wqkv, g_wqh, g_wql, 1024, 192);
}
__global__ void tsplit_wo_kernel(const float* __restrict__ Wout) {
    tsplit_body(Wout, g_woh, g_wol, 1024, 1024);
}

// ---------------------------------------------------------------------------
// GEMM mainloop v2: cp.async double-buffered + ldmatrix fragments.
// C[128x64] = A[128x1024] @ B[64x1024]^T, split-bf16 3-pass.
// Smem layout: per stage, A rows = 128B: [hi k0..31 | lo k0..31], SW128 swizzle.
//              B rows same, 64 rows. 2 stages = 48KB exactly.
// 256 threads, 8 warps 4m x 2n, warp tile 32x32.
// ---------------------------------------------------------------------------
struct GemmSmem {
    __nv_bfloat16 A[2][128 * 64];   // 16KB / stage
    __nv_bfloat16 Bt[2][64 * 64];   //  8KB / stage
};

__device__ __forceinline__ void gemm_stage(
    uint32_t sA, uint32_t sB,
    const uint4* __restrict__ Ah4, const uint4* __restrict__ Al4,
    const uint4* __restrict__ Bh4, const uint4* __restrict__ Bl4,
    int kb4, int tid)
{
#pragma unroll
    for (int p = 0; p < 4; p++) {
        int idx = tid + p * 256;
        int r = idx >> 3, s = idx & 7;
        const uint4* src = (s < 4) ? (Ah4 + (size_t)r * 128 + kb4 + s)
                                   : (Al4 + (size_t)r * 128 + kb4 + (s - 4));
        CP_ASYNC16(sA + SWB(r, s), src);
    }
#pragma unroll
    for (int p = 0; p < 2; p++) {
        int idx = tid + p * 256;
        int r = idx >> 3, s = idx & 7;
        const uint4* src = (s < 4) ? (Bh4 + (size_t)r * 128 + kb4 + s)
                                   : (Bl4 + (size_t)r * 128 + kb4 + (s - 4));
        CP_ASYNC16(sB + SWB(r, s), src);
    }
}

__device__ __forceinline__ void gemm_bf16_mainloop(
    GemmSmem& S,
    const uint4* __restrict__ Ah4, const uint4* __restrict__ Al4,
    const uint4* __restrict__ Bh4, const uint4* __restrict__ Bl4,
    float C[2][4][4])
{
    int tid = threadIdx.x;
    int lane = tid & 31, w = tid >> 5;
    int wm = (w & 3) * 32, wn = (w >> 2) * 32;

#pragma unroll
    for (int mt = 0; mt < 2; mt++)
#pragma unroll
        for (int nt = 0; nt < 4; nt++)
#pragma unroll
            for (int i = 0; i < 4; i++) C[mt][nt][i] = 0.f;

    uint32_t sA0 = smem_u32(S.A[0]), sA1 = smem_u32(S.A[1]);
    uint32_t sB0 = smem_u32(S.Bt[0]), sB1 = smem_u32(S.Bt[1]);

    // ldmatrix per-lane address pieces
    int aRow = (lane & 15);                                  // + wm + mt*16
    int aSlotSel = (lane >> 4) & 1;                          // hi-slot bit
    int bRow = (lane & 7) + ((lane >> 4) & 1) * 8;           // + wn + p*16
    int bSlotSel = (lane >> 3) & 1;

    gemm_stage(sA0, sB0, Ah4, Al4, Bh4, Bl4, 0, tid);
    CP_COMMIT();

    for (int kc = 0; kc < 32; kc++) {
        CP_WAIT0();
        __syncthreads();
        if (kc + 1 < 32) {
            gemm_stage((kc & 1) ? sA0 : sA1, (kc & 1) ? sB0 : sB1,
                       Ah4, Al4, Bh4, Bl4, (kc + 1) * 4, tid);
            CP_COMMIT();
        }
        uint32_t sA = (kc & 1) ? sA1 : sA0;
        uint32_t sB = (kc & 1) ? sB1 : sB0;

#pragma unroll
        for (int k16 = 0; k16 < 2; k16++) {
            int shi = k16 * 2, slo = 4 + k16 * 2;
            uint32_t ah[2][4], al[2][4], bh[4][2], bl[4][2];
#pragma unroll
            for (int mt = 0; mt < 2; mt++) {
                int row = wm + mt * 16 + aRow;
                ldsm_x4(ah[mt], sA + SWB(row, shi + aSlotSel));
                ldsm_x4(al[mt], sA + SWB(row, slo + aSlotSel));
            }
#pragma unroll
            for (int p = 0; p < 2; p++) {
                int row = wn + p * 16 + bRow;
                uint32_t r4[4];
                ldsm_x4(r4, sB + SWB(row, shi + bSlotSel));
                bh[2 * p][0] = r4[0]; bh[2 * p][1] = r4[1];
                bh[2 * p + 1][0] = r4[2]; bh[2 * p + 1][1] = r4[3];
                ldsm_x4(r4, sB + SWB(row, slo + bSlotSel));
                bl[2 * p][0] = r4[0]; bl[2 * p][1] = r4[1];
                bl[2 * p + 1][0] = r4[2]; bl[2 * p + 1][1] = r4[3];
            }
#pragma unroll
            for (int mt = 0; mt < 2; mt++)
#pragma unroll
                for (int nt = 0; nt < 4; nt++) {
                    mma_bf16(C[mt][nt], ah[mt], bh[nt]);
                    mma_bf16(C[mt][nt], ah[mt], bl[nt]);
                    mma_bf16(C[mt][nt], al[mt], bh[nt]);
                }
        }
        __syncthreads();
    }
}

// ---------------------------------------------------------------------------
// QKV: writes bf16 hi/lo Q/K/V directly. grid = (3, 32, 16), block = 256
// ---------------------------------------------------------------------------
__global__ __launch_bounds__(256) void qkv_mma_kernel(const float* __restrict__ bqkv) {
    __shared__ GemmSmem S;
    int nt = blockIdx.x, mt = blockIdx.y, h = blockIdx.z;
    int mbase = mt * 128;

    const uint4* Ah4 = (const uint4*)g_xh + (size_t)mbase * 128;
    const uint4* Al4 = (const uint4*)g_xl + (size_t)mbase * 128;
    size_t boff = ((size_t)h * 192 + nt * 64) * 128;
    const uint4* Bh4 = (const uint4*)g_wqh + boff;
    const uint4* Bl4 = (const uint4*)g_wql + boff;

    float C[2][4][4];
    gemm_bf16_mainloop(S, Ah4, Al4, Bh4, Bl4, C);

    int lane = threadIdx.x & 31, w = threadIdx.x >> 5;
    int wm = (w & 3) * 32, wn = (w >> 2) * 32;
    int g = lane >> 2, tg = lane & 3;

    const float* bp = bqkv + h * 192 + nt * 64;
    __nv_bfloat16* dh = (nt == 0) ? g_Kh : (nt == 1) ? g_Qh : g_Vh;
    __nv_bfloat16* dl = (nt == 0) ? g_Kl : (nt == 1) ? g_Ql : g_Vl;

#pragma unroll
    for (int mt2 = 0; mt2 < 2; mt2++) {
#pragma unroll
        for (int half = 0; half < 2; half++) {
            int m = mbase + wm + mt2 * 16 + g + half * 8;
            int b = m >> 11, n = m & 2047;
            size_t ro = (((size_t)(b * H_ + h)) * N_ + n) * HD_;
#pragma unroll
            for (int nt2 = 0; nt2 < 4; nt2++) {
                int col = wn + nt2 * 8 + tg * 2;
                float vx = C[mt2][nt2][half * 2 + 0] + bp[col];
                float vy = C[mt2][nt2][half * 2 + 1] + bp[col + 1];
                split_store_pair(vx, vy, dh + ro + col, dl + ro + col);
            }
        }
    }
}

// ---------------------------------------------------------------------------
// Tensor-core causal flash attention v2: cp.async tile loads, ldmatrix K,
// ldmatrix.trans V. Block = 128 q rows; 8 warps x 16 rows. grid = (16, 32).
// Smem: 4 buffers (Kh,Kl,Vh,Vl) 64 rows x 128B, SW128 swizzle = 32KB.
// ---------------------------------------------------------------------------
__global__ __launch_bounds__(256) void attn_mma_kernel() {
    __shared__ __nv_bfloat16 sKh[64 * 64];
    __shared__ __nv_bfloat16 sKl[64 * 64];
    __shared__ __nv_bfloat16 sVh[64 * 64];
    __shared__ __nv_bfloat16 sVl[64 * 64];

    int qt = (int)(gridDim.x - 1) - (int)blockIdx.x;   // heavy tiles first
    int bh = blockIdx.y;
    int tid = threadIdx.x, lane = tid & 31, w = tid >> 5;
    int g = lane >> 2, tg = lane & 3;
    int qbase = qt * 128, wrow = w * 16;
    int row0 = qbase + wrow + g, row1 = row0 + 8;

    uint32_t uKh = smem_u32(sKh), uKl = smem_u32(sKl);
    uint32_t uVh = smem_u32(sVh), uVl = smem_u32(sVl);

    // Q fragments (hi/lo) straight from gmem
    const __nv_bfloat16* Qh = g_Qh + ((size_t)bh * N_ + qbase + wrow) * HD_;
    const __nv_bfloat16* Ql = g_Ql + ((size_t)bh * N_ + qbase + wrow) * HD_;
    uint32_t qh[4][4], ql[4][4];
#pragma unroll
    for (int ko = 0; ko < 4; ko++) {
        int c = ko * 16 + tg * 2;
        qh[ko][0] = *(const uint32_t*)&Qh[(size_t)g * 64 + c];
        qh[ko][1] = *(const uint32_t*)&Qh[(size_t)(g + 8) * 64 + c];
        qh[ko][2] = *(const uint32_t*)&Qh[(size_t)g * 64 + c + 8];
        qh[ko][3] = *(const uint32_t*)&Qh[(size_t)(g + 8) * 64 + c + 8];
        ql[ko][0] = *(const uint32_t*)&Ql[(size_t)g * 64 + c];
        ql[ko][1] = *(const uint32_t*)&Ql[(size_t)(g + 8) * 64 + c];
        ql[ko][2] = *(const uint32_t*)&Ql[(size_t)g * 64 + c + 8];
        ql[ko][3] = *(const uint32_t*)&Ql[(size_t)(g + 8) * 64 + c + 8];
    }

    float Co[8][4];
#pragma unroll
    for (int nt = 0; nt < 8; nt++)
#pragma unroll
        for (int i = 0; i < 4; i++) Co[nt][i] = 0.f;
    float m0 = -1e30f, m1 = -1e30f, l0 = 0.f, l1 = 0.f;

    const uint4* KhG = (const uint4*)(g_Kh + (size_t)bh * N_ * HD_);
    const uint4* KlG = (const uint4*)(g_Kl + (size_t)bh * N_ * HD_);
    const uint4* VhG = (const uint4*)(g_Vh + (size_t)bh * N_ * HD_);
    const uint4* VlG = (const uint4*)(g_Vl + (size_t)bh * N_ * HD_);

    // ldmatrix per-lane address pieces
    int kRow = (lane & 7) + ((lane >> 4) & 1) * 8;   // K (non-trans, B-style)
    int kSlotSel = (lane >> 3) & 1;
    int vRow = (lane & 15);                          // V (trans, A-style)
    int vSlotSel = (lane >> 4) & 1;

    int nkt = 2 * qt + 2;
    for (int kt = 0; kt < nkt; kt++) {
        // ---- stage K/V tiles via cp.async ----
        int gbase = kt * 64 * 8;     // uint4 index of tile start (row stride 8)
#pragma unroll
        for (int p = 0; p < 2; p++) {
            int idx = tid + p * 256;
            int r = idx >> 3, s = idx & 7;
            uint32_t so = SWB(r, s);
            int gi = gbase + r * 8 + s;
            CP_ASYNC16(uKh + so, KhG + gi);
            CP_ASYNC16(uKl + so, KlG + gi);
            CP_ASYNC16(uVh + so, VhG + gi);
            CP_ASYNC16(uVl + so, VlG + gi);
        }
        CP_COMMIT();
        CP_WAIT0();
        __syncthreads();

        // ---- S = Q K^T (3-pass split) ----
        float Cs[8][4];
#pragma unroll
        for (int nt = 0; nt < 8; nt++)
#pragma unroll
            for (int i = 0; i < 4; i++) Cs[nt][i] = 0.f;

#pragma unroll
        for (int ko = 0; ko < 4; ko++) {
#pragma unroll
            for (int p = 0; p < 4; p++) {
                int row = p * 16 + kRow;
                uint32_t so = SWB(row, ko * 2 + kSlotSel);
                uint32_t kh4[4], kl4[4];
                ldsm_x4(kh4, uKh + so);
                ldsm_x4(kl4, uKl + so);
                mma_bf16(Cs[2 * p],     qh[ko], kh4);
                mma_bf16(Cs[2 * p],     ql[ko], kh4);
                mma_bf16(Cs[2 * p],     qh[ko], kl4);
                mma_bf16(Cs[2 * p + 1], qh[ko], kh4 + 2);
                mma_bf16(Cs[2 * p + 1], ql[ko], kh4 + 2);
                mma_bf16(Cs[2 * p + 1], qh[ko], kl4 + 2);
            }
        }

        // ---- mask + scale + row max ----
        int kb = kt * 64;
        float mt0 = -1e30f, mt1 = -1e30f;
#pragma unroll
        for (int nt = 0; nt < 8; nt++) {
            int col = kb + nt * 8 + tg * 2;
#pragma unroll
            for (int j = 0; j < 2; j++) {
                float v0 = Cs[nt][j] * 0.125f;
                float v1 = Cs[nt][2 + j] * 0.125f;
                v0 = (col + j <= row0) ? v0 : -1e30f;
                v1 = (col + j <= row1) ? v1 : -1e30f;
                Cs[nt][j] = v0; Cs[nt][2 + j] = v1;
                mt0 = fmaxf(mt0, v0); mt1 = fmaxf(mt1, v1);
            }
        }
        mt0 = fmaxf(mt0, __shfl_xor_sync(0xffffffffu, mt0, 1));
        mt0 = fmaxf(mt0, __shfl_xor_sync(0xffffffffu, mt0, 2));
        mt1 = fmaxf(mt1, __shfl_xor_sync(0xffffffffu, mt1, 1));
        mt1 = fmaxf(mt1, __shfl_xor_sync(0xffffffffu, mt1, 2));

        float mn0 = fmaxf(m0, mt0), mn1 = fmaxf(m1, mt1);
        float a0 = __expf(m0 - mn0), a1 = __expf(m1 - mn1);
        m0 = mn0; m1 = mn1;
        l0 *= a0; l1 *= a1;
#pragma unroll
        for (int nt = 0; nt < 8; nt++) {
            Co[nt][0] *= a0; Co[nt][1] *= a0;
            Co[nt][2] *= a1; Co[nt][3] *= a1;
        }

        // ---- exp + row sums ----
        float s0 = 0.f, s1 = 0.f;
#pragma unroll
        for (int nt = 0; nt < 8; nt++) {
#pragma unroll
            for (int j = 0; j < 2; j++) {
                float p0 = __expf(Cs[nt][j] - m0);
                float p1 = __expf(Cs[nt][2 + j] - m1);
                Cs[nt][j] = p0; Cs[nt][2 + j] = p1;
                s0 += p0; s1 += p1;
            }
        }
        s0 += __shfl_xor_sync(0xffffffffu, s0, 1);
        s0 += __shfl_xor_sync(0xffffffffu, s0, 2);
        s1 += __shfl_xor_sync(0xffffffffu, s1, 1);
        s1 += __shfl_xor_sync(0xffffffffu, s1, 2);
        l0 += s0; l1 += s1;

        // ---- O += P V (3-pass split); P fragments built in registers ----
#pragma unroll
        for (int ko = 0; ko < 4; ko++) {
            uint32_t ph[4], pl[4];
            ph[0] = pack_bf16(Cs[2 * ko][0], Cs[2 * ko][1]);
            ph[1] = pack_bf16(Cs[2 * ko][2], Cs[2 * ko][3]);
            ph[2] = pack_bf16(Cs[2 * ko + 1][0], Cs[2 * ko + 1][1]);
            ph[3] = pack_bf16(Cs[2 * ko + 1][2], Cs[2 * ko + 1][3]);
#pragma unroll
            for (int i = 0; i < 4; i++) {
                const float* src = &Cs[2 * ko + (i >> 1)][(i & 1) * 2];
                union { uint32_t u; __nv_bfloat162 v; } U; U.u = ph[i];
                pl[i] = pack_bf16(src[0] - __bfloat162float(U.v.x),
                                  src[1] - __bfloat162float(U.v.y));
            }
#pragma unroll
            for (int p = 0; p < 4; p++) {           // d16 pairs
                int row = ko * 16 + vRow;
                uint32_t so = SWB(row, p * 2 + vSlotSel);
                uint32_t vh4[4], vl4[4];
                ldsm_x4_t(vh4, uVh + so);
                ldsm_x4_t(vl4, uVl + so);
                mma_bf16(Co[2 * p],     ph, vh4);
                mma_bf16(Co[2 * p],     ph, vl4);
                mma_bf16(Co[2 * p],     pl, vh4);
                mma_bf16(Co[2 * p + 1], ph, vh4 + 2);
                mma_bf16(Co[2 * p + 1], ph, vl4 + 2);
                mma_bf16(Co[2 * p + 1], pl, vh4 + 2);
            }
        }
        __syncthreads();
    }

    // ---- finalize: O /= l, write bf16 hi/lo into sa layout [b][n][E] ----
    float inv0 = 1.f / l0, inv1 = 1.f / l1;
    int b = bh >> 4, h = bh & 15;
    size_t ro0 = ((size_t)(b * N_) + row0) * E_ + h * HD_;
    size_t ro1 = ((size_t)(b * N_) + row1) * E_ + h * HD_;
#pragma unroll
    for (int nt = 0; nt < 8; nt++) {
        int col = nt * 8 + tg * 2;
        split_store_pair(Co[nt][0] * inv0, Co[nt][1] * inv0,
                         g_sah + ro0 + col, g_sal + ro0 + col);
        split_store_pair(Co[nt][2] * inv1, Co[nt][3] * inv1,
                         g_sah + ro1 + col, g_sal + ro1 + col);
    }
}

// ---------------------------------------------------------------------------
// Output projection: out[4096 x 1024] = sa @ Wout + bout. grid = (16, 32)
// ---------------------------------------------------------------------------
__global__ __launch_bounds__(256) void outproj_mma_kernel(const float* __restrict__ bout,
                                                          float* __restrict__ out) {
    __shared__ GemmSmem S;
    int nt = blockIdx.x, mt = blockIdx.y;
    int mbase = mt * 128;

    const uint4* Ah4 = (const uint4*)g_sah + (size_t)mbase * 128;
    const uint4* Al4 = (const uint4*)g_sal + (size_t)mbase * 128;
    size_t boff = (size_t)nt * 64 * 128;
    const uint4* Bh4 = (const uint4*)g_woh + boff;
    const uint4* Bl4 = (const uint4*)g_wol + boff;

    float C[2][4][4];
    gemm_bf16_mainloop(S, Ah4, Al4, Bh4, Bl4, C);

    int lane = threadIdx.x & 31, w = threadIdx.x >> 5;
    int wm = (w & 3) * 32, wn = (w >> 2) * 32;
    int g = lane >> 2, tg = lane & 3;

    const float* bp = bout + nt * 64;

#pragma unroll
    for (int mt2 = 0; mt2 < 2; mt2++) {
#pragma unroll
        for (int half = 0; half < 2; half++) {
            int m = mbase + wm + mt2 * 16 + g + half * 8;
            float* drow = out + (size_t)m * E_ + nt * 64;
#pragma unroll
            for (int nt2 = 0; nt2 < 4; nt2++) {
                int col = wn + nt2 * 8 + tg * 2;
                float2 v;
                v.x = C[mt2][nt2][half * 2 + 0] + bp[col];
                v.y = C[mt2][nt2][half * 2 + 1] + bp[col + 1];
                *(float2*)&drow[col] = v;
            }
        }
    }
}

// ---------------------------------------------------------------------------
extern "C" void kernel_launch(void* const* d_in, const int* in_sizes, int n_in,
                              void* d_out, int out_size) {
    const float* x    = (const float*)d_in[0];
    const float* Wqkv = (const float*)d_in[1];
    const float* bqkv = (const float*)d_in[2];
    const float* Wout = (const float*)d_in[3];
    const float* bout = (const float*)d_in[4];
    float* out = (float*)d_out;

    split_x_kernel<<<2048, 256>>>(x);
    tsplit_wq_kernel<<<dim3(6, 32, 16), dim3(32, 8)>>>(Wqkv);
    tsplit_wo_kernel<<<dim3(32, 32, 1), dim3(32, 8)>>>(Wout);

    qkv_mma_kernel<<<dim3(3, 32, 16), 256>>>(bqkv);

    attn_mma_kernel<<<dim3(16, 32), 256>>>();

    outproj_mma_kernel<<<dim3(16, 32), 256>>>(bout, out);
}

// round 11
// speedup vs baseline: 4.1594x; 1.2025x over previous
#include <cuda_runtime.h>
#include <cuda_fp16.h>
#include <math.h>
#include <stdint.h>

#define B_ 2
#define N_ 2048
#define E_ 1024
#define H_ 16
#define HD_ 64

// ---------------------------------------------------------------------------
// Scratch (__device__ globals; allocation-free rule). fp16 hi/lo splits.
// ---------------------------------------------------------------------------
__device__ __half g_xh[(size_t)4096*1024];
__device__ __half g_xl[(size_t)4096*1024];
__device__ __half g_wqh[(size_t)16*192*1024];   // [h][n][k] (transposed)
__device__ __half g_wql[(size_t)16*192*1024];
__device__ __half g_woh[(size_t)1024*1024];     // [n][k] (transposed)
__device__ __half g_wol[(size_t)1024*1024];
__device__ __half g_sah[(size_t)4096*1024];     // attention output, fp16 hi only

// Q/K/V fp16 hi/lo, layout [bh][n][64]
__device__ __half g_Qh[(size_t)B_*H_*N_*HD_];
__device__ __half g_Ql[(size_t)B_*H_*N_*HD_];
__device__ __half g_Kh[(size_t)B_*H_*N_*HD_];
__device__ __half g_Kl[(size_t)B_*H_*N_*HD_];
__device__ __half g_Vh[(size_t)B_*H_*N_*HD_];
__device__ __half g_Vl[(size_t)B_*H_*N_*HD_];

// ---------------------------------------------------------------------------
// PTX helpers (baseline-PTX features only)
// ---------------------------------------------------------------------------
__device__ __forceinline__ void mma_f16(float* c, const uint32_t* a, const uint32_t* b) {
    asm volatile(
        "mma.sync.aligned.m16n8k16.row.col.f32.f16.f16.f32 "
        "{%0,%1,%2,%3},{%4,%5,%6,%7},{%8,%9},{%0,%1,%2,%3};"
        : "+f"(c[0]), "+f"(c[1]), "+f"(c[2]), "+f"(c[3])
        : "r"(a[0]), "r"(a[1]), "r"(a[2]), "r"(a[3]), "r"(b[0]), "r"(b[1]));
}

__device__ __forceinline__ void ldsm_x4(uint32_t* r, uint32_t addr) {
    asm volatile("ldmatrix.sync.aligned.m8n8.x4.shared.b16 {%0,%1,%2,%3}, [%4];"
        : "=r"(r[0]), "=r"(r[1]), "=r"(r[2]), "=r"(r[3]) : "r"(addr));
}
__device__ __forceinline__ void ldsm_x4_t(uint32_t* r, uint32_t addr) {
    asm volatile("ldmatrix.sync.aligned.m8n8.x4.trans.shared.b16 {%0,%1,%2,%3}, [%4];"
        : "=r"(r[0]), "=r"(r[1]), "=r"(r[2]), "=r"(r[3]) : "r"(addr));
}

#define CP_ASYNC16(dst, src) \
    asm volatile("cp.async.cg.shared.global [%0], [%1], 16;" :: "r"(dst), "l"(src))
#define CP_COMMIT() asm volatile("cp.async.commit_group;" ::: "memory")
#define CP_WAIT0()  asm volatile("cp.async.wait_group 0;" ::: "memory")

__device__ __forceinline__ uint32_t smem_u32(const void* p) {
    return (uint32_t)__cvta_generic_to_shared(p);
}

// 128B rows, classic SW128: 16B slot s of row r lives at slot s^(r&7)
#define SWB(r, s) ((uint32_t)((r) * 128 + (((s) ^ ((r) & 7)) << 4)))

__device__ __forceinline__ uint32_t pack_h2(float lo, float hi) {
    union { __half2 v; uint32_t u; } U;
    U.v = __floats2half2_rn(lo, hi);
    return U.u;
}

// split fp32 pair into fp16 hi pair + fp16 residual pair
__device__ __forceinline__ void split_store_pair(float vx, float vy,
                                                 __half* dh, __half* dl) {
    __half hx = __float2half_rn(vx);
    __half hy = __float2half_rn(vy);
    union { __half2 v; uint32_t u; } H, L;
    H.v.x = hx; H.v.y = hy;
    L.v = __floats2half2_rn(vx - __half2float(hx), vy - __half2float(hy));
    *(uint32_t*)dh = H.u;
    *(uint32_t*)dl = L.u;
}

// ---------------------------------------------------------------------------
// Conversion kernels
// ---------------------------------------------------------------------------
__device__ __forceinline__ void split_body(const float* __restrict__ src,
                                           __half* __restrict__ hi,
                                           __half* __restrict__ lo, int n4) {
    int i = blockIdx.x * blockDim.x + threadIdx.x;
    int stride = gridDim.x * blockDim.x;
    for (; i < n4; i += stride) {
        float4 v = ((const float4*)src)[i];
        union { __half b[4]; uint2 u; } Hh, Ll;
        float vs[4] = {v.x, v.y, v.z, v.w};
#pragma unroll
        for (int j = 0; j < 4; j++) {
            __half h = __float2half_rn(vs[j]);
            Hh.b[j] = h;
            Ll.b[j] = __float2half_rn(vs[j] - __half2float(h));
        }
        ((uint2*)hi)[i] = Hh.u;
        ((uint2*)lo)[i] = Ll.u;
    }
}

__global__ void split_x_kernel(const float* __restrict__ x) {
    split_body(x, g_xh, g_xl, 4096 * 1024 / 4);
}

__device__ __forceinline__ void tsplit_body(const float* __restrict__ in,
                                            __half* __restrict__ oh,
                                            __half* __restrict__ ol,
                                            int R, int C) {
    __shared__ float t[32][33];
    size_t zo = (size_t)blockIdx.z * R * C;
    in += zo; oh += zo; ol += zo;
    int c0 = blockIdx.x * 32, r0 = blockIdx.y * 32;
    int tx = threadIdx.x, ty = threadIdx.y;
#pragma unroll
    for (int i = 0; i < 32; i += 8)
        t[ty + i][tx] = in[(size_t)(r0 + ty + i) * C + c0 + tx];
    __syncthreads();
#pragma unroll
    for (int i = 0; i < 32; i += 8) {
        float v = t[tx][ty + i];
        __half h = __float2half_rn(v);
        oh[(size_t)(c0 + ty + i) * R + r0 + tx] = h;
        ol[(size_t)(c0 + ty + i) * R + r0 + tx] = __float2half_rn(v - __half2float(h));
    }
}

__global__ void tsplit_wq_kernel(const float* __restrict__ Wqkv) {
    tsplit_body(Wqkv, g_wqh, g_wql, 1024, 192);
}
__global__ void tsplit_wo_kernel(const float* __restrict__ Wout) {
    tsplit_body(Wout, g_woh, g_wol, 1024, 1024);
}

// ---------------------------------------------------------------------------
// GEMM mainloop v3: 128 threads, 4 warps, warp tile 32x64 (4m x 1n).
// C[128x64] = A[128x1024] @ B[64x1024]^T.
// THREE=true : 3-pass Ah*Bh + Ah*Bl + Al*Bh (qkv)
// THREE=false: 2-pass Ah*Bh + Ah*Bl         (outproj; Al never loaded)
// Smem rows 128B = [hi k0..31 | lo k0..31], SW128 swizzle. 2 stages = 48KB.
// ---------------------------------------------------------------------------
struct GemmSmem {
    __half A[2][128 * 64];   // 16KB / stage
    __half Bt[2][64 * 64];   //  8KB / stage
};

template <bool THREE>
__device__ __forceinline__ void gemm_stage(
    uint32_t sA, uint32_t sB,
    const uint4* __restrict__ Ah4, const uint4* __restrict__ Al4,
    const uint4* __restrict__ Bh4, const uint4* __restrict__ Bl4,
    int kb4, int tid)
{
    if (THREE) {
#pragma unroll
        for (int p = 0; p < 8; p++) {
            int idx = tid + p * 128;
            int r = idx >> 3, s = idx & 7;
            const uint4* src = (s < 4) ? (Ah4 + (size_t)r * 128 + kb4 + s)
                                       : (Al4 + (size_t)r * 128 + kb4 + (s - 4));
            CP_ASYNC16(sA + SWB(r, s), src);
        }
    } else {
#pragma unroll
        for (int p = 0; p < 4; p++) {
            int idx = tid + p * 128;
            int r = idx >> 2, s = idx & 3;
            CP_ASYNC16(sA + SWB(r, s), Ah4 + (size_t)r * 128 + kb4 + s);
        }
    }
#pragma unroll
    for (int p = 0; p < 4; p++) {
        int idx = tid + p * 128;
        int r = idx >> 3, s = idx & 7;
        const uint4* src = (s < 4) ? (Bh4 + (size_t)r * 128 + kb4 + s)
                                   : (Bl4 + (size_t)r * 128 + kb4 + (s - 4));
        CP_ASYNC16(sB + SWB(r, s), src);
    }
}

template <bool THREE>
__device__ __forceinline__ void gemm_mainloop(
    GemmSmem& S,
    const uint4* __restrict__ Ah4, const uint4* __restrict__ Al4,
    const uint4* __restrict__ Bh4, const uint4* __restrict__ Bl4,
    float C[2][8][4])
{
    int tid = threadIdx.x;
    int lane = tid & 31, w = tid >> 5;
    int wm = w * 32;

#pragma unroll
    for (int mt = 0; mt < 2; mt++)
#pragma unroll
        for (int nt = 0; nt < 8; nt++)
#pragma unroll
            for (int i = 0; i < 4; i++) C[mt][nt][i] = 0.f;

    uint32_t sA0 = smem_u32(S.A[0]), sA1 = smem_u32(S.A[1]);
    uint32_t sB0 = smem_u32(S.Bt[0]), sB1 = smem_u32(S.Bt[1]);

    int aRow = (lane & 15);
    int aSel = (lane >> 4) & 1;
    int bRow = (lane & 7) + ((lane >> 4) & 1) * 8;
    int bSel = (lane >> 3) & 1;

    gemm_stage<THREE>(sA0, sB0, Ah4, Al4, Bh4, Bl4, 0, tid);
    CP_COMMIT();

    for (int kc = 0; kc < 32; kc++) {
        CP_WAIT0();
        __syncthreads();
        if (kc + 1 < 32) {
            gemm_stage<THREE>((kc & 1) ? sA0 : sA1, (kc & 1) ? sB0 : sB1,
                              Ah4, Al4, Bh4, Bl4, (kc + 1) * 4, tid);
            CP_COMMIT();
        }
        uint32_t sA = (kc & 1) ? sA1 : sA0;
        uint32_t sB = (kc & 1) ? sB1 : sB0;

#pragma unroll
        for (int k16 = 0; k16 < 2; k16++) {
            int shi = k16 * 2, slo = 4 + k16 * 2;
            uint32_t ah[2][4], al[2][4], bh[8][2], bl[8][2];
#pragma unroll
            for (int mt = 0; mt < 2; mt++) {
                int row = wm + mt * 16 + aRow;
                ldsm_x4(ah[mt], sA + SWB(row, shi + aSel));
                if (THREE) ldsm_x4(al[mt], sA + SWB(row, slo + aSel));
            }
#pragma unroll
            for (int p = 0; p < 4; p++) {
                int row = p * 16 + bRow;
                uint32_t r4[4];
                ldsm_x4(r4, sB + SWB(row, shi + bSel));
                bh[2 * p][0] = r4[0]; bh[2 * p][1] = r4[1];
                bh[2 * p + 1][0] = r4[2]; bh[2 * p + 1][1] = r4[3];
                ldsm_x4(r4, sB + SWB(row, slo + bSel));
                bl[2 * p][0] = r4[0]; bl[2 * p][1] = r4[1];
                bl[2 * p + 1][0] = r4[2]; bl[2 * p + 1][1] = r4[3];
            }
#pragma unroll
            for (int mt = 0; mt < 2; mt++)
#pragma unroll
                for (int nt = 0; nt < 8; nt++) {
                    mma_f16(C[mt][nt], ah[mt], bh[nt]);
                    mma_f16(C[mt][nt], ah[mt], bl[nt]);
                    if (THREE) mma_f16(C[mt][nt], al[mt], bh[nt]);
                }
        }
        __syncthreads();
    }
}

// ---------------------------------------------------------------------------
// QKV: 3-pass; writes fp16 hi/lo Q/K/V. grid = (3, 32, 16), block = 128
// ---------------------------------------------------------------------------
__global__ __launch_bounds__(128, 3) void qkv_mma_kernel(const float* __restrict__ bqkv) {
    __shared__ GemmSmem S;
    int nt = blockIdx.x, mt = blockIdx.y, h = blockIdx.z;
    int mbase = mt * 128;

    const uint4* Ah4 = (const uint4*)g_xh + (size_t)mbase * 128;
    const uint4* Al4 = (const uint4*)g_xl + (size_t)mbase * 128;
    size_t boff = ((size_t)h * 192 + nt * 64) * 128;
    const uint4* Bh4 = (const uint4*)g_wqh + boff;
    const uint4* Bl4 = (const uint4*)g_wql + boff;

    float C[2][8][4];
    gemm_mainloop<true>(S, Ah4, Al4, Bh4, Bl4, C);

    int lane = threadIdx.x & 31, w = threadIdx.x >> 5;
    int g = lane >> 2, tg = lane & 3;

    const float* bp = bqkv + h * 192 + nt * 64;
    __half* dh = (nt == 0) ? g_Kh : (nt == 1) ? g_Qh : g_Vh;
    __half* dl = (nt == 0) ? g_Kl : (nt == 1) ? g_Ql : g_Vl;

#pragma unroll
    for (int mt2 = 0; mt2 < 2; mt2++) {
#pragma unroll
        for (int half = 0; half < 2; half++) {
            int m = mbase + w * 32 + mt2 * 16 + g + half * 8;
            int b = m >> 11, n = m & 2047;
            size_t ro = (((size_t)(b * H_ + h)) * N_ + n) * HD_;
#pragma unroll
            for (int nt2 = 0; nt2 < 8; nt2++) {
                int col = nt2 * 8 + tg * 2;
                float vx = C[mt2][nt2][half * 2 + 0] + bp[col];
                float vy = C[mt2][nt2][half * 2 + 1] + bp[col + 1];
                split_store_pair(vx, vy, dh + ro + col, dl + ro + col);
            }
        }
    }
}

// ---------------------------------------------------------------------------
// Output projection: 2-pass (A hi only). grid = (16, 32), block = 128
// ---------------------------------------------------------------------------
__global__ __launch_bounds__(128, 3) void outproj_mma_kernel(const float* __restrict__ bout,
                                                             float* __restrict__ out) {
    __shared__ GemmSmem S;
    int nt = blockIdx.x, mt = blockIdx.y;
    int mbase = mt * 128;

    const uint4* Ah4 = (const uint4*)g_sah + (size_t)mbase * 128;
    size_t boff = (size_t)nt * 64 * 128;
    const uint4* Bh4 = (const uint4*)g_woh + boff;
    const uint4* Bl4 = (const uint4*)g_wol + boff;

    float C[2][8][4];
    gemm_mainloop<false>(S, Ah4, Ah4, Bh4, Bl4, C);

    int lane = threadIdx.x & 31, w = threadIdx.x >> 5;
    int g = lane >> 2, tg = lane & 3;

    const float* bp = bout + nt * 64;

#pragma unroll
    for (int mt2 = 0; mt2 < 2; mt2++) {
#pragma unroll
        for (int half = 0; half < 2; half++) {
            int m = mbase + w * 32 + mt2 * 16 + g + half * 8;
            float* drow = out + (size_t)m * E_ + nt * 64;
#pragma unroll
            for (int nt2 = 0; nt2 < 8; nt2++) {
                int col = nt2 * 8 + tg * 2;
                float2 v;
                v.x = C[mt2][nt2][half * 2 + 0] + bp[col];
                v.y = C[mt2][nt2][half * 2 + 1] + bp[col + 1];
                *(float2*)&drow[col] = v;
            }
        }
    }
}

// ---------------------------------------------------------------------------
// Tensor-core causal flash attention (fp16): S 3-pass, PV 2-pass.
// Block = 128 q rows; 8 warps x 16 rows. grid = (16, 32), block = 256.
// ---------------------------------------------------------------------------
__global__ __launch_bounds__(256) void attn_mma_kernel() {
    __shared__ __half sKh[64 * 64];
    __shared__ __half sKl[64 * 64];
    __shared__ __half sVh[64 * 64];
    __shared__ __half sVl[64 * 64];

    int qt = (int)(gridDim.x - 1) - (int)blockIdx.x;   // heavy tiles first
    int bh = blockIdx.y;
    int tid = threadIdx.x, lane = tid & 31, w = tid >> 5;
    int g = lane >> 2, tg = lane & 3;
    int qbase = qt * 128, wrow = w * 16;
    int row0 = qbase + wrow + g, row1 = row0 + 8;

    uint32_t uKh = smem_u32(sKh), uKl = smem_u32(sKl);
    uint32_t uVh = smem_u32(sVh), uVl = smem_u32(sVl);

    // Q fragments (hi/lo) straight from gmem
    const __half* Qh = g_Qh + ((size_t)bh * N_ + qbase + wrow) * HD_;
    const __half* Ql = g_Ql + ((size_t)bh * N_ + qbase + wrow) * HD_;
    uint32_t qh[4][4], ql[4][4];
#pragma unroll
    for (int ko = 0; ko < 4; ko++) {
        int c = ko * 16 + tg * 2;
        qh[ko][0] = *(const uint32_t*)&Qh[(size_t)g * 64 + c];
        qh[ko][1] = *(const uint32_t*)&Qh[(size_t)(g + 8) * 64 + c];
        qh[ko][2] = *(const uint32_t*)&Qh[(size_t)g * 64 + c + 8];
        qh[ko][3] = *(const uint32_t*)&Qh[(size_t)(g + 8) * 64 + c + 8];
        ql[ko][0] = *(const uint32_t*)&Ql[(size_t)g * 64 + c];
        ql[ko][1] = *(const uint32_t*)&Ql[(size_t)(g + 8) * 64 + c];
        ql[ko][2] = *(const uint32_t*)&Ql[(size_t)g * 64 + c + 8];
        ql[ko][3] = *(const uint32_t*)&Ql[(size_t)(g + 8) * 64 + c + 8];
    }

    float Co[8][4];
#pragma unroll
    for (int nt = 0; nt < 8; nt++)
#pragma unroll
        for (int i = 0; i < 4; i++) Co[nt][i] = 0.f;
    float m0 = -1e30f, m1 = -1e30f, l0 = 0.f, l1 = 0.f;

    const uint4* KhG = (const uint4*)(g_Kh + (size_t)bh * N_ * HD_);
    const uint4* KlG = (const uint4*)(g_Kl + (size_t)bh * N_ * HD_);
    const uint4* VhG = (const uint4*)(g_Vh + (size_t)bh * N_ * HD_);
    const uint4* VlG = (const uint4*)(g_Vl + (size_t)bh * N_ * HD_);

    int kRow = (lane & 7) + ((lane >> 4) & 1) * 8;   // K (non-trans, B-style)
    int kSel = (lane >> 3) & 1;
    int vRow = (lane & 15);                          // V (trans, A-style)
    int vSel = (lane >> 4) & 1;

    int nkt = 2 * qt + 2;
    for (int kt = 0; kt < nkt; kt++) {
        int gbase = kt * 64 * 8;
#pragma unroll
        for (int p = 0; p < 2; p++) {
            int idx = tid + p * 256;
            int r = idx >> 3, s = idx & 7;
            uint32_t so = SWB(r, s);
            int gi = gbase + r * 8 + s;
            CP_ASYNC16(uKh + so, KhG + gi);
            CP_ASYNC16(uKl + so, KlG + gi);
            CP_ASYNC16(uVh + so, VhG + gi);
            CP_ASYNC16(uVl + so, VlG + gi);
        }
        CP_COMMIT();
        CP_WAIT0();
        __syncthreads();

        // ---- S = Q K^T (3-pass split) ----
        float Cs[8][4];
#pragma unroll
        for (int nt = 0; nt < 8; nt++)
#pragma unroll
            for (int i = 0; i < 4; i++) Cs[nt][i] = 0.f;

#pragma unroll
        for (int ko = 0; ko < 4; ko++) {
#pragma unroll
            for (int p = 0; p < 4; p++) {
                int row = p * 16 + kRow;
                uint32_t so = SWB(row, ko * 2 + kSel);
                uint32_t kh4[4], kl4[4];
                ldsm_x4(kh4, uKh + so);
                ldsm_x4(kl4, uKl + so);
                mma_f16(Cs[2 * p],     qh[ko], kh4);
                mma_f16(Cs[2 * p],     ql[ko], kh4);
                mma_f16(Cs[2 * p],     qh[ko], kl4);
                mma_f16(Cs[2 * p + 1], qh[ko], kh4 + 2);
                mma_f16(Cs[2 * p + 1], ql[ko], kh4 + 2);
                mma_f16(Cs[2 * p + 1], qh[ko], kl4 + 2);
            }
        }

        // ---- mask + scale + row max ----
        int kb = kt * 64;
        float mt0 = -1e30f, mt1 = -1e30f;
#pragma unroll
        for (int nt = 0; nt < 8; nt++) {
            int col = kb + nt * 8 + tg * 2;
#pragma unroll
            for (int j = 0; j < 2; j++) {
                float v0 = Cs[nt][j] * 0.125f;
                float v1 = Cs[nt][2 + j] * 0.125f;
                v0 = (col + j <= row0) ? v0 : -1e30f;
                v1 = (col + j <= row1) ? v1 : -1e30f;
                Cs[nt][j] = v0; Cs[nt][2 + j] = v1;
                mt0 = fmaxf(mt0, v0); mt1 = fmaxf(mt1, v1);
            }
        }
        mt0 = fmaxf(mt0, __shfl_xor_sync(0xffffffffu, mt0, 1));
        mt0 = fmaxf(mt0, __shfl_xor_sync(0xffffffffu, mt0, 2));
        mt1 = fmaxf(mt1, __shfl_xor_sync(0xffffffffu, mt1, 1));
        mt1 = fmaxf(mt1, __shfl_xor_sync(0xffffffffu, mt1, 2));

        float mn0 = fmaxf(m0, mt0), mn1 = fmaxf(m1, mt1);
        float a0 = __expf(m0 - mn0), a1 = __expf(m1 - mn1);
        m0 = mn0; m1 = mn1;
        l0 *= a0; l1 *= a1;
#pragma unroll
        for (int nt = 0; nt < 8; nt++) {
            Co[nt][0] *= a0; Co[nt][1] *= a0;
            Co[nt][2] *= a1; Co[nt][3] *= a1;
        }

        // ---- exp + row sums ----
        float s0 = 0.f, s1 = 0.f;
#pragma unroll
        for (int nt = 0; nt < 8; nt++) {
#pragma unroll
            for (int j = 0; j < 2; j++) {
                float p0 = __expf(Cs[nt][j] - m0);
                float p1 = __expf(Cs[nt][2 + j] - m1);
                Cs[nt][j] = p0; Cs[nt][2 + j] = p1;
                s0 += p0; s1 += p1;
            }
        }
        s0 += __shfl_xor_sync(0xffffffffu, s0, 1);
        s0 += __shfl_xor_sync(0xffffffffu, s0, 2);
        s1 += __shfl_xor_sync(0xffffffffu, s1, 1);
        s1 += __shfl_xor_sync(0xffffffffu, s1, 2);
        l0 += s0; l1 += s1;

        // ---- O += P V (2-pass: Ph*(Vh+Vl)) ----
#pragma unroll
        for (int ko = 0; ko < 4; ko++) {
            uint32_t ph[4];
            ph[0] = pack_h2(Cs[2 * ko][0], Cs[2 * ko][1]);
            ph[1] = pack_h2(Cs[2 * ko][2], Cs[2 * ko][3]);
            ph[2] = pack_h2(Cs[2 * ko + 1][0], Cs[2 * ko + 1][1]);
            ph[3] = pack_h2(Cs[2 * ko + 1][2], Cs[2 * ko + 1][3]);
#pragma unroll
            for (int p = 0; p < 4; p++) {
                int row = ko * 16 + vRow;
                uint32_t so = SWB(row, p * 2 + vSel);
                uint32_t vh4[4], vl4[4];
                ldsm_x4_t(vh4, uVh + so);
                ldsm_x4_t(vl4, uVl + so);
                mma_f16(Co[2 * p],     ph, vh4);
                mma_f16(Co[2 * p],     ph, vl4);
                mma_f16(Co[2 * p + 1], ph, vh4 + 2);
                mma_f16(Co[2 * p + 1], ph, vl4 + 2);
            }
        }
        __syncthreads();
    }

    // ---- finalize: O /= l, write fp16 hi into sa layout [b][n][E] ----
    float inv0 = 1.f / l0, inv1 = 1.f / l1;
    int b = bh >> 4, h = bh & 15;
    size_t ro0 = ((size_t)(b * N_) + row0) * E_ + h * HD_;
    size_t ro1 = ((size_t)(b * N_) + row1) * E_ + h * HD_;
#pragma unroll
    for (int nt = 0; nt < 8; nt++) {
        int col = nt * 8 + tg * 2;
        *(uint32_t*)&g_sah[ro0 + col] = pack_h2(Co[nt][0] * inv0, Co[nt][1] * inv0);
        *(uint32_t*)&g_sah[ro1 + col] = pack_h2(Co[nt][2] * inv1, Co[nt][3] * inv1);
    }
}

// ---------------------------------------------------------------------------
extern "C" void kernel_launch(void* const* d_in, const int* in_sizes, int n_in,
                              void* d_out, int out_size) {
    const float* x    = (const float*)d_in[0];
    const float* Wqkv = (const float*)d_in[1];
    const float* bqkv = (const float*)d_in[2];
    const float* Wout = (const float*)d_in[3];
    const float* bout = (const float*)d_in[4];
    float* out = (float*)d_out;

    split_x_kernel<<<2048, 256>>>(x);
    tsplit_wq_kernel<<<dim3(6, 32, 16), dim3(32, 8)>>>(Wqkv);
    tsplit_wo_kernel<<<dim3(32, 32, 1), dim3(32, 8)>>>(Wout);

    qkv_mma_kernel<<<dim3(3, 32, 16), 128>>>(bqkv);

    attn_mma_kernel<<<dim3(16, 32), 256>>>();

    outproj_mma_kernel<<<dim3(16, 32), 128>>>(bout, out);
}

// round 12
// speedup vs baseline: 4.5864x; 1.1027x over previous
#include <cuda_runtime.h>
#include <cuda_fp16.h>
#include <math.h>
#include <stdint.h>

#define B_ 2
#define N_ 2048
#define E_ 1024
#define H_ 16
#define HD_ 64

// ---------------------------------------------------------------------------
// Scratch (__device__ globals; allocation-free rule). fp16 hi/lo splits.
// ---------------------------------------------------------------------------
__device__ __half g_xh[(size_t)4096*1024];
__device__ __half g_xl[(size_t)4096*1024];
__device__ __half g_wqh[(size_t)16*192*1024];   // [h][n][k] (transposed)
__device__ __half g_wql[(size_t)16*192*1024];
__device__ __half g_woh[(size_t)1024*1024];     // [n][k] (transposed)
__device__ __half g_wol[(size_t)1024*1024];
__device__ __half g_sah[(size_t)4096*1024];     // attention output, fp16 hi only

// Q/K/V fp16 hi/lo, layout [bh][n][64]
__device__ __half g_Qh[(size_t)B_*H_*N_*HD_];
__device__ __half g_Ql[(size_t)B_*H_*N_*HD_];
__device__ __half g_Kh[(size_t)B_*H_*N_*HD_];
__device__ __half g_Kl[(size_t)B_*H_*N_*HD_];
__device__ __half g_Vh[(size_t)B_*H_*N_*HD_];
__device__ __half g_Vl[(size_t)B_*H_*N_*HD_];

// ---------------------------------------------------------------------------
// PTX helpers (baseline-PTX features only)
// ---------------------------------------------------------------------------
__device__ __forceinline__ void mma_f16(float* c, const uint32_t* a, const uint32_t* b) {
    asm volatile(
        "mma.sync.aligned.m16n8k16.row.col.f32.f16.f16.f32 "
        "{%0,%1,%2,%3},{%4,%5,%6,%7},{%8,%9},{%0,%1,%2,%3};"
        : "+f"(c[0]), "+f"(c[1]), "+f"(c[2]), "+f"(c[3])
        : "r"(a[0]), "r"(a[1]), "r"(a[2]), "r"(a[3]), "r"(b[0]), "r"(b[1]));
}

__device__ __forceinline__ void ldsm_x4(uint32_t* r, uint32_t addr) {
    asm volatile("ldmatrix.sync.aligned.m8n8.x4.shared.b16 {%0,%1,%2,%3}, [%4];"
        : "=r"(r[0]), "=r"(r[1]), "=r"(r[2]), "=r"(r[3]) : "r"(addr));
}
__device__ __forceinline__ void ldsm_x4_t(uint32_t* r, uint32_t addr) {
    asm volatile("ldmatrix.sync.aligned.m8n8.x4.trans.shared.b16 {%0,%1,%2,%3}, [%4];"
        : "=r"(r[0]), "=r"(r[1]), "=r"(r[2]), "=r"(r[3]) : "r"(addr));
}

#define CP_ASYNC16(dst, src) \
    asm volatile("cp.async.cg.shared.global [%0], [%1], 16;" :: "r"(dst), "l"(src))
#define CP_COMMIT() asm volatile("cp.async.commit_group;" ::: "memory")
#define CP_WAIT0()  asm volatile("cp.async.wait_group 0;" ::: "memory")
#define CP_WAIT1()  asm volatile("cp.async.wait_group 1;" ::: "memory")

__device__ __forceinline__ uint32_t smem_u32(const void* p) {
    return (uint32_t)__cvta_generic_to_shared(p);
}

// 128B rows, classic SW128: 16B slot s of row r lives at slot s^(r&7)
#define SWB(r, s) ((uint32_t)((r) * 128 + (((s) ^ ((r) & 7)) << 4)))

__device__ __forceinline__ uint32_t pack_h2(float lo, float hi) {
    union { __half2 v; uint32_t u; } U;
    U.v = __floats2half2_rn(lo, hi);
    return U.u;
}

// split fp32 pair into fp16 hi pair + fp16 residual pair
__device__ __forceinline__ void split_store_pair(float vx, float vy,
                                                 __half* dh, __half* dl) {
    __half hx = __float2half_rn(vx);
    __half hy = __float2half_rn(vy);
    union { __half2 v; uint32_t u; } H, L;
    H.v.x = hx; H.v.y = hy;
    L.v = __floats2half2_rn(vx - __half2float(hx), vy - __half2float(hy));
    *(uint32_t*)dh = H.u;
    *(uint32_t*)dl = L.u;
}

// ---------------------------------------------------------------------------
// Conversion kernels
// ---------------------------------------------------------------------------
__device__ __forceinline__ void split_body(const float* __restrict__ src,
                                           __half* __restrict__ hi,
                                           __half* __restrict__ lo, int n4) {
    int i = blockIdx.x * blockDim.x + threadIdx.x;
    int stride = gridDim.x * blockDim.x;
    for (; i < n4; i += stride) {
        float4 v = ((const float4*)src)[i];
        union { __half b[4]; uint2 u; } Hh, Ll;
        float vs[4] = {v.x, v.y, v.z, v.w};
#pragma unroll
        for (int j = 0; j < 4; j++) {
            __half h = __float2half_rn(vs[j]);
            Hh.b[j] = h;
            Ll.b[j] = __float2half_rn(vs[j] - __half2float(h));
        }
        ((uint2*)hi)[i] = Hh.u;
        ((uint2*)lo)[i] = Ll.u;
    }
}

__global__ void split_x_kernel(const float* __restrict__ x) {
    split_body(x, g_xh, g_xl, 4096 * 1024 / 4);
}

__device__ __forceinline__ void tsplit_body(const float* __restrict__ in,
                                            __half* __restrict__ oh,
                                            __half* __restrict__ ol,
                                            int R, int C) {
    __shared__ float t[32][33];
    size_t zo = (size_t)blockIdx.z * R * C;
    in += zo; oh += zo; ol += zo;
    int c0 = blockIdx.x * 32, r0 = blockIdx.y * 32;
    int tx = threadIdx.x, ty = threadIdx.y;
#pragma unroll
    for (int i = 0; i < 32; i += 8)
        t[ty + i][tx] = in[(size_t)(r0 + ty + i) * C + c0 + tx];
    __syncthreads();
#pragma unroll
    for (int i = 0; i < 32; i += 8) {
        float v = t[tx][ty + i];
        __half h = __float2half_rn(v);
        oh[(size_t)(c0 + ty + i) * R + r0 + tx] = h;
        ol[(size_t)(c0 + ty + i) * R + r0 + tx] = __float2half_rn(v - __half2float(h));
    }
}

__global__ void tsplit_wq_kernel(const float* __restrict__ Wqkv) {
    tsplit_body(Wqkv, g_wqh, g_wql, 1024, 192);
}
__global__ void tsplit_wo_kernel(const float* __restrict__ Wout) {
    tsplit_body(Wout, g_woh, g_wol, 1024, 1024);
}

// ---------------------------------------------------------------------------
// GEMM mainloop v4: 3-stage cp.async pipeline, dynamic smem (72KB),
// single __syncthreads per chunk. 128 threads, 4 warps, warp tile 32x64.
// C[128x64] = A[128x1024] @ B[64x1024]^T.
// THREE=true : 3-pass Ah*Bh + Ah*Bl + Al*Bh
// THREE=false: 2-pass Ah*Bh + Ah*Bl (Al never loaded)
// Per stage: A 16KB (rows 128B = hi|lo) + B 8KB = 24KB. 3 stages = 72KB.
// ---------------------------------------------------------------------------
#define STG_BYTES 24576

template <bool THREE>
__device__ __forceinline__ void gemm_stage(
    uint32_t sA, uint32_t sB,
    const uint4* __restrict__ Ah4, const uint4* __restrict__ Al4,
    const uint4* __restrict__ Bh4, const uint4* __restrict__ Bl4,
    int kb4, int tid)
{
    if (THREE) {
#pragma unroll
        for (int p = 0; p < 8; p++) {
            int idx = tid + p * 128;
            int r = idx >> 3, s = idx & 7;
            const uint4* src = (s < 4) ? (Ah4 + (size_t)r * 128 + kb4 + s)
                                       : (Al4 + (size_t)r * 128 + kb4 + (s - 4));
            CP_ASYNC16(sA + SWB(r, s), src);
        }
    } else {
#pragma unroll
        for (int p = 0; p < 4; p++) {
            int idx = tid + p * 128;
            int r = idx >> 2, s = idx & 3;
            CP_ASYNC16(sA + SWB(r, s), Ah4 + (size_t)r * 128 + kb4 + s);
        }
    }
#pragma unroll
    for (int p = 0; p < 4; p++) {
        int idx = tid + p * 128;
        int r = idx >> 3, s = idx & 7;
        const uint4* src = (s < 4) ? (Bh4 + (size_t)r * 128 + kb4 + s)
                                   : (Bl4 + (size_t)r * 128 + kb4 + (s - 4));
        CP_ASYNC16(sB + SWB(r, s), src);
    }
}

template <bool THREE>
__device__ __forceinline__ void gemm_mainloop(
    const uint4* __restrict__ Ah4, const uint4* __restrict__ Al4,
    const uint4* __restrict__ Bh4, const uint4* __restrict__ Bl4,
    float C[2][8][4])
{
    extern __shared__ __align__(128) char dynsm[];
    uint32_t base = smem_u32(dynsm);

    int tid = threadIdx.x;
    int lane = tid & 31, w = tid >> 5;
    int wm = w * 32;

#pragma unroll
    for (int mt = 0; mt < 2; mt++)
#pragma unroll
        for (int nt = 0; nt < 8; nt++)
#pragma unroll
            for (int i = 0; i < 4; i++) C[mt][nt][i] = 0.f;

    int aRow = (lane & 15);
    int aSel = (lane >> 4) & 1;
    int bRow = (lane & 7) + ((lane >> 4) & 1) * 8;
    int bSel = (lane >> 3) & 1;

    // prologue: stages 0 and 1
    gemm_stage<THREE>(base, base + 16384, Ah4, Al4, Bh4, Bl4, 0, tid);
    CP_COMMIT();
    gemm_stage<THREE>(base + STG_BYTES, base + STG_BYTES + 16384,
                      Ah4, Al4, Bh4, Bl4, 4, tid);
    CP_COMMIT();

    int st = 0;   // stage of current chunk
    for (int kc = 0; kc < 32; kc++) {
        if (kc < 31) { CP_WAIT1(); } else { CP_WAIT0(); }
        __syncthreads();
        uint32_t sA = base + st * STG_BYTES;
        uint32_t sB = sA + 16384;

#pragma unroll
        for (int k16 = 0; k16 < 2; k16++) {
            int shi = k16 * 2, slo = 4 + k16 * 2;
            uint32_t ah[2][4], al[2][4], bh[8][2], bl[8][2];
#pragma unroll
            for (int mt = 0; mt < 2; mt++) {
                int row = wm + mt * 16 + aRow;
                ldsm_x4(ah[mt], sA + SWB(row, shi + aSel));
                if (THREE) ldsm_x4(al[mt], sA + SWB(row, slo + aSel));
            }
#pragma unroll
            for (int p = 0; p < 4; p++) {
                int row = p * 16 + bRow;
                uint32_t r4[4];
                ldsm_x4(r4, sB + SWB(row, shi + bSel));
                bh[2 * p][0] = r4[0]; bh[2 * p][1] = r4[1];
                bh[2 * p + 1][0] = r4[2]; bh[2 * p + 1][1] = r4[3];
                ldsm_x4(r4, sB + SWB(row, slo + bSel));
                bl[2 * p][0] = r4[0]; bl[2 * p][1] = r4[1];
                bl[2 * p + 1][0] = r4[2]; bl[2 * p + 1][1] = r4[3];
            }
#pragma unroll
            for (int mt = 0; mt < 2; mt++)
#pragma unroll
                for (int nt = 0; nt < 8; nt++) {
                    mma_f16(C[mt][nt], ah[mt], bh[nt]);
                    mma_f16(C[mt][nt], ah[mt], bl[nt]);
                    if (THREE) mma_f16(C[mt][nt], al[mt], bh[nt]);
                }
        }

        if (kc + 2 < 32) {
            int ns = (st + 2) % 3;
            gemm_stage<THREE>(base + ns * STG_BYTES, base + ns * STG_BYTES + 16384,
                              Ah4, Al4, Bh4, Bl4, (kc + 2) * 4, tid);
            CP_COMMIT();
        }
        st = (st + 1) % 3;
    }
}

// ---------------------------------------------------------------------------
// QKV: templated passes; writes fp16 hi/lo Q/K/V. block = 128.
// K,Q tiles (ntBase=0, gridDim.x=2): 3-pass.  V tile (ntBase=2): 2-pass.
// ---------------------------------------------------------------------------
template <bool THREE>
__global__ __launch_bounds__(128, 3) void qkv_mma_kernel(const float* __restrict__ bqkv,
                                                         int ntBase) {
    int nt = blockIdx.x + ntBase, mt = blockIdx.y, h = blockIdx.z;
    int mbase = mt * 128;

    const uint4* Ah4 = (const uint4*)g_xh + (size_t)mbase * 128;
    const uint4* Al4 = (const uint4*)g_xl + (size_t)mbase * 128;
    size_t boff = ((size_t)h * 192 + nt * 64) * 128;
    const uint4* Bh4 = (const uint4*)g_wqh + boff;
    const uint4* Bl4 = (const uint4*)g_wql + boff;

    float C[2][8][4];
    gemm_mainloop<THREE>(Ah4, Al4, Bh4, Bl4, C);

    int lane = threadIdx.x & 31, w = threadIdx.x >> 5;
    int g = lane >> 2, tg = lane & 3;

    const float* bp = bqkv + h * 192 + nt * 64;
    __half* dh = (nt == 0) ? g_Kh : (nt == 1) ? g_Qh : g_Vh;
    __half* dl = (nt == 0) ? g_Kl : (nt == 1) ? g_Ql : g_Vl;

#pragma unroll
    for (int mt2 = 0; mt2 < 2; mt2++) {
#pragma unroll
        for (int half = 0; half < 2; half++) {
            int m = mbase + w * 32 + mt2 * 16 + g + half * 8;
            int b = m >> 11, n = m & 2047;
            size_t ro = (((size_t)(b * H_ + h)) * N_ + n) * HD_;
#pragma unroll
            for (int nt2 = 0; nt2 < 8; nt2++) {
                int col = nt2 * 8 + tg * 2;
                float vx = C[mt2][nt2][half * 2 + 0] + bp[col];
                float vy = C[mt2][nt2][half * 2 + 1] + bp[col + 1];
                split_store_pair(vx, vy, dh + ro + col, dl + ro + col);
            }
        }
    }
}

// ---------------------------------------------------------------------------
// Output projection: 2-pass (A hi only). grid = (16, 32), block = 128
// ---------------------------------------------------------------------------
__global__ __launch_bounds__(128, 3) void outproj_mma_kernel(const float* __restrict__ bout,
                                                             float* __restrict__ out) {
    int nt = blockIdx.x, mt = blockIdx.y;
    int mbase = mt * 128;

    const uint4* Ah4 = (const uint4*)g_sah + (size_t)mbase * 128;
    size_t boff = (size_t)nt * 64 * 128;
    const uint4* Bh4 = (const uint4*)g_woh + boff;
    const uint4* Bl4 = (const uint4*)g_wol + boff;

    float C[2][8][4];
    gemm_mainloop<false>(Ah4, Ah4, Bh4, Bl4, C);

    int lane = threadIdx.x & 31, w = threadIdx.x >> 5;
    int g = lane >> 2, tg = lane & 3;

    const float* bp = bout + nt * 64;

#pragma unroll
    for (int mt2 = 0; mt2 < 2; mt2++) {
#pragma unroll
        for (int half = 0; half < 2; half++) {
            int m = mbase + w * 32 + mt2 * 16 + g + half * 8;
            float* drow = out + (size_t)m * E_ + nt * 64;
#pragma unroll
            for (int nt2 = 0; nt2 < 8; nt2++) {
                int col = nt2 * 8 + tg * 2;
                float2 v;
                v.x = C[mt2][nt2][half * 2 + 0] + bp[col];
                v.y = C[mt2][nt2][half * 2 + 1] + bp[col + 1];
                *(float2*)&drow[col] = v;
            }
        }
    }
}

// ---------------------------------------------------------------------------
// Tensor-core causal flash attention: S 3-pass, PV 2-pass, staged prefetch.
// K(kt+1) loads issued after S(kt) (overlap softmax+PV); V(kt+1) after PV(kt)
// (overlap next S). Separate commit groups; wait_group 1 / 0 pairing.
// Block = 128 q rows; 8 warps x 16 rows. grid = (16, 32), block = 256.
// ---------------------------------------------------------------------------
__global__ __launch_bounds__(256) void attn_mma_kernel() {
    __shared__ __half sKh[64 * 64];
    __shared__ __half sKl[64 * 64];
    __shared__ __half sVh[64 * 64];
    __shared__ __half sVl[64 * 64];

    int qt = (int)(gridDim.x - 1) - (int)blockIdx.x;   // heavy tiles first
    int bh = blockIdx.y;
    int tid = threadIdx.x, lane = tid & 31, w = tid >> 5;
    int g = lane >> 2, tg = lane & 3;
    int qbase = qt * 128, wrow = w * 16;
    int row0 = qbase + wrow + g, row1 = row0 + 8;

    uint32_t uKh = smem_u32(sKh), uKl = smem_u32(sKl);
    uint32_t uVh = smem_u32(sVh), uVl = smem_u32(sVl);

    const uint4* KhG = (const uint4*)(g_Kh + (size_t)bh * N_ * HD_);
    const uint4* KlG = (const uint4*)(g_Kl + (size_t)bh * N_ * HD_);
    const uint4* VhG = (const uint4*)(g_Vh + (size_t)bh * N_ * HD_);
    const uint4* VlG = (const uint4*)(g_Vl + (size_t)bh * N_ * HD_);

    int ldR = tid >> 3, ldS = tid & 7;            // 256 threads cover 64 rows x 8 slots / 2
    uint32_t ldOff = SWB(ldR, ldS);
    int nkt = 2 * qt + 2;

    // prologue: K0 group, then V0 group
    {
        int gbase = 0;
#pragma unroll
        for (int p = 0; p < 2; p++) {
            int idx = tid + p * 256;
            int r = idx >> 3, s = idx & 7;
            uint32_t so = SWB(r, s);
            CP_ASYNC16(uKh + so, KhG + gbase + r * 8 + s);
            CP_ASYNC16(uKl + so, KlG + gbase + r * 8 + s);
        }
        CP_COMMIT();
#pragma unroll
        for (int p = 0; p < 2; p++) {
            int idx = tid + p * 256;
            int r = idx >> 3, s = idx & 7;
            uint32_t so = SWB(r, s);
            CP_ASYNC16(uVh + so, VhG + gbase + r * 8 + s);
            CP_ASYNC16(uVl + so, VlG + gbase + r * 8 + s);
        }
        CP_COMMIT();
    }

    // Q fragments (hi/lo) straight from gmem (overlaps prologue loads)
    const __half* Qh = g_Qh + ((size_t)bh * N_ + qbase + wrow) * HD_;
    const __half* Ql = g_Ql + ((size_t)bh * N_ + qbase + wrow) * HD_;
    uint32_t qh[4][4], ql[4][4];
#pragma unroll
    for (int ko = 0; ko < 4; ko++) {
        int c = ko * 16 + tg * 2;
        qh[ko][0] = *(const uint32_t*)&Qh[(size_t)g * 64 + c];
        qh[ko][1] = *(const uint32_t*)&Qh[(size_t)(g + 8) * 64 + c];
        qh[ko][2] = *(const uint32_t*)&Qh[(size_t)g * 64 + c + 8];
        qh[ko][3] = *(const uint32_t*)&Qh[(size_t)(g + 8) * 64 + c + 8];
        ql[ko][0] = *(const uint32_t*)&Ql[(size_t)g * 64 + c];
        ql[ko][1] = *(const uint32_t*)&Ql[(size_t)(g + 8) * 64 + c];
        ql[ko][2] = *(const uint32_t*)&Ql[(size_t)g * 64 + c + 8];
        ql[ko][3] = *(const uint32_t*)&Ql[(size_t)(g + 8) * 64 + c + 8];
    }

    float Co[8][4];
#pragma unroll
    for (int nt = 0; nt < 8; nt++)
#pragma unroll
        for (int i = 0; i < 4; i++) Co[nt][i] = 0.f;
    float m0 = -1e30f, m1 = -1e30f, l0 = 0.f, l1 = 0.f;

    int kRow = (lane & 7) + ((lane >> 4) & 1) * 8;   // K (non-trans, B-style)
    int kSel = (lane >> 3) & 1;
    int vRow = (lane & 15);                          // V (trans, A-style)
    int vSel = (lane >> 4) & 1;

    for (int kt = 0; kt < nkt; kt++) {
        // K tile of kt ready (all groups except newest V group)
        CP_WAIT1();
        __syncthreads();

        // ---- S = Q K^T (3-pass split) ----
        float Cs[8][4];
#pragma unroll
        for (int nt = 0; nt < 8; nt++)
#pragma unroll
            for (int i = 0; i < 4; i++) Cs[nt][i] = 0.f;

#pragma unroll
        for (int ko = 0; ko < 4; ko++) {
#pragma unroll
            for (int p = 0; p < 4; p++) {
                int row = p * 16 + kRow;
                uint32_t so = SWB(row, ko * 2 + kSel);
                uint32_t kh4[4], kl4[4];
                ldsm_x4(kh4, uKh + so);
                ldsm_x4(kl4, uKl + so);
                mma_f16(Cs[2 * p],     qh[ko], kh4);
                mma_f16(Cs[2 * p],     ql[ko], kh4);
                mma_f16(Cs[2 * p],     qh[ko], kl4);
                mma_f16(Cs[2 * p + 1], qh[ko], kh4 + 2);
                mma_f16(Cs[2 * p + 1], ql[ko], kh4 + 2);
                mma_f16(Cs[2 * p + 1], qh[ko], kl4 + 2);
            }
        }

        // all warps done reading K tile kt
        __syncthreads();

        // prefetch K(kt+1), then make V(kt) ready
        if (kt + 1 < nkt) {
            int gbase = (kt + 1) * 64 * 8;
#pragma unroll
            for (int p = 0; p < 2; p++) {
                int idx = tid + p * 256;
                int r = idx >> 3, s = idx & 7;
                uint32_t so = SWB(r, s);
                CP_ASYNC16(uKh + so, KhG + gbase + r * 8 + s);
                CP_ASYNC16(uKl + so, KlG + gbase + r * 8 + s);
            }
            CP_COMMIT();
            CP_WAIT1();              // completes V(kt); K(kt+1) still in flight
        } else {
            CP_WAIT0();              // last tile: only V(kt) outstanding
        }
        __syncthreads();

        // ---- mask + scale + row max ----
        int kb = kt * 64;
        float mt0 = -1e30f, mt1 = -1e30f;
#pragma unroll
        for (int nt = 0; nt < 8; nt++) {
            int col = kb + nt * 8 + tg * 2;
#pragma unroll
            for (int j = 0; j < 2; j++) {
                float v0 = Cs[nt][j] * 0.125f;
                float v1 = Cs[nt][2 + j] * 0.125f;
                v0 = (col + j <= row0) ? v0 : -1e30f;
                v1 = (col + j <= row1) ? v1 : -1e30f;
                Cs[nt][j] = v0; Cs[nt][2 + j] = v1;
                mt0 = fmaxf(mt0, v0); mt1 = fmaxf(mt1, v1);
            }
        }
        mt0 = fmaxf(mt0, __shfl_xor_sync(0xffffffffu, mt0, 1));
        mt0 = fmaxf(mt0, __shfl_xor_sync(0xffffffffu, mt0, 2));
        mt1 = fmaxf(mt1, __shfl_xor_sync(0xffffffffu, mt1, 1));
        mt1 = fmaxf(mt1, __shfl_xor_sync(0xffffffffu, mt1, 2));

        float mn0 = fmaxf(m0, mt0), mn1 = fmaxf(m1, mt1);
        float a0 = __expf(m0 - mn0), a1 = __expf(m1 - mn1);
        m0 = mn0; m1 = mn1;
        l0 *= a0; l1 *= a1;
#pragma unroll
        for (int nt = 0; nt < 8; nt++) {
            Co[nt][0] *= a0; Co[nt][1] *= a0;
            Co[nt][2] *= a1; Co[nt][3] *= a1;
        }

        // ---- exp + row sums ----
        float s0 = 0.f, s1 = 0.f;
#pragma unroll
        for (int nt = 0; nt < 8; nt++) {
#pragma unroll
            for (int j = 0; j < 2; j++) {
                float p0 = __expf(Cs[nt][j] - m0);
                float p1 = __expf(Cs[nt][2 + j] - m1);
                Cs[nt][j] = p0; Cs[nt][2 + j] = p1;
                s0 += p0; s1 += p1;
            }
        }
        s0 += __shfl_xor_sync(0xffffffffu, s0, 1);
        s0 += __shfl_xor_sync(0xffffffffu, s0, 2);
        s1 += __shfl_xor_sync(0xffffffffu, s1, 1);
        s1 += __shfl_xor_sync(0xffffffffu, s1, 2);
        l0 += s0; l1 += s1;

        // ---- O += P V (2-pass: Ph*(Vh+Vl)) ----
#pragma unroll
        for (int ko = 0; ko < 4; ko++) {
            uint32_t ph[4];
            ph[0] = pack_h2(Cs[2 * ko][0], Cs[2 * ko][1]);
            ph[1] = pack_h2(Cs[2 * ko][2], Cs[2 * ko][3]);
            ph[2] = pack_h2(Cs[2 * ko + 1][0], Cs[2 * ko + 1][1]);
            ph[3] = pack_h2(Cs[2 * ko + 1][2], Cs[2 * ko + 1][3]);
#pragma unroll
            for (int p = 0; p < 4; p++) {
                int row = ko * 16 + vRow;
                uint32_t so = SWB(row, p * 2 + vSel);
                uint32_t vh4[4], vl4[4];
                ldsm_x4_t(vh4, uVh + so);
                ldsm_x4_t(vl4, uVl + so);
                mma_f16(Co[2 * p],     ph, vh4);
                mma_f16(Co[2 * p],     ph, vl4);
                mma_f16(Co[2 * p + 1], ph, vh4 + 2);
                mma_f16(Co[2 * p + 1], ph, vl4 + 2);
            }
        }

        // all warps done reading V tile kt; prefetch V(kt+1)
        __syncthreads();
        if (kt + 1 < nkt) {
            int gbase = (kt + 1) * 64 * 8;
#pragma unroll
            for (int p = 0; p < 2; p++) {
                int idx = tid + p * 256;
                int r = idx >> 3, s = idx & 7;
                uint32_t so = SWB(r, s);
                CP_ASYNC16(uVh + so, VhG + gbase + r * 8 + s);
                CP_ASYNC16(uVl + so, VlG + gbase + r * 8 + s);
            }
            CP_COMMIT();
        }
    }

    // ---- finalize: O /= l, write fp16 hi into sa layout [b][n][E] ----
    float inv0 = 1.f / l0, inv1 = 1.f / l1;
    int b = bh >> 4, h = bh & 15;
    size_t ro0 = ((size_t)(b * N_) + row0) * E_ + h * HD_;
    size_t ro1 = ((size_t)(b * N_) + row1) * E_ + h * HD_;
#pragma unroll
    for (int nt = 0; nt < 8; nt++) {
        int col = nt * 8 + tg * 2;
        *(uint32_t*)&g_sah[ro0 + col] = pack_h2(Co[nt][0] * inv0, Co[nt][1] * inv0);
        *(uint32_t*)&g_sah[ro1 + col] = pack_h2(Co[nt][2] * inv1, Co[nt][3] * inv1);
    }
}

// ---------------------------------------------------------------------------
extern "C" void kernel_launch(void* const* d_in, const int* in_sizes, int n_in,
                              void* d_out, int out_size) {
    const float* x    = (const float*)d_in[0];
    const float* Wqkv = (const float*)d_in[1];
    const float* bqkv = (const float*)d_in[2];
    const float* Wout = (const float*)d_in[3];
    const float* bout = (const float*)d_in[4];
    float* out = (float*)d_out;

    const int DSM = 3 * STG_BYTES;   // 72KB
    cudaFuncSetAttribute(qkv_mma_kernel<true>,
                         cudaFuncAttributeMaxDynamicSharedMemorySize, DSM);
    cudaFuncSetAttribute(qkv_mma_kernel<false>,
                         cudaFuncAttributeMaxDynamicSharedMemorySize, DSM);
    cudaFuncSetAttribute(outproj_mma_kernel,
                         cudaFuncAttributeMaxDynamicSharedMemorySize, DSM);

    split_x_kernel<<<2048, 256>>>(x);
    tsplit_wq_kernel<<<dim3(6, 32, 16), dim3(32, 8)>>>(Wqkv);
    tsplit_wo_kernel<<<dim3(32, 32, 1), dim3(32, 8)>>>(Wout);

    // K,Q tiles: 3-pass.  V tile: 2-pass.
    qkv_mma_kernel<true><<<dim3(2, 32, 16), 128, DSM>>>(bqkv, 0);
    qkv_mma_kernel<false><<<dim3(1, 32, 16), 128, DSM>>>(bqkv, 2);

    attn_mma_kernel<<<dim3(16, 32), 256>>>();

    outproj_mma_kernel<<<dim3(16, 32), 128, DSM>>>(bout, out);
}

// round 14
// speedup vs baseline: 4.7051x; 1.0259x over previous
#include <cuda_runtime.h>
#include <cuda_fp16.h>
#include <math.h>
#include <stdint.h>

#define B_ 2
#define N_ 2048
#define E_ 1024
#define H_ 16
#define HD_ 64

// ---------------------------------------------------------------------------
// Scratch (__device__ globals; allocation-free rule). fp16 hi/lo splits.
// ---------------------------------------------------------------------------
__device__ __half g_xh[(size_t)4096*1024];
__device__ __half g_xl[(size_t)4096*1024];
__device__ __half g_wqh[(size_t)16*192*1024];   // [h][n][k] (transposed)
__device__ __half g_wql[(size_t)16*192*1024];
__device__ __half g_woh[(size_t)1024*1024];     // [n][k] (transposed)
__device__ __half g_wol[(size_t)1024*1024];
__device__ __half g_sah[(size_t)4096*1024];     // attention output, fp16 hi only

// Q (hi only), K/V fp16 hi/lo, layout [bh][n][64]
__device__ __half g_Qh[(size_t)B_*H_*N_*HD_];
__device__ __half g_Kh[(size_t)B_*H_*N_*HD_];
__device__ __half g_Kl[(size_t)B_*H_*N_*HD_];
__device__ __half g_Vh[(size_t)B_*H_*N_*HD_];
__device__ __half g_Vl[(size_t)B_*H_*N_*HD_];

// ---------------------------------------------------------------------------
// PTX helpers (baseline-PTX features only)
// ---------------------------------------------------------------------------
__device__ __forceinline__ void mma_f16(float* c, const uint32_t* a, const uint32_t* b) {
    asm volatile(
        "mma.sync.aligned.m16n8k16.row.col.f32.f16.f16.f32 "
        "{%0,%1,%2,%3},{%4,%5,%6,%7},{%8,%9},{%0,%1,%2,%3};"
        : "+f"(c[0]), "+f"(c[1]), "+f"(c[2]), "+f"(c[3])
        : "r"(a[0]), "r"(a[1]), "r"(a[2]), "r"(a[3]), "r"(b[0]), "r"(b[1]));
}

__device__ __forceinline__ void ldsm_x4(uint32_t* r, uint32_t addr) {
    asm volatile("ldmatrix.sync.aligned.m8n8.x4.shared.b16 {%0,%1,%2,%3}, [%4];"
        : "=r"(r[0]), "=r"(r[1]), "=r"(r[2]), "=r"(r[3]) : "r"(addr));
}
__device__ __forceinline__ void ldsm_x4_t(uint32_t* r, uint32_t addr) {
    asm volatile("ldmatrix.sync.aligned.m8n8.x4.trans.shared.b16 {%0,%1,%2,%3}, [%4];"
        : "=r"(r[0]), "=r"(r[1]), "=r"(r[2]), "=r"(r[3]) : "r"(addr));
}

#define CP_ASYNC16(dst, src) \
    asm volatile("cp.async.cg.shared.global [%0], [%1], 16;" :: "r"(dst), "l"(src))
#define CP_COMMIT() asm volatile("cp.async.commit_group;" ::: "memory")
#define CP_WAIT0()  asm volatile("cp.async.wait_group 0;" ::: "memory")
#define CP_WAIT1()  asm volatile("cp.async.wait_group 1;" ::: "memory")

__device__ __forceinline__ uint32_t smem_u32(const void* p) {
    return (uint32_t)__cvta_generic_to_shared(p);
}

// 128B rows, classic SW128: 16B slot s of row r lives at slot s^(r&7)
#define SWB(r, s) ((uint32_t)((r) * 128 + (((s) ^ ((r) & 7)) << 4)))

__device__ __forceinline__ uint32_t pack_h2(float lo, float hi) {
    union { __half2 v; uint32_t u; } U;
    U.v = __floats2half2_rn(lo, hi);
    return U.u;
}

// split fp32 pair into fp16 hi pair + fp16 residual pair
__device__ __forceinline__ void split_store_pair(float vx, float vy,
                                                 __half* dh, __half* dl) {
    __half hx = __float2half_rn(vx);
    __half hy = __float2half_rn(vy);
    union { __half2 v; uint32_t u; } H, L;
    H.v.x = hx; H.v.y = hy;
    L.v = __floats2half2_rn(vx - __half2float(hx), vy - __half2float(hy));
    *(uint32_t*)dh = H.u;
    *(uint32_t*)dl = L.u;
}

// ---------------------------------------------------------------------------
// Conversion kernels
// ---------------------------------------------------------------------------
__device__ __forceinline__ void split_body(const float* __restrict__ src,
                                           __half* __restrict__ hi,
                                           __half* __restrict__ lo, int n4) {
    int i = blockIdx.x * blockDim.x + threadIdx.x;
    int stride = gridDim.x * blockDim.x;
    for (; i < n4; i += stride) {
        float4 v = ((const float4*)src)[i];
        union { __half b[4]; uint2 u; } Hh, Ll;
        float vs[4] = {v.x, v.y, v.z, v.w};
#pragma unroll
        for (int j = 0; j < 4; j++) {
            __half h = __float2half_rn(vs[j]);
            Hh.b[j] = h;
            Ll.b[j] = __float2half_rn(vs[j] - __half2float(h));
        }
        ((uint2*)hi)[i] = Hh.u;
        ((uint2*)lo)[i] = Ll.u;
    }
}

__global__ void split_x_kernel(const float* __restrict__ x) {
    split_body(x, g_xh, g_xl, 4096 * 1024 / 4);
}

__device__ __forceinline__ void tsplit_body(const float* __restrict__ in,
                                            __half* __restrict__ oh,
                                            __half* __restrict__ ol,
                                            int R, int C) {
    __shared__ float t[32][33];
    size_t zo = (size_t)blockIdx.z * R * C;
    in += zo; oh += zo; ol += zo;
    int c0 = blockIdx.x * 32, r0 = blockIdx.y * 32;
    int tx = threadIdx.x, ty = threadIdx.y;
#pragma unroll
    for (int i = 0; i < 32; i += 8)
        t[ty + i][tx] = in[(size_t)(r0 + ty + i) * C + c0 + tx];
    __syncthreads();
#pragma unroll
    for (int i = 0; i < 32; i += 8) {
        float v = t[tx][ty + i];
        __half h = __float2half_rn(v);
        oh[(size_t)(c0 + ty + i) * R + r0 + tx] = h;
        ol[(size_t)(c0 + ty + i) * R + r0 + tx] = __float2half_rn(v - __half2float(h));
    }
}

__global__ void tsplit_wq_kernel(const float* __restrict__ Wqkv) {
    tsplit_body(Wqkv, g_wqh, g_wql, 1024, 192);
}
__global__ void tsplit_wo_kernel(const float* __restrict__ Wout) {
    tsplit_body(Wout, g_woh, g_wol, 1024, 1024);
}

// ---------------------------------------------------------------------------
// GEMM mainloop: 3-stage cp.async pipeline, dynamic smem (72KB), 128 threads.
// three=true : 3-pass Ah*Bh + Ah*Bl + Al*Bh
// three=false: 2-pass Ah*Bh + Ah*Bl (Al never loaded)
// Per stage: A 16KB (rows 128B = hi|lo) + B 8KB = 24KB. 3 stages = 72KB.
// ---------------------------------------------------------------------------
#define STG_BYTES 24576

__device__ __forceinline__ void gemm_stage(
    bool three, uint32_t sA, uint32_t sB,
    const uint4* __restrict__ Ah4, const uint4* __restrict__ Al4,
    const uint4* __restrict__ Bh4, const uint4* __restrict__ Bl4,
    int kb4, int tid)
{
    if (three) {
#pragma unroll
        for (int p = 0; p < 8; p++) {
            int idx = tid + p * 128;
            int r = idx >> 3, s = idx & 7;
            const uint4* src = (s < 4) ? (Ah4 + (size_t)r * 128 + kb4 + s)
                                       : (Al4 + (size_t)r * 128 + kb4 + (s - 4));
            CP_ASYNC16(sA + SWB(r, s), src);
        }
    } else {
#pragma unroll
        for (int p = 0; p < 4; p++) {
            int idx = tid + p * 128;
            int r = idx >> 2, s = idx & 3;
            CP_ASYNC16(sA + SWB(r, s), Ah4 + (size_t)r * 128 + kb4 + s);
        }
    }
#pragma unroll
    for (int p = 0; p < 4; p++) {
        int idx = tid + p * 128;
        int r = idx >> 3, s = idx & 7;
        const uint4* src = (s < 4) ? (Bh4 + (size_t)r * 128 + kb4 + s)
                                   : (Bl4 + (size_t)r * 128 + kb4 + (s - 4));
        CP_ASYNC16(sB + SWB(r, s), src);
    }
}

__device__ __forceinline__ void gemm_mainloop(
    bool three,
    const uint4* __restrict__ Ah4, const uint4* __restrict__ Al4,
    const uint4* __restrict__ Bh4, const uint4* __restrict__ Bl4,
    float C[2][8][4])
{
    extern __shared__ __align__(128) char dynsm[];
    uint32_t base = smem_u32(dynsm);

    int tid = threadIdx.x;
    int lane = tid & 31, w = tid >> 5;
    int wm = w * 32;

#pragma unroll
    for (int mt = 0; mt < 2; mt++)
#pragma unroll
        for (int nt = 0; nt < 8; nt++)
#pragma unroll
            for (int i = 0; i < 4; i++) C[mt][nt][i] = 0.f;

    int aRow = (lane & 15);
    int aSel = (lane >> 4) & 1;
    int bRow = (lane & 7) + ((lane >> 4) & 1) * 8;
    int bSel = (lane >> 3) & 1;

    gemm_stage(three, base, base + 16384, Ah4, Al4, Bh4, Bl4, 0, tid);
    CP_COMMIT();
    gemm_stage(three, base + STG_BYTES, base + STG_BYTES + 16384,
               Ah4, Al4, Bh4, Bl4, 4, tid);
    CP_COMMIT();

    int st = 0;
    for (int kc = 0; kc < 32; kc++) {
        if (kc < 31) { CP_WAIT1(); } else { CP_WAIT0(); }
        __syncthreads();
        uint32_t sA = base + st * STG_BYTES;
        uint32_t sB = sA + 16384;

#pragma unroll
        for (int k16 = 0; k16 < 2; k16++) {
            int shi = k16 * 2, slo = 4 + k16 * 2;
            uint32_t ah[2][4], al[2][4], bh[8][2], bl[8][2];
#pragma unroll
            for (int mt = 0; mt < 2; mt++) {
                int row = wm + mt * 16 + aRow;
                ldsm_x4(ah[mt], sA + SWB(row, shi + aSel));
                if (three) ldsm_x4(al[mt], sA + SWB(row, slo + aSel));
            }
#pragma unroll
            for (int p = 0; p < 4; p++) {
                int row = p * 16 + bRow;
                uint32_t r4[4];
                ldsm_x4(r4, sB + SWB(row, shi + bSel));
                bh[2 * p][0] = r4[0]; bh[2 * p][1] = r4[1];
                bh[2 * p + 1][0] = r4[2]; bh[2 * p + 1][1] = r4[3];
                ldsm_x4(r4, sB + SWB(row, slo + bSel));
                bl[2 * p][0] = r4[0]; bl[2 * p][1] = r4[1];
                bl[2 * p + 1][0] = r4[2]; bl[2 * p + 1][1] = r4[3];
            }
#pragma unroll
            for (int mt = 0; mt < 2; mt++)
#pragma unroll
                for (int nt = 0; nt < 8; nt++) {
                    mma_f16(C[mt][nt], ah[mt], bh[nt]);
                    mma_f16(C[mt][nt], ah[mt], bl[nt]);
                    if (three) mma_f16(C[mt][nt], al[mt], bh[nt]);
                }
        }

        if (kc + 2 < 32) {
            int ns = (st + 2) % 3;
            gemm_stage(three, base + ns * STG_BYTES, base + ns * STG_BYTES + 16384,
                       Ah4, Al4, Bh4, Bl4, (kc + 2) * 4, tid);
            CP_COMMIT();
        }
        st = (st + 1) % 3;
    }
}

// ---------------------------------------------------------------------------
// QKV merged: nt 0=K (3-pass), 1=Q (3-pass, hi-only store), 2=V (2-pass).
// grid = (3, 32, 16), block = 128.
// ---------------------------------------------------------------------------
__global__ __launch_bounds__(128, 3) void qkv_mma_kernel(const float* __restrict__ bqkv) {
    int nt = blockIdx.x, mt = blockIdx.y, h = blockIdx.z;
    int mbase = mt * 128;
    bool three = (nt < 2);

    const uint4* Ah4 = (const uint4*)g_xh + (size_t)mbase * 128;
    const uint4* Al4 = (const uint4*)g_xl + (size_t)mbase * 128;
    size_t boff = ((size_t)h * 192 + nt * 64) * 128;
    const uint4* Bh4 = (const uint4*)g_wqh + boff;
    const uint4* Bl4 = (const uint4*)g_wql + boff;

    float C[2][8][4];
    gemm_mainloop(three, Ah4, Al4, Bh4, Bl4, C);

    int lane = threadIdx.x & 31, w = threadIdx.x >> 5;
    int g = lane >> 2, tg = lane & 3;

    const float* bp = bqkv + h * 192 + nt * 64;
    __half* dh = (nt == 0) ? g_Kh : (nt == 1) ? g_Qh : g_Vh;
    __half* dl = (nt == 0) ? g_Kl : g_Vl;   // unused for nt==1

#pragma unroll
    for (int mt2 = 0; mt2 < 2; mt2++) {
#pragma unroll
        for (int half = 0; half < 2; half++) {
            int m = mbase + w * 32 + mt2 * 16 + g + half * 8;
            int b = m >> 11, n = m & 2047;
            size_t ro = (((size_t)(b * H_ + h)) * N_ + n) * HD_;
#pragma unroll
            for (int nt2 = 0; nt2 < 8; nt2++) {
                int col = nt2 * 8 + tg * 2;
                float vx = C[mt2][nt2][half * 2 + 0] + bp[col];
                float vy = C[mt2][nt2][half * 2 + 1] + bp[col + 1];
                if (nt == 1) {
                    *(uint32_t*)&dh[ro + col] = pack_h2(vx, vy);
                } else {
                    split_store_pair(vx, vy, dh + ro + col, dl + ro + col);
                }
            }
        }
    }
}

// ---------------------------------------------------------------------------
// Output projection: 2-pass (A hi only). grid = (16, 32), block = 128
// ---------------------------------------------------------------------------
__global__ __launch_bounds__(128, 3) void outproj_mma_kernel(const float* __restrict__ bout,
                                                             float* __restrict__ out) {
    int nt = blockIdx.x, mt = blockIdx.y;
    int mbase = mt * 128;

    const uint4* Ah4 = (const uint4*)g_sah + (size_t)mbase * 128;
    size_t boff = (size_t)nt * 64 * 128;
    const uint4* Bh4 = (const uint4*)g_woh + boff;
    const uint4* Bl4 = (const uint4*)g_wol + boff;

    float C[2][8][4];
    gemm_mainloop(false, Ah4, Ah4, Bh4, Bl4, C);

    int lane = threadIdx.x & 31, w = threadIdx.x >> 5;
    int g = lane >> 2, tg = lane & 3;

    const float* bp = bout + nt * 64;

#pragma unroll
    for (int mt2 = 0; mt2 < 2; mt2++) {
#pragma unroll
        for (int half = 0; half < 2; half++) {
            int m = mbase + w * 32 + mt2 * 16 + g + half * 8;
            float* drow = out + (size_t)m * E_ + nt * 64;
#pragma unroll
            for (int nt2 = 0; nt2 < 8; nt2++) {
                int col = nt2 * 8 + tg * 2;
                float2 v;
                v.x = C[mt2][nt2][half * 2 + 0] + bp[col];
                v.y = C[mt2][nt2][half * 2 + 1] + bp[col + 1];
                *(float2*)&drow[col] = v;
            }
        }
    }
}

// ---------------------------------------------------------------------------
// Tensor-core causal flash attention: S 2-pass (qh*(kh+kl)), PV 2-pass,
// staged K/V prefetch with separate commit groups.
// Block = 128 q rows; 8 warps x 16 rows. grid = (16, 32), block = 256.
// ---------------------------------------------------------------------------
__global__ __launch_bounds__(256) void attn_mma_kernel() {
    __shared__ __half sKh[64 * 64];
    __shared__ __half sKl[64 * 64];
    __shared__ __half sVh[64 * 64];
    __shared__ __half sVl[64 * 64];

    int qt = (int)(gridDim.x - 1) - (int)blockIdx.x;   // heavy tiles first
    int bh = blockIdx.y;
    int tid = threadIdx.x, lane = tid & 31, w = tid >> 5;
    int g = lane >> 2, tg = lane & 3;
    int qbase = qt * 128, wrow = w * 16;
    int row0 = qbase + wrow + g, row1 = row0 + 8;

    uint32_t uKh = smem_u32(sKh), uKl = smem_u32(sKl);
    uint32_t uVh = smem_u32(sVh), uVl = smem_u32(sVl);

    const uint4* KhG = (const uint4*)(g_Kh + (size_t)bh * N_ * HD_);
    const uint4* KlG = (const uint4*)(g_Kl + (size_t)bh * N_ * HD_);
    const uint4* VhG = (const uint4*)(g_Vh + (size_t)bh * N_ * HD_);
    const uint4* VlG = (const uint4*)(g_Vl + (size_t)bh * N_ * HD_);

    int nkt = 2 * qt + 2;

    // prologue: K0 group, then V0 group
    {
#pragma unroll
        for (int p = 0; p < 2; p++) {
            int idx = tid + p * 256;
            int r = idx >> 3, s = idx & 7;
            uint32_t so = SWB(r, s);
            CP_ASYNC16(uKh + so, KhG + r * 8 + s);
            CP_ASYNC16(uKl + so, KlG + r * 8 + s);
        }
        CP_COMMIT();
#pragma unroll
        for (int p = 0; p < 2; p++) {
            int idx = tid + p * 256;
            int r = idx >> 3, s = idx & 7;
            uint32_t so = SWB(r, s);
            CP_ASYNC16(uVh + so, VhG + r * 8 + s);
            CP_ASYNC16(uVl + so, VlG + r * 8 + s);
        }
        CP_COMMIT();
    }

    // Q hi fragments straight from gmem (overlaps prologue loads)
    const __half* Qh = g_Qh + ((size_t)bh * N_ + qbase + wrow) * HD_;
    uint32_t qh[4][4];
#pragma unroll
    for (int ko = 0; ko < 4; ko++) {
        int c = ko * 16 + tg * 2;
        qh[ko][0] = *(const uint32_t*)&Qh[(size_t)g * 64 + c];
        qh[ko][1] = *(const uint32_t*)&Qh[(size_t)(g + 8) * 64 + c];
        qh[ko][2] = *(const uint32_t*)&Qh[(size_t)g * 64 + c + 8];
        qh[ko][3] = *(const uint32_t*)&Qh[(size_t)(g + 8) * 64 + c + 8];
    }

    float Co[8][4];
#pragma unroll
    for (int nt = 0; nt < 8; nt++)
#pragma unroll
        for (int i = 0; i < 4; i++) Co[nt][i] = 0.f;
    float m0 = -1e30f, m1 = -1e30f, l0 = 0.f, l1 = 0.f;

    int kRow = (lane & 7) + ((lane >> 4) & 1) * 8;   // K (non-trans, B-style)
    int kSel = (lane >> 3) & 1;
    int vRow = (lane & 15);                          // V (trans, A-style)
    int vSel = (lane >> 4) & 1;

    for (int kt = 0; kt < nkt; kt++) {
        // K tile of kt ready (all groups except newest V group)
        CP_WAIT1();
        __syncthreads();

        // ---- S = Q K^T (2-pass: qh*(kh+kl)) ----
        float Cs[8][4];
#pragma unroll
        for (int nt = 0; nt < 8; nt++)
#pragma unroll
            for (int i = 0; i < 4; i++) Cs[nt][i] = 0.f;

#pragma unroll
        for (int ko = 0; ko < 4; ko++) {
#pragma unroll
            for (int p = 0; p < 4; p++) {
                int row = p * 16 + kRow;
                uint32_t so = SWB(row, ko * 2 + kSel);
                uint32_t kh4[4], kl4[4];
                ldsm_x4(kh4, uKh + so);
                ldsm_x4(kl4, uKl + so);
                mma_f16(Cs[2 * p],     qh[ko], kh4);
                mma_f16(Cs[2 * p],     qh[ko], kl4);
                mma_f16(Cs[2 * p + 1], qh[ko], kh4 + 2);
                mma_f16(Cs[2 * p + 1], qh[ko], kl4 + 2);
            }
        }

        // all warps done reading K tile kt
        __syncthreads();

        // prefetch K(kt+1), then make V(kt) ready
        if (kt + 1 < nkt) {
            int gbase = (kt + 1) * 64 * 8;
#pragma unroll
            for (int p = 0; p < 2; p++) {
                int idx = tid + p * 256;
                int r = idx >> 3, s = idx & 7;
                uint32_t so = SWB(r, s);
                CP_ASYNC16(uKh + so, KhG + gbase + r * 8 + s);
                CP_ASYNC16(uKl + so, KlG + gbase + r * 8 + s);
            }
            CP_COMMIT();
            CP_WAIT1();              // completes V(kt); K(kt+1) still in flight
        } else {
            CP_WAIT0();              // last tile: only V(kt) outstanding
        }
        __syncthreads();

        // ---- mask + scale + row max ----
        int kb = kt * 64;
        float mt0 = -1e30f, mt1 = -1e30f;
#pragma unroll
        for (int nt = 0; nt < 8; nt++) {
            int col = kb + nt * 8 + tg * 2;
#pragma unroll
            for (int j = 0; j < 2; j++) {
                float v0 = Cs[nt][j] * 0.125f;
                float v1 = Cs[nt][2 + j] * 0.125f;
                v0 = (col + j <= row0) ? v0 : -1e30f;
                v1 = (col + j <= row1) ? v1 : -1e30f;
                Cs[nt][j] = v0; Cs[nt][2 + j] = v1;
                mt0 = fmaxf(mt0, v0); mt1 = fmaxf(mt1, v1);
            }
        }
        mt0 = fmaxf(mt0, __shfl_xor_sync(0xffffffffu, mt0, 1));
        mt0 = fmaxf(mt0, __shfl_xor_sync(0xffffffffu, mt0, 2));
        mt1 = fmaxf(mt1, __shfl_xor_sync(0xffffffffu, mt1, 1));
        mt1 = fmaxf(mt1, __shfl_xor_sync(0xffffffffu, mt1, 2));

        float mn0 = fmaxf(m0, mt0), mn1 = fmaxf(m1, mt1);
        float a0 = __expf(m0 - mn0), a1 = __expf(m1 - mn1);
        m0 = mn0; m1 = mn1;
        l0 *= a0; l1 *= a1;
#pragma unroll
        for (int nt = 0; nt < 8; nt++) {
            Co[nt][0] *= a0; Co[nt][1] *= a0;
            Co[nt][2] *= a1; Co[nt][3] *= a1;
        }

        // ---- exp + row sums ----
        float s0 = 0.f, s1 = 0.f;
#pragma unroll
        for (int nt = 0; nt < 8; nt++) {
#pragma unroll
            for (int j = 0; j < 2; j++) {
                float p0 = __expf(Cs[nt][j] - m0);
                float p1 = __expf(Cs[nt][2 + j] - m1);
                Cs[nt][j] = p0; Cs[nt][2 + j] = p1;
                s0 += p0; s1 += p1;
            }
        }
        s0 += __shfl_xor_sync(0xffffffffu, s0, 1);
        s0 += __shfl_xor_sync(0xffffffffu, s0, 2);
        s1 += __shfl_xor_sync(0xffffffffu, s1, 1);
        s1 += __shfl_xor_sync(0xffffffffu, s1, 2);
        l0 += s0; l1 += s1;

        // ---- O += P V (2-pass: Ph*(Vh+Vl)) ----
#pragma unroll
        for (int ko = 0; ko < 4; ko++) {
            uint32_t ph[4];
            ph[0] = pack_h2(Cs[2 * ko][0], Cs[2 * ko][1]);
            ph[1] = pack_h2(Cs[2 * ko][2], Cs[2 * ko][3]);
            ph[2] = pack_h2(Cs[2 * ko + 1][0], Cs[2 * ko + 1][1]);
            ph[3] = pack_h2(Cs[2 * ko + 1][2], Cs[2 * ko + 1][3]);
#pragma unroll
            for (int p = 0; p < 4; p++) {
                int row = ko * 16 + vRow;
                uint32_t so = SWB(row, p * 2 + vSel);
                uint32_t vh4[4], vl4[4];
                ldsm_x4_t(vh4, uVh + so);
                ldsm_x4_t(vl4, uVl + so);
                mma_f16(Co[2 * p],     ph, vh4);
                mma_f16(Co[2 * p],     ph, vl4);
                mma_f16(Co[2 * p + 1], ph, vh4 + 2);
                mma_f16(Co[2 * p + 1], ph, vl4 + 2);
            }
        }

        // all warps done reading V tile kt; prefetch V(kt+1)
        __syncthreads();
        if (kt + 1 < nkt) {
            int gbase = (kt + 1) * 64 * 8;
#pragma unroll
            for (int p = 0; p < 2; p++) {
                int idx = tid + p * 256;
                int r = idx >> 3, s = idx & 7;
                uint32_t so = SWB(r, s);
                CP_ASYNC16(uVh + so, VhG + gbase + r * 8 + s);
                CP_ASYNC16(uVl + so, VlG + gbase + r * 8 + s);
            }
            CP_COMMIT();
        }
    }

    // ---- finalize: O /= l, write fp16 hi into sa layout [b][n][E] ----
    float inv0 = 1.f / l0, inv1 = 1.f / l1;
    int b = bh >> 4, h = bh & 15;
    size_t ro0 = ((size_t)(b * N_) + row0) * E_ + h * HD_;
    size_t ro1 = ((size_t)(b * N_) + row1) * E_ + h * HD_;
#pragma unroll
    for (int nt = 0; nt < 8; nt++) {
        int col = nt * 8 + tg * 2;
        *(uint32_t*)&g_sah[ro0 + col] = pack_h2(Co[nt][0] * inv0, Co[nt][1] * inv0);
        *(uint32_t*)&g_sah[ro1 + col] = pack_h2(Co[nt][2] * inv1, Co[nt][3] * inv1);
    }
}

// ---------------------------------------------------------------------------
extern "C" void kernel_launch(void* const* d_in, const int* in_sizes, int n_in,
                              void* d_out, int out_size) {
    const float* x    = (const float*)d_in[0];
    const float* Wqkv = (const float*)d_in[1];
    const float* bqkv = (const float*)d_in[2];
    const float* Wout = (const float*)d_in[3];
    const float* bout = (const float*)d_in[4];
    float* out = (float*)d_out;

    const int DSM = 3 * STG_BYTES;   // 72KB
    cudaFuncSetAttribute(qkv_mma_kernel,
                         cudaFuncAttributeMaxDynamicSharedMemorySize, DSM);
    cudaFuncSetAttribute(outproj_mma_kernel,
                         cudaFuncAttributeMaxDynamicSharedMemorySize, DSM);

    split_x_kernel<<<2048, 256>>>(x);
    tsplit_wq_kernel<<<dim3(6, 32, 16), dim3(32, 8)>>>(Wqkv);
    tsplit_wo_kernel<<<dim3(32, 32, 1), dim3(32, 8)>>>(Wout);

    qkv_mma_kernel<<<dim3(3, 32, 16), 128, DSM>>>(bqkv);

    attn_mma_kernel<<<dim3(16, 32), 256>>>();

    outproj_mma_kernel<<<dim3(16, 32), 128, DSM>>>(bout, out);
}

// round 15
// speedup vs baseline: 5.4769x; 1.1640x over previous
#include <cuda_runtime.h>
#include <cuda_fp16.h>
#include <math.h>
#include <stdint.h>

#define B_ 2
#define N_ 2048
#define E_ 1024
#define H_ 16
#define HD_ 64

// ---------------------------------------------------------------------------
// Scratch (__device__ globals; allocation-free rule). fp16 hi/lo splits.
// ---------------------------------------------------------------------------
__device__ __half g_xh[(size_t)4096*1024];      // x, fp16 hi only
__device__ __half g_wqh[(size_t)16*192*1024];   // [h][n][k] (transposed)
__device__ __half g_wql[(size_t)16*192*1024];
__device__ __half g_woh[(size_t)1024*1024];     // [n][k] (transposed)
__device__ __half g_wol[(size_t)1024*1024];
__device__ __half g_sah[(size_t)4096*1024];     // attention output, fp16 hi only

// Q (hi only), K/V fp16 hi/lo, layout [bh][n][64]
__device__ __half g_Qh[(size_t)B_*H_*N_*HD_];
__device__ __half g_Kh[(size_t)B_*H_*N_*HD_];
__device__ __half g_Kl[(size_t)B_*H_*N_*HD_];
__device__ __half g_Vh[(size_t)B_*H_*N_*HD_];
__device__ __half g_Vl[(size_t)B_*H_*N_*HD_];

// ---------------------------------------------------------------------------
// PTX helpers (baseline-PTX features only)
// ---------------------------------------------------------------------------
__device__ __forceinline__ void mma_f16(float* c, const uint32_t* a, const uint32_t* b) {
    asm volatile(
        "mma.sync.aligned.m16n8k16.row.col.f32.f16.f16.f32 "
        "{%0,%1,%2,%3},{%4,%5,%6,%7},{%8,%9},{%0,%1,%2,%3};"
        : "+f"(c[0]), "+f"(c[1]), "+f"(c[2]), "+f"(c[3])
        : "r"(a[0]), "r"(a[1]), "r"(a[2]), "r"(a[3]), "r"(b[0]), "r"(b[1]));
}

__device__ __forceinline__ void ldsm_x4(uint32_t* r, uint32_t addr) {
    asm volatile("ldmatrix.sync.aligned.m8n8.x4.shared.b16 {%0,%1,%2,%3}, [%4];"
        : "=r"(r[0]), "=r"(r[1]), "=r"(r[2]), "=r"(r[3]) : "r"(addr));
}
__device__ __forceinline__ void ldsm_x4_t(uint32_t* r, uint32_t addr) {
    asm volatile("ldmatrix.sync.aligned.m8n8.x4.trans.shared.b16 {%0,%1,%2,%3}, [%4];"
        : "=r"(r[0]), "=r"(r[1]), "=r"(r[2]), "=r"(r[3]) : "r"(addr));
}

#define CP_ASYNC16(dst, src) \
    asm volatile("cp.async.cg.shared.global [%0], [%1], 16;" :: "r"(dst), "l"(src))
#define CP_COMMIT() asm volatile("cp.async.commit_group;" ::: "memory")
#define CP_WAIT0()  asm volatile("cp.async.wait_group 0;" ::: "memory")
#define CP_WAIT1()  asm volatile("cp.async.wait_group 1;" ::: "memory")

__device__ __forceinline__ uint32_t smem_u32(const void* p) {
    return (uint32_t)__cvta_generic_to_shared(p);
}

// 128B rows, classic SW128: 16B slot s of row r lives at slot s^(r&7)
#define SWB(r, s) ((uint32_t)((r) * 128 + (((s) ^ ((r) & 7)) << 4)))

__device__ __forceinline__ uint32_t pack_h2(float lo, float hi) {
    union { __half2 v; uint32_t u; } U;
    U.v = __floats2half2_rn(lo, hi);
    return U.u;
}

// split fp32 pair into fp16 hi pair + fp16 residual pair
__device__ __forceinline__ void split_store_pair(float vx, float vy,
                                                 __half* dh, __half* dl) {
    __half hx = __float2half_rn(vx);
    __half hy = __float2half_rn(vy);
    union { __half2 v; uint32_t u; } H, L;
    H.v.x = hx; H.v.y = hy;
    L.v = __floats2half2_rn(vx - __half2float(hx), vy - __half2float(hy));
    *(uint32_t*)dh = H.u;
    *(uint32_t*)dl = L.u;
}

// ---------------------------------------------------------------------------
// Conversion kernels
// ---------------------------------------------------------------------------
__global__ void convert_x_kernel(const float* __restrict__ x) {
    int i = blockIdx.x * blockDim.x + threadIdx.x;
    int stride = gridDim.x * blockDim.x;
    int n4 = 4096 * 1024 / 4;
    for (; i < n4; i += stride) {
        float4 v = ((const float4*)x)[i];
        union { __half b[4]; uint2 u; } Hh;
        Hh.b[0] = __float2half_rn(v.x);
        Hh.b[1] = __float2half_rn(v.y);
        Hh.b[2] = __float2half_rn(v.z);
        Hh.b[3] = __float2half_rn(v.w);
        ((uint2*)g_xh)[i] = Hh.u;
    }
}

__device__ __forceinline__ void tsplit_body(const float* __restrict__ in,
                                            __half* __restrict__ oh,
                                            __half* __restrict__ ol,
                                            int R, int C) {
    __shared__ float t[32][33];
    size_t zo = (size_t)blockIdx.z * R * C;
    in += zo; oh += zo; ol += zo;
    int c0 = blockIdx.x * 32, r0 = blockIdx.y * 32;
    int tx = threadIdx.x, ty = threadIdx.y;
#pragma unroll
    for (int i = 0; i < 32; i += 8)
        t[ty + i][tx] = in[(size_t)(r0 + ty + i) * C + c0 + tx];
    __syncthreads();
#pragma unroll
    for (int i = 0; i < 32; i += 8) {
        float v = t[tx][ty + i];
        __half h = __float2half_rn(v);
        oh[(size_t)(c0 + ty + i) * R + r0 + tx] = h;
        ol[(size_t)(c0 + ty + i) * R + r0 + tx] = __float2half_rn(v - __half2float(h));
    }
}

__global__ void tsplit_wq_kernel(const float* __restrict__ Wqkv) {
    tsplit_body(Wqkv, g_wqh, g_wql, 1024, 192);
}
__global__ void tsplit_wo_kernel(const float* __restrict__ Wout) {
    tsplit_body(Wout, g_woh, g_wol, 1024, 1024);
}

// ---------------------------------------------------------------------------
// GEMM mainloop: uniform 2-pass Ah*Bh + Ah*Bl. 3-stage cp.async pipeline,
// dynamic smem (72KB), 128 threads, 4 warps, warp tile 32x64.
// C[128x64] = A[128x1024] @ B[64x1024]^T.
// Per stage: A 16KB region (rows 128B, hi in slots 0-3) + B 8KB = 24KB.
// ---------------------------------------------------------------------------
#define STG_BYTES 24576

__device__ __forceinline__ void gemm_stage(
    uint32_t sA, uint32_t sB,
    const uint4* __restrict__ Ah4,
    const uint4* __restrict__ Bh4, const uint4* __restrict__ Bl4,
    int kb4, int tid)
{
#pragma unroll
    for (int p = 0; p < 4; p++) {
        int idx = tid + p * 128;
        int r = idx >> 2, s = idx & 3;
        CP_ASYNC16(sA + SWB(r, s), Ah4 + (size_t)r * 128 + kb4 + s);
    }
#pragma unroll
    for (int p = 0; p < 4; p++) {
        int idx = tid + p * 128;
        int r = idx >> 3, s = idx & 7;
        const uint4* src = (s < 4) ? (Bh4 + (size_t)r * 128 + kb4 + s)
                                   : (Bl4 + (size_t)r * 128 + kb4 + (s - 4));
        CP_ASYNC16(sB + SWB(r, s), src);
    }
}

__device__ __forceinline__ void gemm_mainloop(
    const uint4* __restrict__ Ah4,
    const uint4* __restrict__ Bh4, const uint4* __restrict__ Bl4,
    float C[2][8][4])
{
    extern __shared__ __align__(128) char dynsm[];
    uint32_t base = smem_u32(dynsm);

    int tid = threadIdx.x;
    int lane = tid & 31, w = tid >> 5;
    int wm = w * 32;

#pragma unroll
    for (int mt = 0; mt < 2; mt++)
#pragma unroll
        for (int nt = 0; nt < 8; nt++)
#pragma unroll
            for (int i = 0; i < 4; i++) C[mt][nt][i] = 0.f;

    int aRow = (lane & 15);
    int aSel = (lane >> 4) & 1;
    int bRow = (lane & 7) + ((lane >> 4) & 1) * 8;
    int bSel = (lane >> 3) & 1;

    gemm_stage(base, base + 16384, Ah4, Bh4, Bl4, 0, tid);
    CP_COMMIT();
    gemm_stage(base + STG_BYTES, base + STG_BYTES + 16384, Ah4, Bh4, Bl4, 4, tid);
    CP_COMMIT();

    int st = 0;
    for (int kc = 0; kc < 32; kc++) {
        if (kc < 31) { CP_WAIT1(); } else { CP_WAIT0(); }
        __syncthreads();
        uint32_t sA = base + st * STG_BYTES;
        uint32_t sB = sA + 16384;

#pragma unroll
        for (int k16 = 0; k16 < 2; k16++) {
            int shi = k16 * 2, slo = 4 + k16 * 2;
            uint32_t ah[2][4], bh[8][2], bl[8][2];
#pragma unroll
            for (int mt = 0; mt < 2; mt++) {
                int row = wm + mt * 16 + aRow;
                ldsm_x4(ah[mt], sA + SWB(row, shi + aSel));
            }
#pragma unroll
            for (int p = 0; p < 4; p++) {
                int row = p * 16 + bRow;
                uint32_t r4[4];
                ldsm_x4(r4, sB + SWB(row, shi + bSel));
                bh[2 * p][0] = r4[0]; bh[2 * p][1] = r4[1];
                bh[2 * p + 1][0] = r4[2]; bh[2 * p + 1][1] = r4[3];
                ldsm_x4(r4, sB + SWB(row, slo + bSel));
                bl[2 * p][0] = r4[0]; bl[2 * p][1] = r4[1];
                bl[2 * p + 1][0] = r4[2]; bl[2 * p + 1][1] = r4[3];
            }
#pragma unroll
            for (int mt = 0; mt < 2; mt++)
#pragma unroll
                for (int nt = 0; nt < 8; nt++) {
                    mma_f16(C[mt][nt], ah[mt], bh[nt]);
                    mma_f16(C[mt][nt], ah[mt], bl[nt]);
                }
        }

        if (kc + 2 < 32) {
            int ns = (st + 2) % 3;
            gemm_stage(base + ns * STG_BYTES, base + ns * STG_BYTES + 16384,
                       Ah4, Bh4, Bl4, (kc + 2) * 4, tid);
            CP_COMMIT();
        }
        st = (st + 1) % 3;
    }
}

// ---------------------------------------------------------------------------
// QKV: uniform 2-pass. nt 0=K, 1=Q (hi-only store), 2=V.
// grid = (3, 32, 16), block = 128.
// ---------------------------------------------------------------------------
__global__ __launch_bounds__(128, 3) void qkv_mma_kernel(const float* __restrict__ bqkv) {
    int nt = blockIdx.x, mt = blockIdx.y, h = blockIdx.z;
    int mbase = mt * 128;

    const uint4* Ah4 = (const uint4*)g_xh + (size_t)mbase * 128;
    size_t boff = ((size_t)h * 192 + nt * 64) * 128;
    const uint4* Bh4 = (const uint4*)g_wqh + boff;
    const uint4* Bl4 = (const uint4*)g_wql + boff;

    float C[2][8][4];
    gemm_mainloop(Ah4, Bh4, Bl4, C);

    int lane = threadIdx.x & 31, w = threadIdx.x >> 5;
    int g = lane >> 2, tg = lane & 3;

    const float* bp = bqkv + h * 192 + nt * 64;
    __half* dh = (nt == 0) ? g_Kh : (nt == 1) ? g_Qh : g_Vh;
    __half* dl = (nt == 0) ? g_Kl : g_Vl;   // unused for nt==1

#pragma unroll
    for (int mt2 = 0; mt2 < 2; mt2++) {
#pragma unroll
        for (int half = 0; half < 2; half++) {
            int m = mbase + w * 32 + mt2 * 16 + g + half * 8;
            int b = m >> 11, n = m & 2047;
            size_t ro = (((size_t)(b * H_ + h)) * N_ + n) * HD_;
#pragma unroll
            for (int nt2 = 0; nt2 < 8; nt2++) {
                int col = nt2 * 8 + tg * 2;
                float vx = C[mt2][nt2][half * 2 + 0] + bp[col];
                float vy = C[mt2][nt2][half * 2 + 1] + bp[col + 1];
                if (nt == 1) {
                    *(uint32_t*)&dh[ro + col] = pack_h2(vx, vy);
                } else {
                    split_store_pair(vx, vy, dh + ro + col, dl + ro + col);
                }
            }
        }
    }
}

// ---------------------------------------------------------------------------
// Output projection: 2-pass. grid = (16, 32), block = 128
// ---------------------------------------------------------------------------
__global__ __launch_bounds__(128, 3) void outproj_mma_kernel(const float* __restrict__ bout,
                                                             float* __restrict__ out) {
    int nt = blockIdx.x, mt = blockIdx.y;
    int mbase = mt * 128;

    const uint4* Ah4 = (const uint4*)g_sah + (size_t)mbase * 128;
    size_t boff = (size_t)nt * 64 * 128;
    const uint4* Bh4 = (const uint4*)g_woh + boff;
    const uint4* Bl4 = (const uint4*)g_wol + boff;

    float C[2][8][4];
    gemm_mainloop(Ah4, Bh4, Bl4, C);

    int lane = threadIdx.x & 31, w = threadIdx.x >> 5;
    int g = lane >> 2, tg = lane & 3;

    const float* bp = bout + nt * 64;

#pragma unroll
    for (int mt2 = 0; mt2 < 2; mt2++) {
#pragma unroll
        for (int half = 0; half < 2; half++) {
            int m = mbase + w * 32 + mt2 * 16 + g + half * 8;
            float* drow = out + (size_t)m * E_ + nt * 64;
#pragma unroll
            for (int nt2 = 0; nt2 < 8; nt2++) {
                int col = nt2 * 8 + tg * 2;
                float2 v;
                v.x = C[mt2][nt2][half * 2 + 0] + bp[col];
                v.y = C[mt2][nt2][half * 2 + 1] + bp[col + 1];
                *(float2*)&drow[col] = v;
            }
        }
    }
}

// ---------------------------------------------------------------------------
// Tensor-core causal flash attention: S 2-pass (qh*(kh+kl)), PV 2-pass,
// staged K/V prefetch; V wait deferred past the register-only softmax.
// Block = 128 q rows; 8 warps x 16 rows. grid = (16, 32), block = 256.
// ---------------------------------------------------------------------------
__global__ __launch_bounds__(256) void attn_mma_kernel() {
    __shared__ __half sKh[64 * 64];
    __shared__ __half sKl[64 * 64];
    __shared__ __half sVh[64 * 64];
    __shared__ __half sVl[64 * 64];

    int qt = (int)(gridDim.x - 1) - (int)blockIdx.x;   // heavy tiles first
    int bh = blockIdx.y;
    int tid = threadIdx.x, lane = tid & 31, w = tid >> 5;
    int g = lane >> 2, tg = lane & 3;
    int qbase = qt * 128, wrow = w * 16;
    int row0 = qbase + wrow + g, row1 = row0 + 8;

    uint32_t uKh = smem_u32(sKh), uKl = smem_u32(sKl);
    uint32_t uVh = smem_u32(sVh), uVl = smem_u32(sVl);

    const uint4* KhG = (const uint4*)(g_Kh + (size_t)bh * N_ * HD_);
    const uint4* KlG = (const uint4*)(g_Kl + (size_t)bh * N_ * HD_);
    const uint4* VhG = (const uint4*)(g_Vh + (size_t)bh * N_ * HD_);
    const uint4* VlG = (const uint4*)(g_Vl + (size_t)bh * N_ * HD_);

    int nkt = 2 * qt + 2;

    // prologue: K0 group, then V0 group
    {
#pragma unroll
        for (int p = 0; p < 2; p++) {
            int idx = tid + p * 256;
            int r = idx >> 3, s = idx & 7;
            uint32_t so = SWB(r, s);
            CP_ASYNC16(uKh + so, KhG + r * 8 + s);
            CP_ASYNC16(uKl + so, KlG + r * 8 + s);
        }
        CP_COMMIT();
#pragma unroll
        for (int p = 0; p < 2; p++) {
            int idx = tid + p * 256;
            int r = idx >> 3, s = idx & 7;
            uint32_t so = SWB(r, s);
            CP_ASYNC16(uVh + so, VhG + r * 8 + s);
            CP_ASYNC16(uVl + so, VlG + r * 8 + s);
        }
        CP_COMMIT();
    }

    // Q hi fragments straight from gmem (overlaps prologue loads)
    const __half* Qh = g_Qh + ((size_t)bh * N_ + qbase + wrow) * HD_;
    uint32_t qh[4][4];
#pragma unroll
    for (int ko = 0; ko < 4; ko++) {
        int c = ko * 16 + tg * 2;
        qh[ko][0] = *(const uint32_t*)&Qh[(size_t)g * 64 + c];
        qh[ko][1] = *(const uint32_t*)&Qh[(size_t)(g + 8) * 64 + c];
        qh[ko][2] = *(const uint32_t*)&Qh[(size_t)g * 64 + c + 8];
        qh[ko][3] = *(const uint32_t*)&Qh[(size_t)(g + 8) * 64 + c + 8];
    }

    float Co[8][4];
#pragma unroll
    for (int nt = 0; nt < 8; nt++)
#pragma unroll
        for (int i = 0; i < 4; i++) Co[nt][i] = 0.f;
    float m0 = -1e30f, m1 = -1e30f, l0 = 0.f, l1 = 0.f;

    int kRow = (lane & 7) + ((lane >> 4) & 1) * 8;   // K (non-trans, B-style)
    int kSel = (lane >> 3) & 1;
    int vRow = (lane & 15);                          // V (trans, A-style)
    int vSel = (lane >> 4) & 1;

    for (int kt = 0; kt < nkt; kt++) {
        // K tile of kt ready (all groups except newest V group)
        CP_WAIT1();
        __syncthreads();

        // ---- S = Q K^T (2-pass: qh*(kh+kl)) ----
        float Cs[8][4];
#pragma unroll
        for (int nt = 0; nt < 8; nt++)
#pragma unroll
            for (int i = 0; i < 4; i++) Cs[nt][i] = 0.f;

#pragma unroll
        for (int ko = 0; ko < 4; ko++) {
#pragma unroll
            for (int p = 0; p < 4; p++) {
                int row = p * 16 + kRow;
                uint32_t so = SWB(row, ko * 2 + kSel);
                uint32_t kh4[4], kl4[4];
                ldsm_x4(kh4, uKh + so);
                ldsm_x4(kl4, uKl + so);
                mma_f16(Cs[2 * p],     qh[ko], kh4);
                mma_f16(Cs[2 * p],     qh[ko], kl4);
                mma_f16(Cs[2 * p + 1], qh[ko], kh4 + 2);
                mma_f16(Cs[2 * p + 1], qh[ko], kl4 + 2);
            }
        }

        // all warps done reading K tile kt
        __syncthreads();

        // prefetch K(kt+1) (V(kt) wait deferred past softmax)
        if (kt + 1 < nkt) {
            int gbase = (kt + 1) * 64 * 8;
#pragma unroll
            for (int p = 0; p < 2; p++) {
                int idx = tid + p * 256;
                int r = idx >> 3, s = idx & 7;
                uint32_t so = SWB(r, s);
                CP_ASYNC16(uKh + so, KhG + gbase + r * 8 + s);
                CP_ASYNC16(uKl + so, KlG + gbase + r * 8 + s);
            }
            CP_COMMIT();
        }

        // ---- mask + scale + row max (registers only) ----
        int kb = kt * 64;
        float mt0 = -1e30f, mt1 = -1e30f;
#pragma unroll
        for (int nt = 0; nt < 8; nt++) {
            int col = kb + nt * 8 + tg * 2;
#pragma unroll
            for (int j = 0; j < 2; j++) {
                float v0 = Cs[nt][j] * 0.125f;
                float v1 = Cs[nt][2 + j] * 0.125f;
                v0 = (col + j <= row0) ? v0 : -1e30f;
                v1 = (col + j <= row1) ? v1 : -1e30f;
                Cs[nt][j] = v0; Cs[nt][2 + j] = v1;
                mt0 = fmaxf(mt0, v0); mt1 = fmaxf(mt1, v1);
            }
        }
        mt0 = fmaxf(mt0, __shfl_xor_sync(0xffffffffu, mt0, 1));
        mt0 = fmaxf(mt0, __shfl_xor_sync(0xffffffffu, mt0, 2));
        mt1 = fmaxf(mt1, __shfl_xor_sync(0xffffffffu, mt1, 1));
        mt1 = fmaxf(mt1, __shfl_xor_sync(0xffffffffu, mt1, 2));

        float mn0 = fmaxf(m0, mt0), mn1 = fmaxf(m1, mt1);
        float a0 = __expf(m0 - mn0), a1 = __expf(m1 - mn1);
        m0 = mn0; m1 = mn1;
        l0 *= a0; l1 *= a1;
#pragma unroll
        for (int nt = 0; nt < 8; nt++) {
            Co[nt][0] *= a0; Co[nt][1] *= a0;
            Co[nt][2] *= a1; Co[nt][3] *= a1;
        }

        // ---- exp + row sums ----
        float s0 = 0.f, s1 = 0.f;
#pragma unroll
        for (int nt = 0; nt < 8; nt++) {
#pragma unroll
            for (int j = 0; j < 2; j++) {
                float p0 = __expf(Cs[nt][j] - m0);
                float p1 = __expf(Cs[nt][2 + j] - m1);
                Cs[nt][j] = p0; Cs[nt][2 + j] = p1;
                s0 += p0; s1 += p1;
            }
        }
        s0 += __shfl_xor_sync(0xffffffffu, s0, 1);
        s0 += __shfl_xor_sync(0xffffffffu, s0, 2);
        s1 += __shfl_xor_sync(0xffffffffu, s1, 1);
        s1 += __shfl_xor_sync(0xffffffffu, s1, 2);
        l0 += s0; l1 += s1;

        // now require V(kt): all groups older than the newest K group done
        if (kt + 1 < nkt) { CP_WAIT1(); } else { CP_WAIT0(); }
        __syncthreads();

        // ---- O += P V (2-pass: Ph*(Vh+Vl)) ----
#pragma unroll
        for (int ko = 0; ko < 4; ko++) {
            uint32_t ph[4];
            ph[0] = pack_h2(Cs[2 * ko][0], Cs[2 * ko][1]);
            ph[1] = pack_h2(Cs[2 * ko][2], Cs[2 * ko][3]);
            ph[2] = pack_h2(Cs[2 * ko + 1][0], Cs[2 * ko + 1][1]);
            ph[3] = pack_h2(Cs[2 * ko + 1][2], Cs[2 * ko + 1][3]);
#pragma unroll
            for (int p = 0; p < 4; p++) {
                int row = ko * 16 + vRow;
                uint32_t so = SWB(row, p * 2 + vSel);
                uint32_t vh4[4], vl4[4];
                ldsm_x4_t(vh4, uVh + so);
                ldsm_x4_t(vl4, uVl + so);
                mma_f16(Co[2 * p],     ph, vh4);
                mma_f16(Co[2 * p],     ph, vl4);
                mma_f16(Co[2 * p + 1], ph, vh4 + 2);
                mma_f16(Co[2 * p + 1], ph, vl4 + 2);
            }
        }

        // all warps done reading V tile kt; prefetch V(kt+1)
        __syncthreads();
        if (kt + 1 < nkt) {
            int gbase = (kt + 1) * 64 * 8;
#pragma unroll
            for (int p = 0; p < 2; p++) {
                int idx = tid + p * 256;
                int r = idx >> 3, s = idx & 7;
                uint32_t so = SWB(r, s);
                CP_ASYNC16(uVh + so, VhG + gbase + r * 8 + s);
                CP_ASYNC16(uVl + so, VlG + gbase + r * 8 + s);
            }
            CP_COMMIT();
        }
    }

    // ---- finalize: O /= l, write fp16 hi into sa layout [b][n][E] ----
    float inv0 = 1.f / l0, inv1 = 1.f / l1;
    int b = bh >> 4, h = bh & 15;
    size_t ro0 = ((size_t)(b * N_) + row0) * E_ + h * HD_;
    size_t ro1 = ((size_t)(b * N_) + row1) * E_ + h * HD_;
#pragma unroll
    for (int nt = 0; nt < 8; nt++) {
        int col = nt * 8 + tg * 2;
        *(uint32_t*)&g_sah[ro0 + col] = pack_h2(Co[nt][0] * inv0, Co[nt][1] * inv0);
        *(uint32_t*)&g_sah[ro1 + col] = pack_h2(Co[nt][2] * inv1, Co[nt][3] * inv1);
    }
}

// ---------------------------------------------------------------------------
extern "C" void kernel_launch(void* const* d_in, const int* in_sizes, int n_in,
                              void* d_out, int out_size) {
    const float* x    = (const float*)d_in[0];
    const float* Wqkv = (const float*)d_in[1];
    const float* bqkv = (const float*)d_in[2];
    const float* Wout = (const float*)d_in[3];
    const float* bout = (const float*)d_in[4];
    float* out = (float*)d_out;

    const int DSM = 3 * STG_BYTES;   // 72KB
    cudaFuncSetAttribute(qkv_mma_kernel,
                         cudaFuncAttributeMaxDynamicSharedMemorySize, DSM);
    cudaFuncSetAttribute(outproj_mma_kernel,
                         cudaFuncAttributeMaxDynamicSharedMemorySize, DSM);

    convert_x_kernel<<<2048, 256>>>(x);
    tsplit_wq_kernel<<<dim3(6, 32, 16), dim3(32, 8)>>>(Wqkv);
    tsplit_wo_kernel<<<dim3(32, 32, 1), dim3(32, 8)>>>(Wout);

    qkv_mma_kernel<<<dim3(3, 32, 16), 128, DSM>>>(bqkv);

    attn_mma_kernel<<<dim3(16, 32), 256>>>();

    outproj_mma_kernel<<<dim3(16, 32), 128, DSM>>>(bout, out);
}

// round 16
// speedup vs baseline: 6.0978x; 1.1134x over previous
#include <cuda_runtime.h>
#include <cuda_fp16.h>
#include <math.h>
#include <stdint.h>

#define B_ 2
#define N_ 2048
#define E_ 1024
#define H_ 16
#define HD_ 64

// ---------------------------------------------------------------------------
// Scratch (__device__ globals; allocation-free rule). fp16 hi/lo splits.
// ---------------------------------------------------------------------------
__device__ __half g_xh[(size_t)4096*1024];      // x, fp16 hi only
__device__ __half g_wqh[(size_t)16*192*1024];   // [h][n][k] (transposed)
__device__ __half g_wql[(size_t)16*192*1024];
__device__ __half g_woh[(size_t)1024*1024];     // [n][k] (transposed)
__device__ __half g_wol[(size_t)1024*1024];
__device__ __half g_sah[(size_t)4096*1024];     // attention output, fp16 hi only

// Q (hi), K (hi/lo), V (hi), layout [bh][n][64]
__device__ __half g_Qh[(size_t)B_*H_*N_*HD_];
__device__ __half g_Kh[(size_t)B_*H_*N_*HD_];
__device__ __half g_Kl[(size_t)B_*H_*N_*HD_];
__device__ __half g_Vh[(size_t)B_*H_*N_*HD_];

// ---------------------------------------------------------------------------
// PTX helpers (baseline-PTX features only)
// ---------------------------------------------------------------------------
__device__ __forceinline__ void mma_f16(float* c, const uint32_t* a, const uint32_t* b) {
    asm volatile(
        "mma.sync.aligned.m16n8k16.row.col.f32.f16.f16.f32 "
        "{%0,%1,%2,%3},{%4,%5,%6,%7},{%8,%9},{%0,%1,%2,%3};"
        : "+f"(c[0]), "+f"(c[1]), "+f"(c[2]), "+f"(c[3])
        : "r"(a[0]), "r"(a[1]), "r"(a[2]), "r"(a[3]), "r"(b[0]), "r"(b[1]));
}

__device__ __forceinline__ void ldsm_x4(uint32_t* r, uint32_t addr) {
    asm volatile("ldmatrix.sync.aligned.m8n8.x4.shared.b16 {%0,%1,%2,%3}, [%4];"
        : "=r"(r[0]), "=r"(r[1]), "=r"(r[2]), "=r"(r[3]) : "r"(addr));
}
__device__ __forceinline__ void ldsm_x4_t(uint32_t* r, uint32_t addr) {
    asm volatile("ldmatrix.sync.aligned.m8n8.x4.trans.shared.b16 {%0,%1,%2,%3}, [%4];"
        : "=r"(r[0]), "=r"(r[1]), "=r"(r[2]), "=r"(r[3]) : "r"(addr));
}

#define CP_ASYNC16(dst, src) \
    asm volatile("cp.async.cg.shared.global [%0], [%1], 16;" :: "r"(dst), "l"(src))
#define CP_COMMIT() asm volatile("cp.async.commit_group;" ::: "memory")
#define CP_WAIT0()  asm volatile("cp.async.wait_group 0;" ::: "memory")
#define CP_WAIT1()  asm volatile("cp.async.wait_group 1;" ::: "memory")

__device__ __forceinline__ uint32_t smem_u32(const void* p) {
    return (uint32_t)__cvta_generic_to_shared(p);
}

// 128B rows, classic SW128: 16B slot s of row r lives at slot s^(r&7)
#define SWB(r, s) ((uint32_t)((r) * 128 + (((s) ^ ((r) & 7)) << 4)))

__device__ __forceinline__ uint32_t pack_h2(float lo, float hi) {
    union { __half2 v; uint32_t u; } U;
    U.v = __floats2half2_rn(lo, hi);
    return U.u;
}

// split fp32 pair into fp16 hi pair + fp16 residual pair
__device__ __forceinline__ void split_store_pair(float vx, float vy,
                                                 __half* dh, __half* dl) {
    __half hx = __float2half_rn(vx);
    __half hy = __float2half_rn(vy);
    union { __half2 v; uint32_t u; } H, L;
    H.v.x = hx; H.v.y = hy;
    L.v = __floats2half2_rn(vx - __half2float(hx), vy - __half2float(hy));
    *(uint32_t*)dh = H.u;
    *(uint32_t*)dl = L.u;
}

// ---------------------------------------------------------------------------
// Conversion kernels
// ---------------------------------------------------------------------------
__global__ void convert_x_kernel(const float* __restrict__ x) {
    int i = blockIdx.x * blockDim.x + threadIdx.x;
    int stride = gridDim.x * blockDim.x;
    int n4 = 4096 * 1024 / 4;
    for (; i < n4; i += stride) {
        float4 v = ((const float4*)x)[i];
        union { __half b[4]; uint2 u; } Hh;
        Hh.b[0] = __float2half_rn(v.x);
        Hh.b[1] = __float2half_rn(v.y);
        Hh.b[2] = __float2half_rn(v.z);
        Hh.b[3] = __float2half_rn(v.w);
        ((uint2*)g_xh)[i] = Hh.u;
    }
}

__device__ __forceinline__ void tsplit_body(const float* __restrict__ in,
                                            __half* __restrict__ oh,
                                            __half* __restrict__ ol,
                                            int R, int C) {
    __shared__ float t[32][33];
    size_t zo = (size_t)blockIdx.z * R * C;
    in += zo; oh += zo; ol += zo;
    int c0 = blockIdx.x * 32, r0 = blockIdx.y * 32;
    int tx = threadIdx.x, ty = threadIdx.y;
#pragma unroll
    for (int i = 0; i < 32; i += 8)
        t[ty + i][tx] = in[(size_t)(r0 + ty + i) * C + c0 + tx];
    __syncthreads();
#pragma unroll
    for (int i = 0; i < 32; i += 8) {
        float v = t[tx][ty + i];
        __half h = __float2half_rn(v);
        oh[(size_t)(c0 + ty + i) * R + r0 + tx] = h;
        ol[(size_t)(c0 + ty + i) * R + r0 + tx] = __float2half_rn(v - __half2float(h));
    }
}

__global__ void tsplit_wq_kernel(const float* __restrict__ Wqkv) {
    tsplit_body(Wqkv, g_wqh, g_wql, 1024, 192);
}
__global__ void tsplit_wo_kernel(const float* __restrict__ Wout) {
    tsplit_body(Wout, g_woh, g_wol, 1024, 1024);
}

// ---------------------------------------------------------------------------
// GEMM mainloop: uniform 2-pass Ah*Bh + Ah*Bl. 3-stage cp.async pipeline,
// dynamic smem (72KB), 128 threads, 4 warps, warp tile 32x64.
// ---------------------------------------------------------------------------
#define STG_BYTES 24576

__device__ __forceinline__ void gemm_stage(
    uint32_t sA, uint32_t sB,
    const uint4* __restrict__ Ah4,
    const uint4* __restrict__ Bh4, const uint4* __restrict__ Bl4,
    int kb4, int tid)
{
#pragma unroll
    for (int p = 0; p < 4; p++) {
        int idx = tid + p * 128;
        int r = idx >> 2, s = idx & 3;
        CP_ASYNC16(sA + SWB(r, s), Ah4 + (size_t)r * 128 + kb4 + s);
    }
#pragma unroll
    for (int p = 0; p < 4; p++) {
        int idx = tid + p * 128;
        int r = idx >> 3, s = idx & 7;
        const uint4* src = (s < 4) ? (Bh4 + (size_t)r * 128 + kb4 + s)
                                   : (Bl4 + (size_t)r * 128 + kb4 + (s - 4));
        CP_ASYNC16(sB + SWB(r, s), src);
    }
}

__device__ __forceinline__ void gemm_mainloop(
    const uint4* __restrict__ Ah4,
    const uint4* __restrict__ Bh4, const uint4* __restrict__ Bl4,
    float C[2][8][4])
{
    extern __shared__ __align__(128) char dynsm[];
    uint32_t base = smem_u32(dynsm);

    int tid = threadIdx.x;
    int lane = tid & 31, w = tid >> 5;
    int wm = w * 32;

#pragma unroll
    for (int mt = 0; mt < 2; mt++)
#pragma unroll
        for (int nt = 0; nt < 8; nt++)
#pragma unroll
            for (int i = 0; i < 4; i++) C[mt][nt][i] = 0.f;

    int aRow = (lane & 15);
    int aSel = (lane >> 4) & 1;
    int bRow = (lane & 7) + ((lane >> 4) & 1) * 8;
    int bSel = (lane >> 3) & 1;

    gemm_stage(base, base + 16384, Ah4, Bh4, Bl4, 0, tid);
    CP_COMMIT();
    gemm_stage(base + STG_BYTES, base + STG_BYTES + 16384, Ah4, Bh4, Bl4, 4, tid);
    CP_COMMIT();

    int st = 0;
    for (int kc = 0; kc < 32; kc++) {
        if (kc < 31) { CP_WAIT1(); } else { CP_WAIT0(); }
        __syncthreads();
        uint32_t sA = base + st * STG_BYTES;
        uint32_t sB = sA + 16384;

#pragma unroll
        for (int k16 = 0; k16 < 2; k16++) {
            int shi = k16 * 2, slo = 4 + k16 * 2;
            uint32_t ah[2][4], bh[8][2], bl[8][2];
#pragma unroll
            for (int mt = 0; mt < 2; mt++) {
                int row = wm + mt * 16 + aRow;
                ldsm_x4(ah[mt], sA + SWB(row, shi + aSel));
            }
#pragma unroll
            for (int p = 0; p < 4; p++) {
                int row = p * 16 + bRow;
                uint32_t r4[4];
                ldsm_x4(r4, sB + SWB(row, shi + bSel));
                bh[2 * p][0] = r4[0]; bh[2 * p][1] = r4[1];
                bh[2 * p + 1][0] = r4[2]; bh[2 * p + 1][1] = r4[3];
                ldsm_x4(r4, sB + SWB(row, slo + bSel));
                bl[2 * p][0] = r4[0]; bl[2 * p][1] = r4[1];
                bl[2 * p + 1][0] = r4[2]; bl[2 * p + 1][1] = r4[3];
            }
#pragma unroll
            for (int mt = 0; mt < 2; mt++)
#pragma unroll
                for (int nt = 0; nt < 8; nt++) {
                    mma_f16(C[mt][nt], ah[mt], bh[nt]);
                    mma_f16(C[mt][nt], ah[mt], bl[nt]);
                }
        }

        if (kc + 2 < 32) {
            int ns = (st + 2) % 3;
            gemm_stage(base + ns * STG_BYTES, base + ns * STG_BYTES + 16384,
                       Ah4, Bh4, Bl4, (kc + 2) * 4, tid);
            CP_COMMIT();
        }
        st = (st + 1) % 3;
    }
}

// ---------------------------------------------------------------------------
// QKV: uniform 2-pass. nt 0=K (hi/lo store), 1=Q (hi), 2=V (hi).
// grid = (3, 32, 16), block = 128.
// ---------------------------------------------------------------------------
__global__ __launch_bounds__(128, 3) void qkv_mma_kernel(const float* __restrict__ bqkv) {
    int nt = blockIdx.x, mt = blockIdx.y, h = blockIdx.z;
    int mbase = mt * 128;

    const uint4* Ah4 = (const uint4*)g_xh + (size_t)mbase * 128;
    size_t boff = ((size_t)h * 192 + nt * 64) * 128;
    const uint4* Bh4 = (const uint4*)g_wqh + boff;
    const uint4* Bl4 = (const uint4*)g_wql + boff;

    float C[2][8][4];
    gemm_mainloop(Ah4, Bh4, Bl4, C);

    int lane = threadIdx.x & 31, w = threadIdx.x >> 5;
    int g = lane >> 2, tg = lane & 3;

    const float* bp = bqkv + h * 192 + nt * 64;
    __half* dh = (nt == 0) ? g_Kh : (nt == 1) ? g_Qh : g_Vh;

#pragma unroll
    for (int mt2 = 0; mt2 < 2; mt2++) {
#pragma unroll
        for (int half = 0; half < 2; half++) {
            int m = mbase + w * 32 + mt2 * 16 + g + half * 8;
            int b = m >> 11, n = m & 2047;
            size_t ro = (((size_t)(b * H_ + h)) * N_ + n) * HD_;
#pragma unroll
            for (int nt2 = 0; nt2 < 8; nt2++) {
                int col = nt2 * 8 + tg * 2;
                float vx = C[mt2][nt2][half * 2 + 0] + bp[col];
                float vy = C[mt2][nt2][half * 2 + 1] + bp[col + 1];
                if (nt == 0) {
                    split_store_pair(vx, vy, dh + ro + col, g_Kl + ro + col);
                } else {
                    *(uint32_t*)&dh[ro + col] = pack_h2(vx, vy);
                }
            }
        }
    }
}

// ---------------------------------------------------------------------------
// Output projection: 2-pass. grid = (16, 32), block = 128
// ---------------------------------------------------------------------------
__global__ __launch_bounds__(128, 3) void outproj_mma_kernel(const float* __restrict__ bout,
                                                             float* __restrict__ out) {
    int nt = blockIdx.x, mt = blockIdx.y;
    int mbase = mt * 128;

    const uint4* Ah4 = (const uint4*)g_sah + (size_t)mbase * 128;
    size_t boff = (size_t)nt * 64 * 128;
    const uint4* Bh4 = (const uint4*)g_woh + boff;
    const uint4* Bl4 = (const uint4*)g_wol + boff;

    float C[2][8][4];
    gemm_mainloop(Ah4, Bh4, Bl4, C);

    int lane = threadIdx.x & 31, w = threadIdx.x >> 5;
    int g = lane >> 2, tg = lane & 3;

    const float* bp = bout + nt * 64;

#pragma unroll
    for (int mt2 = 0; mt2 < 2; mt2++) {
#pragma unroll
        for (int half = 0; half < 2; half++) {
            int m = mbase + w * 32 + mt2 * 16 + g + half * 8;
            float* drow = out + (size_t)m * E_ + nt * 64;
#pragma unroll
            for (int nt2 = 0; nt2 < 8; nt2++) {
                int col = nt2 * 8 + tg * 2;
                float2 v;
                v.x = C[mt2][nt2][half * 2 + 0] + bp[col];
                v.y = C[mt2][nt2][half * 2 + 1] + bp[col + 1];
                *(float2*)&drow[col] = v;
            }
        }
    }
}

// ---------------------------------------------------------------------------
// Attention: S 2-pass (qh*(kh+kl)), PV 1-pass (ph*vh), DOUBLE-BUFFERED tiles.
// 2 stages x (Kh 8K + Kl 8K + Vh 8K) = 48KB dynamic smem. One {K,V} commit
// group per tile, issued one tile ahead. Per tile: wait, sync, compute, sync,
// issue t+2. Block = 128 q rows; 8 warps x 16 rows. grid = (16, 32), 256 thr.
// ---------------------------------------------------------------------------
#define ASTG 24576   // attention stage bytes

__global__ __launch_bounds__(256) void attn_mma_kernel() {
    extern __shared__ __align__(128) char dynsm[];
    uint32_t base = smem_u32(dynsm);

    int qt = (int)(gridDim.x - 1) - (int)blockIdx.x;   // heavy tiles first
    int bh = blockIdx.y;
    int tid = threadIdx.x, lane = tid & 31, w = tid >> 5;
    int g = lane >> 2, tg = lane & 3;
    int qbase = qt * 128, wrow = w * 16;
    int row0 = qbase + wrow + g, row1 = row0 + 8;

    const uint4* KhG = (const uint4*)(g_Kh + (size_t)bh * N_ * HD_);
    const uint4* KlG = (const uint4*)(g_Kl + (size_t)bh * N_ * HD_);
    const uint4* VhG = (const uint4*)(g_Vh + (size_t)bh * N_ * HD_);

    int nkt = 2 * qt + 2;

    // load one {Kh,Kl,Vh} tile group into stage st
    int ldR = tid >> 2;                 // 0..63 (r for 2-thread split below)
    // each thread does 2 (r,s) pairs per tile buffer: idx = tid, tid+256
    // prologue: G0 -> stage0, G1 -> stage1  (nkt >= 2 always)
    {
#pragma unroll
        for (int p = 0; p < 2; p++) {
            int idx = tid + p * 256;
            int r = idx >> 3, s = idx & 7;
            uint32_t so = SWB(r, s);
            CP_ASYNC16(base + so,         KhG + r * 8 + s);
            CP_ASYNC16(base + 8192 + so,  KlG + r * 8 + s);
            CP_ASYNC16(base + 16384 + so, VhG + r * 8 + s);
        }
        CP_COMMIT();
        int gb = 64 * 8;
#pragma unroll
        for (int p = 0; p < 2; p++) {
            int idx = tid + p * 256;
            int r = idx >> 3, s = idx & 7;
            uint32_t so = SWB(r, s);
            CP_ASYNC16(base + ASTG + so,         KhG + gb + r * 8 + s);
            CP_ASYNC16(base + ASTG + 8192 + so,  KlG + gb + r * 8 + s);
            CP_ASYNC16(base + ASTG + 16384 + so, VhG + gb + r * 8 + s);
        }
        CP_COMMIT();
    }

    // Q hi fragments straight from gmem (overlaps prologue loads)
    const __half* Qh = g_Qh + ((size_t)bh * N_ + qbase + wrow) * HD_;
    uint32_t qh[4][4];
#pragma unroll
    for (int ko = 0; ko < 4; ko++) {
        int c = ko * 16 + tg * 2;
        qh[ko][0] = *(const uint32_t*)&Qh[(size_t)g * 64 + c];
        qh[ko][1] = *(const uint32_t*)&Qh[(size_t)(g + 8) * 64 + c];
        qh[ko][2] = *(const uint32_t*)&Qh[(size_t)g * 64 + c + 8];
        qh[ko][3] = *(const uint32_t*)&Qh[(size_t)(g + 8) * 64 + c + 8];
    }

    float Co[8][4];
#pragma unroll
    for (int nt = 0; nt < 8; nt++)
#pragma unroll
        for (int i = 0; i < 4; i++) Co[nt][i] = 0.f;
    float m0 = -1e30f, m1 = -1e30f, l0 = 0.f, l1 = 0.f;

    int kRow = (lane & 7) + ((lane >> 4) & 1) * 8;   // K (non-trans, B-style)
    int kSel = (lane >> 3) & 1;
    int vRow = (lane & 15);                          // V (trans, A-style)
    int vSel = (lane >> 4) & 1;

    for (int kt = 0; kt < nkt; kt++) {
        if (kt + 1 < nkt) { CP_WAIT1(); } else { CP_WAIT0(); }
        __syncthreads();

        uint32_t sb = base + (kt & 1) * ASTG;
        uint32_t uKh = sb, uKl = sb + 8192, uVh = sb + 16384;

        // ---- S = Q K^T (2-pass: qh*(kh+kl)) ----
        float Cs[8][4];
#pragma unroll
        for (int nt = 0; nt < 8; nt++)
#pragma unroll
            for (int i = 0; i < 4; i++) Cs[nt][i] = 0.f;

#pragma unroll
        for (int ko = 0; ko < 4; ko++) {
#pragma unroll
            for (int p = 0; p < 4; p++) {
                int row = p * 16 + kRow;
                uint32_t so = SWB(row, ko * 2 + kSel);
                uint32_t kh4[4], kl4[4];
                ldsm_x4(kh4, uKh + so);
                ldsm_x4(kl4, uKl + so);
                mma_f16(Cs[2 * p],     qh[ko], kh4);
                mma_f16(Cs[2 * p],     qh[ko], kl4);
                mma_f16(Cs[2 * p + 1], qh[ko], kh4 + 2);
                mma_f16(Cs[2 * p + 1], qh[ko], kl4 + 2);
            }
        }

        // ---- mask + scale + row max (registers only) ----
        int kb = kt * 64;
        float mt0 = -1e30f, mt1 = -1e30f;
#pragma unroll
        for (int nt = 0; nt < 8; nt++) {
            int col = kb + nt * 8 + tg * 2;
#pragma unroll
            for (int j = 0; j < 2; j++) {
                float v0 = Cs[nt][j] * 0.125f;
                float v1 = Cs[nt][2 + j] * 0.125f;
                v0 = (col + j <= row0) ? v0 : -1e30f;
                v1 = (col + j <= row1) ? v1 : -1e30f;
                Cs[nt][j] = v0; Cs[nt][2 + j] = v1;
                mt0 = fmaxf(mt0, v0); mt1 = fmaxf(mt1, v1);
            }
        }
        mt0 = fmaxf(mt0, __shfl_xor_sync(0xffffffffu, mt0, 1));
        mt0 = fmaxf(mt0, __shfl_xor_sync(0xffffffffu, mt0, 2));
        mt1 = fmaxf(mt1, __shfl_xor_sync(0xffffffffu, mt1, 1));
        mt1 = fmaxf(mt1, __shfl_xor_sync(0xffffffffu, mt1, 2));

        float mn0 = fmaxf(m0, mt0), mn1 = fmaxf(m1, mt1);
        float a0 = __expf(m0 - mn0), a1 = __expf(m1 - mn1);
        m0 = mn0; m1 = mn1;
        l0 *= a0; l1 *= a1;
#pragma unroll
        for (int nt = 0; nt < 8; nt++) {
            Co[nt][0] *= a0; Co[nt][1] *= a0;
            Co[nt][2] *= a1; Co[nt][3] *= a1;
        }

        // ---- exp + row sums ----
        float s0 = 0.f, s1 = 0.f;
#pragma unroll
        for (int nt = 0; nt < 8; nt++) {
#pragma unroll
            for (int j = 0; j < 2; j++) {
                float p0 = __expf(Cs[nt][j] - m0);
                float p1 = __expf(Cs[nt][2 + j] - m1);
                Cs[nt][j] = p0; Cs[nt][2 + j] = p1;
                s0 += p0; s1 += p1;
            }
        }
        s0 += __shfl_xor_sync(0xffffffffu, s0, 1);
        s0 += __shfl_xor_sync(0xffffffffu, s0, 2);
        s1 += __shfl_xor_sync(0xffffffffu, s1, 1);
        s1 += __shfl_xor_sync(0xffffffffu, s1, 2);
        l0 += s0; l1 += s1;

        // ---- O += P V (1-pass: Ph*Vh) ----
#pragma unroll
        for (int ko = 0; ko < 4; ko++) {
            uint32_t ph[4];
            ph[0] = pack_h2(Cs[2 * ko][0], Cs[2 * ko][1]);
            ph[1] = pack_h2(Cs[2 * ko][2], Cs[2 * ko][3]);
            ph[2] = pack_h2(Cs[2 * ko + 1][0], Cs[2 * ko + 1][1]);
            ph[3] = pack_h2(Cs[2 * ko + 1][2], Cs[2 * ko + 1][3]);
#pragma unroll
            for (int p = 0; p < 4; p++) {
                int row = ko * 16 + vRow;
                uint32_t so = SWB(row, p * 2 + vSel);
                uint32_t vh4[4];
                ldsm_x4_t(vh4, uVh + so);
                mma_f16(Co[2 * p],     ph, vh4);
                mma_f16(Co[2 * p + 1], ph, vh4 + 2);
            }
        }

        __syncthreads();
        // issue G(kt+2) into the stage we just finished
        if (kt + 2 < nkt) {
            int gb = (kt + 2) * 64 * 8;
#pragma unroll
            for (int p = 0; p < 2; p++) {
                int idx = tid + p * 256;
                int r = idx >> 3, s = idx & 7;
                uint32_t so = SWB(r, s);
                CP_ASYNC16(sb + so,         KhG + gb + r * 8 + s);
                CP_ASYNC16(sb + 8192 + so,  KlG + gb + r * 8 + s);
                CP_ASYNC16(sb + 16384 + so, VhG + gb + r * 8 + s);
            }
            CP_COMMIT();
        }
    }

    // ---- finalize: O /= l, write fp16 hi into sa layout [b][n][E] ----
    float inv0 = 1.f / l0, inv1 = 1.f / l1;
    int b = bh >> 4, h = bh & 15;
    size_t ro0 = ((size_t)(b * N_) + row0) * E_ + h * HD_;
    size_t ro1 = ((size_t)(b * N_) + row1) * E_ + h * HD_;
#pragma unroll
    for (int nt = 0; nt < 8; nt++) {
        int col = nt * 8 + tg * 2;
        *(uint32_t*)&g_sah[ro0 + col] = pack_h2(Co[nt][0] * inv0, Co[nt][1] * inv0);
        *(uint32_t*)&g_sah[ro1 + col] = pack_h2(Co[nt][2] * inv1, Co[nt][3] * inv1);
    }
}

// ---------------------------------------------------------------------------
extern "C" void kernel_launch(void* const* d_in, const int* in_sizes, int n_in,
                              void* d_out, int out_size) {
    const float* x    = (const float*)d_in[0];
    const float* Wqkv = (const float*)d_in[1];
    const float* bqkv = (const float*)d_in[2];
    const float* Wout = (const float*)d_in[3];
    const float* bout = (const float*)d_in[4];
    float* out = (float*)d_out;

    const int DSM = 3 * STG_BYTES;   // 72KB (GEMMs)
    const int ASM = 2 * ASTG;        // 48KB (attention)
    cudaFuncSetAttribute(qkv_mma_kernel,
                         cudaFuncAttributeMaxDynamicSharedMemorySize, DSM);
    cudaFuncSetAttribute(outproj_mma_kernel,
                         cudaFuncAttributeMaxDynamicSharedMemorySize, DSM);
    cudaFuncSetAttribute(attn_mma_kernel,
                         cudaFuncAttributeMaxDynamicSharedMemorySize, ASM);

    convert_x_kernel<<<2048, 256>>>(x);
    tsplit_wq_kernel<<<dim3(6, 32, 16), dim3(32, 8)>>>(Wqkv);
    tsplit_wo_kernel<<<dim3(32, 32, 1), dim3(32, 8)>>>(Wout);

    qkv_mma_kernel<<<dim3(3, 32, 16), 128, DSM>>>(bqkv);

    attn_mma_kernel<<<dim3(16, 32), 256, ASM>>>();

    outproj_mma_kernel<<<dim3(16, 32), 128, DSM>>>(bout, out);
}